// round 1
// baseline (speedup 1.0000x reference)
#include <cuda_runtime.h>
#include <math.h>

#define T_   2
#define NP   25000
#define EP   200000
#define HID_ 256
#define NTOT (T_*NP)
#define E2   (2*EP)

// ---------------- scratch (static __device__ — no allocations) ----------------
__device__ float g_hn [(size_t)T_*NP*HID_];
__device__ float g_q  [(size_t)NTOT*HID_];
__device__ float g_k  [(size_t)NTOT*HID_];
__device__ float g_v  [(size_t)NTOT*HID_];
__device__ float g_agg[(size_t)NTOT*HID_];   // conv agg / attn out (time-shared)
__device__ float g_ffn[(size_t)T_*NP*512];
__device__ float g_sc [(size_t)E2*8];        // scores, then ex
__device__ unsigned int g_m[NTOT*8];
__device__ float g_den[NTOT*8];
__device__ float g_cs [T_*NP];               // indexed [et][n] (src type == et)
__device__ float g_cd [T_*NP];               // indexed [dst_type][n]
__device__ int   g_degs[T_*NP];
__device__ int   g_degd[T_*NP];

// ---------------- helpers ----------------
__device__ __forceinline__ float block_sum(float v, float* sh) {
    #pragma unroll
    for (int o = 16; o; o >>= 1) v += __shfl_xor_sync(0xffffffffu, v, o);
    if ((threadIdx.x & 31) == 0) sh[threadIdx.x >> 5] = v;
    __syncthreads();
    float s = 0.f;
    #pragma unroll
    for (int i = 0; i < 8; i++) s += sh[i];
    __syncthreads();
    return s;
}

// ---------------- degree kernels ----------------
__global__ void k_deg(const int* __restrict__ es, const int* __restrict__ ed) {
    int gid = blockIdx.x * blockDim.x + threadIdx.x;
    if (gid >= E2) return;
    int et = gid / EP;
    atomicAdd(&g_degs[et*NP + es[gid]], 1);
    atomicAdd(&g_degd[et*NP + ed[gid]], 1);
}

__global__ void k_degnorm() {
    int n = blockIdx.x * blockDim.x + threadIdx.x;
    if (n >= NP) return;
    #pragma unroll
    for (int et = 0; et < 2; et++) {
        g_cs[et*NP + n]       = rsqrtf((float)max(g_degs[et*NP + n], 1));
        g_cd[(1-et)*NP + n]   = rsqrtf((float)max(g_degd[et*NP + n], 1)); // dt = 1-et
    }
}

// ---------------- layernorm: one block per node, 256 threads ----------------
__global__ void k_ln(const float* __restrict__ x, const float* __restrict__ g,
                     const float* __restrict__ b, float* __restrict__ y) {
    __shared__ float sh[8];
    int n = blockIdx.x, t = blockIdx.y, c = threadIdx.x;
    size_t base = ((size_t)t*NP + n) * HID_;
    float v = x[base + c];
    float mu = block_sum(v, sh) * (1.0f / HID_);
    float d = v - mu;
    float var = block_sum(d * d, sh) * (1.0f / HID_);
    y[base + c] = d * rsqrtf(var + 1e-5f) * g[t*HID_ + c] + b[t*HID_ + c];
}

// ---------------- conv aggregation scatter ----------------
__global__ void k_conv_scatter(const float* __restrict__ hn, const int* __restrict__ es,
                               const int* __restrict__ ed) {
    long gid = (long)blockIdx.x * blockDim.x + threadIdx.x;
    if (gid >= (long)E2 * 64) return;
    int e2 = (int)(gid >> 6);
    int c  = (int)(gid & 63) * 4;
    int et = e2 / EP;
    int src = es[e2], dst = ed[e2];
    float w = g_cs[et*NP + src];
    const float4 hv = *(const float4*)&hn[((size_t)et*NP + src)*HID_ + c];
    float* o = &g_agg[((size_t)(1-et)*NP + dst)*HID_ + c];
    atomicAdd(o+0, hv.x*w); atomicAdd(o+1, hv.y*w);
    atomicAdd(o+2, hv.z*w); atomicAdd(o+3, hv.w*w);
}

// ---------------- generic SGEMM C = op(A@W) with fused epilogue ----------------
// 128x128x8 tiling, 256 threads, 8x8 micro-tile.
// epilogue: v = acc * (rowscale? rowscale[r] : 1) + bias[col] (+resid) (gelu?)
__global__ void __launch_bounds__(256, 2) sgemm(
    const float* __restrict__ A, const float* __restrict__ W,
    const float* __restrict__ bias, const float* __restrict__ rowscale,
    const float* __restrict__ resid, float* __restrict__ C,
    int M, int K, int N, int wswap, int dogelu)
{
    int t = blockIdx.z;
    int wi = wswap ? (1 - t) : t;
    A    += (size_t)t  * M * K;
    W    += (size_t)wi * K * N;
    bias += (size_t)wi * N;
    const float* rs = rowscale ? rowscale + (size_t)t * M     : nullptr;
    const float* rd = resid    ? resid    + (size_t)t * M * N : nullptr;
    C    += (size_t)t * M * N;

    __shared__ float As[8][128];
    __shared__ float Bs[8][128];

    int tid = threadIdx.x;
    int m0 = blockIdx.y * 128, n0 = blockIdx.x * 128;
    int arow = tid >> 1, acol = (tid & 1) * 4;
    int brow = tid >> 5, bcol = (tid & 31) * 4;
    int tx = tid & 15, ty = tid >> 4;

    float acc[8][8];
    #pragma unroll
    for (int i = 0; i < 8; i++)
        #pragma unroll
        for (int j = 0; j < 8; j++) acc[i][j] = 0.f;

    int ar = m0 + arow;
    bool avalid = ar < M;
    const float* Aptr = A + (size_t)ar * K + acol;

    for (int k0 = 0; k0 < K; k0 += 8) {
        float4 av = avalid ? *(const float4*)(Aptr + k0) : make_float4(0.f,0.f,0.f,0.f);
        float4 bv = *(const float4*)&W[(size_t)(k0 + brow) * N + n0 + bcol];
        As[acol+0][arow] = av.x; As[acol+1][arow] = av.y;
        As[acol+2][arow] = av.z; As[acol+3][arow] = av.w;
        *(float4*)&Bs[brow][bcol] = bv;
        __syncthreads();
        #pragma unroll
        for (int kk = 0; kk < 8; kk++) {
            float a[8], bb[8];
            #pragma unroll
            for (int i = 0; i < 8; i++) a[i]  = As[kk][ty*8 + i];
            #pragma unroll
            for (int j = 0; j < 8; j++) bb[j] = Bs[kk][tx*8 + j];
            #pragma unroll
            for (int i = 0; i < 8; i++)
                #pragma unroll
                for (int j = 0; j < 8; j++) acc[i][j] += a[i] * bb[j];
        }
        __syncthreads();
    }

    #pragma unroll
    for (int i = 0; i < 8; i++) {
        int r = m0 + ty*8 + i;
        if (r >= M) continue;
        float scale = rs ? rs[r] : 1.0f;
        #pragma unroll
        for (int j = 0; j < 8; j++) {
            int cc = n0 + tx*8 + j;
            size_t idx = (size_t)r * N + cc;
            float vv = acc[i][j] * scale + bias[cc];
            if (rd) vv += rd[idx];
            if (dogelu) vv = 0.5f * vv * (1.0f + erff(vv * 0.70710678118654752f));
            C[idx] = vv;
        }
    }
}

// ---------------- attention: scores + scatter-max (warp per edge) ----------------
__global__ void k_score(const float* __restrict__ q, const float* __restrict__ k,
                        const int* __restrict__ es, const int* __restrict__ ed) {
    int e2 = blockIdx.x * 8 + (threadIdx.x >> 5);
    if (e2 >= E2) return;
    int lane = threadIdx.x & 31;
    int et = e2 / EP;
    int sg = es[e2] + (et ? NP : 0);
    int dg = ed[e2] + (et ? 0 : NP);
    const float* qv = q + (size_t)dg * HID_;
    const float* kv = k + (size_t)sg * HID_;
    #pragma unroll
    for (int hh = 0; hh < 8; hh++) {
        float p = qv[hh*32 + lane] * kv[hh*32 + lane];
        #pragma unroll
        for (int o = 16; o; o >>= 1) p += __shfl_xor_sync(0xffffffffu, p, o);
        if (lane == 0) {
            float s = fminf(fmaxf(p * 0.17677669529663687f, -5.0f), 5.0f);
            g_sc[(size_t)e2*8 + hh] = s;
            // s+6 in [1,11] > 0 -> float bits monotone as uint; init 0 == -inf
            atomicMax(&g_m[dg*8 + hh], __float_as_uint(s + 6.0f));
        }
    }
}

// ---------------- exp + denom accumulation ----------------
__global__ void k_expsum(const int* __restrict__ ed) {
    int gid = blockIdx.x * blockDim.x + threadIdx.x;
    if (gid >= E2 * 8) return;
    int e2 = gid >> 3, hh = gid & 7;
    int et = e2 / EP;
    int dg = ed[e2] + (et ? 0 : NP);
    float mm = __uint_as_float(g_m[dg*8 + hh]) - 6.0f;
    float ex = expf(g_sc[gid] - mm);
    g_sc[gid] = ex;
    atomicAdd(&g_den[dg*8 + hh], ex);
}

// ---------------- alpha * v scatter ----------------
__global__ void k_attn_scatter(const int* __restrict__ es, const int* __restrict__ ed) {
    long gid = (long)blockIdx.x * blockDim.x + threadIdx.x;
    if (gid >= (long)E2 * 64) return;
    int e2 = (int)(gid >> 6);
    int c  = (int)(gid & 63);
    int et = e2 / EP;
    int sg = es[e2] + (et ? NP : 0);
    int dg = ed[e2] + (et ? 0 : NP);
    int hh = c >> 3;
    float alpha = g_sc[(size_t)e2*8 + hh] / g_den[dg*8 + hh];
    const float4 vv = *(const float4*)&g_v[(size_t)sg*HID_ + c*4];
    float* o = &g_agg[(size_t)dg*HID_ + c*4];
    atomicAdd(o+0, vv.x*alpha); atomicAdd(o+1, vv.y*alpha);
    atomicAdd(o+2, vv.z*alpha); atomicAdd(o+3, vv.w*alpha);
}

// ---------------- host orchestration ----------------
extern "C" void kernel_launch(void* const* d_in, const int* in_sizes, int n_in,
                              void* d_out, int out_size) {
    const float* h      = (const float*)d_in[0];
    const int*   es     = (const int*)  d_in[1];
    const int*   ed     = (const int*)  d_in[2];
    const float* preW   = (const float*)d_in[3];
    const float* preB   = (const float*)d_in[4];
    const float* postW  = (const float*)d_in[5];
    const float* postB  = (const float*)d_in[6];
    const float* qW     = (const float*)d_in[7];
    const float* qB     = (const float*)d_in[8];
    const float* kW     = (const float*)d_in[9];
    const float* kB     = (const float*)d_in[10];
    const float* vW     = (const float*)d_in[11];
    const float* vB     = (const float*)d_in[12];
    const float* oW     = (const float*)d_in[13];
    const float* oB     = (const float*)d_in[14];
    const float* fW1    = (const float*)d_in[15];
    const float* fB1    = (const float*)d_in[16];
    const float* fW2    = (const float*)d_in[17];
    const float* fB2    = (const float*)d_in[18];
    const float* lnPreG = (const float*)d_in[19];
    const float* lnPreB = (const float*)d_in[20];
    const float* lnAtG  = (const float*)d_in[21];
    const float* lnAtB  = (const float*)d_in[22];
    const float* lnPoG  = (const float*)d_in[23];
    const float* lnPoB  = (const float*)d_in[24];
    const float* lnFfG  = (const float*)d_in[25];
    const float* lnFfB  = (const float*)d_in[26];
    float* out = (float*)d_out;

    float *hn, *q, *k, *v, *agg, *ffn, *cd;
    unsigned int *m; float *den; int *degs, *degd;
    cudaGetSymbolAddress((void**)&hn,   g_hn);
    cudaGetSymbolAddress((void**)&q,    g_q);
    cudaGetSymbolAddress((void**)&k,    g_k);
    cudaGetSymbolAddress((void**)&v,    g_v);
    cudaGetSymbolAddress((void**)&agg,  g_agg);
    cudaGetSymbolAddress((void**)&ffn,  g_ffn);
    cudaGetSymbolAddress((void**)&cd,   g_cd);
    cudaGetSymbolAddress((void**)&m,    g_m);
    cudaGetSymbolAddress((void**)&den,  g_den);
    cudaGetSymbolAddress((void**)&degs, g_degs);
    cudaGetSymbolAddress((void**)&degd, g_degd);

    const dim3 lnGrid(NP, T_);
    const dim3 g256(2, 196, 2);   // N=256 GEMMs
    const dim3 g512(4, 196, 2);   // N=512 GEMM
    const int SC_BLOCKS = (long)E2 * 64 / 256;   // 100000

    // degrees
    cudaMemsetAsync(degs, 0, sizeof(int) * T_ * NP);
    cudaMemsetAsync(degd, 0, sizeof(int) * T_ * NP);
    k_deg<<<(E2 + 255)/256, 256>>>(es, ed);
    k_degnorm<<<(NP + 255)/256, 256>>>();

    // ---- conv1: h1 = h + (agg(ln(h)) @ preW) * cd + preB ----
    k_ln<<<lnGrid, 256>>>(h, lnPreG, lnPreB, hn);
    cudaMemsetAsync(agg, 0, sizeof(float) * (size_t)NTOT * HID_);
    k_conv_scatter<<<SC_BLOCKS, 256>>>(hn, es, ed);
    sgemm<<<g256, 256>>>(agg, preW, preB, cd, h, out, NP, HID_, HID_, 1, 0);

    // ---- attention ----
    k_ln<<<lnGrid, 256>>>(out, lnAtG, lnAtB, hn);
    sgemm<<<g256, 256>>>(hn, qW, qB, nullptr, nullptr, q, NP, HID_, HID_, 0, 0);
    sgemm<<<g256, 256>>>(hn, kW, kB, nullptr, nullptr, k, NP, HID_, HID_, 0, 0);
    sgemm<<<g256, 256>>>(hn, vW, vB, nullptr, nullptr, v, NP, HID_, HID_, 0, 0);
    cudaMemsetAsync(m,   0, sizeof(unsigned int) * NTOT * 8);
    cudaMemsetAsync(den, 0, sizeof(float) * NTOT * 8);
    k_score<<<(E2 + 7)/8, 256>>>(q, k, es, ed);
    k_expsum<<<(E2*8 + 255)/256, 256>>>(ed);
    cudaMemsetAsync(agg, 0, sizeof(float) * (size_t)NTOT * HID_);
    k_attn_scatter<<<SC_BLOCKS, 256>>>(es, ed);
    sgemm<<<g256, 256>>>(agg, oW, oB, nullptr, out, out, NP, HID_, HID_, 0, 0);

    // ---- conv2 ----
    k_ln<<<lnGrid, 256>>>(out, lnPoG, lnPoB, hn);
    cudaMemsetAsync(agg, 0, sizeof(float) * (size_t)NTOT * HID_);
    k_conv_scatter<<<SC_BLOCKS, 256>>>(hn, es, ed);
    sgemm<<<g256, 256>>>(agg, postW, postB, cd, out, out, NP, HID_, HID_, 1, 0);

    // ---- FFN ----
    k_ln<<<lnGrid, 256>>>(out, lnFfG, lnFfB, hn);
    sgemm<<<g512, 256>>>(hn,  fW1, fB1, nullptr, nullptr, ffn, NP, HID_, 512, 0, 1);
    sgemm<<<g256, 256>>>(ffn, fW2, fB2, nullptr, out,     out, NP, 512, HID_, 0, 0);
}

// round 3
// speedup vs baseline: 1.5967x; 1.5967x over previous
#include <cuda_runtime.h>
#include <cuda_bf16.h>
#include <math.h>

#define T_   2
#define NP   25000
#define EP   200000
#define HID_ 256
#define NTOT (T_*NP)
#define E2   (2*EP)

// ---------------- scratch (static __device__ — no allocations) ----------------
__device__ float g_hn [(size_t)T_*NP*HID_];
__device__ float g_q  [(size_t)NTOT*HID_];
__device__ float g_k  [(size_t)NTOT*HID_];
__device__ float g_v  [(size_t)NTOT*HID_];
__device__ float g_agg[(size_t)NTOT*HID_];   // conv agg / attn out (time-shared)
__device__ float g_ffn[(size_t)T_*NP*512];
__device__ float g_sc [(size_t)E2*8];        // scores, then ex
__device__ unsigned int g_m[NTOT*8];
__device__ float g_den[NTOT*8];
__device__ float g_cs [T_*NP];
__device__ float g_cd [T_*NP];
__device__ int   g_degs[T_*NP];
__device__ int   g_degd[T_*NP];
// split weights, bf16, layout [matrix][t][N][K] (n-major)
#define WCVT_TOTAL 1310720
__device__ __nv_bfloat16 g_wbhi[WCVT_TOTAL];
__device__ __nv_bfloat16 g_wblo[WCVT_TOTAL];
#define WOFF_PRE  0
#define WOFF_POST 131072
#define WOFF_Q    262144
#define WOFF_K    393216
#define WOFF_V    524288
#define WOFF_O    655360
#define WOFF_F1   786432
#define WOFF_F2   1048576

// ---------------- mma helpers ----------------
__device__ __forceinline__ unsigned smem_u32(const void* p) {
    unsigned a;
    asm("{ .reg .u64 t; cvta.to.shared.u64 t, %1; cvt.u32.u64 %0, t; }" : "=r"(a) : "l"(p));
    return a;
}
#define LDM4(r, a) \
    asm volatile("ldmatrix.sync.aligned.m8n8.x4.shared.b16 {%0,%1,%2,%3}, [%4];" \
        : "=r"((r)[0]),"=r"((r)[1]),"=r"((r)[2]),"=r"((r)[3]) : "r"(a))
#define MMA_BF16(c, a, b0, b1) \
    asm volatile("mma.sync.aligned.m16n8k16.row.col.f32.bf16.bf16.f32 " \
        "{%0,%1,%2,%3}, {%4,%5,%6,%7}, {%8,%9}, {%0,%1,%2,%3};" \
        : "+f"((c)[0]),"+f"((c)[1]),"+f"((c)[2]),"+f"((c)[3]) \
        : "r"((a)[0]),"r"((a)[1]),"r"((a)[2]),"r"((a)[3]), "r"(b0),"r"(b1))

__device__ __forceinline__ unsigned pack_bf2(__nv_bfloat16 a, __nv_bfloat16 b) {
    __nv_bfloat162 t = __halves2bfloat162(a, b);
    return *(unsigned*)&t;
}

// ---------------- helpers ----------------
__device__ __forceinline__ float block_sum(float v, float* sh) {
    #pragma unroll
    for (int o = 16; o; o >>= 1) v += __shfl_xor_sync(0xffffffffu, v, o);
    if ((threadIdx.x & 31) == 0) sh[threadIdx.x >> 5] = v;
    __syncthreads();
    float s = 0.f;
    #pragma unroll
    for (int i = 0; i < 8; i++) s += sh[i];
    __syncthreads();
    return s;
}

// ---------------- degree kernels ----------------
__global__ void k_deg(const int* __restrict__ es, const int* __restrict__ ed) {
    int gid = blockIdx.x * blockDim.x + threadIdx.x;
    if (gid >= E2) return;
    int et = gid / EP;
    atomicAdd(&g_degs[et*NP + es[gid]], 1);
    atomicAdd(&g_degd[et*NP + ed[gid]], 1);
}

__global__ void k_degnorm() {
    int n = blockIdx.x * blockDim.x + threadIdx.x;
    if (n >= NP) return;
    #pragma unroll
    for (int et = 0; et < 2; et++) {
        g_cs[et*NP + n]       = rsqrtf((float)max(g_degs[et*NP + n], 1));
        g_cd[(1-et)*NP + n]   = rsqrtf((float)max(g_degd[et*NP + n], 1)); // dt = 1-et
    }
}

// ---------------- layernorm ----------------
__global__ void k_ln(const float* __restrict__ x, const float* __restrict__ g,
                     const float* __restrict__ b, float* __restrict__ y) {
    __shared__ float sh[8];
    int n = blockIdx.x, t = blockIdx.y, c = threadIdx.x;
    size_t base = ((size_t)t*NP + n) * HID_;
    float v = x[base + c];
    float mu = block_sum(v, sh) * (1.0f / HID_);
    float d = v - mu;
    float var = block_sum(d * d, sh) * (1.0f / HID_);
    y[base + c] = d * rsqrtf(var + 1e-5f) * g[t*HID_ + c] + b[t*HID_ + c];
}

// ---------------- conv aggregation scatter ----------------
__global__ void k_conv_scatter(const float* __restrict__ hn, const int* __restrict__ es,
                               const int* __restrict__ ed) {
    long gid = (long)blockIdx.x * blockDim.x + threadIdx.x;
    if (gid >= (long)E2 * 64) return;
    int e2 = (int)(gid >> 6);
    int c  = (int)(gid & 63) * 4;
    int et = e2 / EP;
    int src = es[e2], dst = ed[e2];
    float w = g_cs[et*NP + src];
    const float4 hv = *(const float4*)&hn[((size_t)et*NP + src)*HID_ + c];
    float* o = &g_agg[((size_t)(1-et)*NP + dst)*HID_ + c];
    atomicAdd(o+0, hv.x*w); atomicAdd(o+1, hv.y*w);
    atomicAdd(o+2, hv.z*w); atomicAdd(o+3, hv.w*w);
}

// ---------------- weight split: W[t][K][N] fp32 -> hi/lo bf16 [t][N][K] ----------------
__global__ void k_wconv(const float* __restrict__ W, __nv_bfloat16* __restrict__ hi,
                        __nv_bfloat16* __restrict__ lo, int K, int N) {
    int t = blockIdx.z;
    size_t sz = (size_t)K * N;
    W += t * sz; hi += t * sz; lo += t * sz;
    int o = blockIdx.x * 256 + threadIdx.x;
    if (o >= K * N) return;
    int n = o / K, k = o % K;
    float x = W[(size_t)k * N + n];
    __nv_bfloat16 h = __float2bfloat16_rn(x);
    hi[o] = h;
    lo[o] = __float2bfloat16_rn(x - __bfloat162float(h));
}

// ---------------- bf16-split tensor GEMM: C = epi(A @ W) ----------------
// CTA 128x128, 8 warps (4m x 2n), warp tile 32x64, K-chunk 32.
// D = Ahi*Bhi + Ahi*Blo + Alo*Bhi  (fp32 reg accumulate)
#define PAD 40
__global__ void __launch_bounds__(256, 2) gemm_mma(
    const float* __restrict__ A, const __nv_bfloat16* __restrict__ Bhi_g,
    const __nv_bfloat16* __restrict__ Blo_g, const float* __restrict__ bias,
    const float* __restrict__ rowscale, const float* __restrict__ resid,
    float* __restrict__ C, int M, int K, int N, int wswap, int dogelu)
{
    __shared__ __nv_bfloat16 sAhi[128*PAD], sAlo[128*PAD];
    __shared__ __nv_bfloat16 sBhi[128*PAD], sBlo[128*PAD];

    int tid = threadIdx.x;
    int warp = tid >> 5, lane = tid & 31;
    int wm = warp & 3, wn = warp >> 2;
    int t = blockIdx.z;
    int wi = wswap ? (1 - t) : t;

    A     += (size_t)t  * M * K;
    Bhi_g += (size_t)wi * K * N;
    Blo_g += (size_t)wi * K * N;
    bias  += (size_t)wi * N;
    const float* rs = rowscale ? rowscale + (size_t)t * M : nullptr;
    const float* rd = resid ? resid + (size_t)t * M * N : nullptr;
    C += (size_t)t * M * N;

    int m0 = blockIdx.y * 128, n0 = blockIdx.x * 128;

    float acc[2][8][4];
    #pragma unroll
    for (int i = 0; i < 2; i++)
        #pragma unroll
        for (int j = 0; j < 8; j++)
            #pragma unroll
            for (int l = 0; l < 4; l++) acc[i][j][l] = 0.f;

    // ldmatrix per-lane offsets
    int lrow = lane & 7, lsel = lane >> 3;
    int a_r = (lsel & 1) * 8 + lrow;     // A: tiles (m-low, m-high, k-high pair)
    int a_c = (lsel >> 1) * 8;
    int b_r = (lsel >> 1) * 8 + lrow;    // B: tiles (k-low, k-high) x (n, n+8)
    int b_c = (lsel & 1) * 8;

    unsigned uAhi = smem_u32(sAhi), uAlo = smem_u32(sAlo);
    unsigned uBhi = smem_u32(sBhi), uBlo = smem_u32(sBlo);

    int nchunks = K >> 5;
    for (int c = 0; c < nchunks; c++) {
        // ---- A chunk: 128 rows x 32 fp32 -> split bf16 hi/lo ----
        #pragma unroll
        for (int i = 0; i < 4; i++) {
            int f = i * 256 + tid;               // 0..1023 float4s
            int row = f >> 3, c4 = f & 7;
            float4 v = make_float4(0.f, 0.f, 0.f, 0.f);
            int gm = m0 + row;
            if (gm < M) v = *(const float4*)&A[(size_t)gm * K + (c << 5) + (c4 << 2)];
            __nv_bfloat16 h0 = __float2bfloat16_rn(v.x), h1 = __float2bfloat16_rn(v.y);
            __nv_bfloat16 h2 = __float2bfloat16_rn(v.z), h3 = __float2bfloat16_rn(v.w);
            uint2 hh, ll;
            hh.x = pack_bf2(h0, h1); hh.y = pack_bf2(h2, h3);
            ll.x = pack_bf2(__float2bfloat16_rn(v.x - __bfloat162float(h0)),
                            __float2bfloat16_rn(v.y - __bfloat162float(h1)));
            ll.y = pack_bf2(__float2bfloat16_rn(v.z - __bfloat162float(h2)),
                            __float2bfloat16_rn(v.w - __bfloat162float(h3)));
            *(uint2*)&sAhi[row * PAD + c4 * 4] = hh;
            *(uint2*)&sAlo[row * PAD + c4 * 4] = ll;
        }
        // ---- B chunk: 128 n-rows x 32 bf16 (hi and lo) ----
        #pragma unroll
        for (int i = 0; i < 2; i++) {
            int f = i * 256 + tid;               // 0..511 float4s (8 bf16 each)
            int row = f >> 2, c4 = f & 3;
            size_t go = (size_t)(n0 + row) * K + (c << 5) + (c4 << 3);
            *(float4*)&sBhi[row * PAD + c4 * 8] = *(const float4*)&Bhi_g[go];
            *(float4*)&sBlo[row * PAD + c4 * 8] = *(const float4*)&Blo_g[go];
        }
        __syncthreads();

        // ---- compute: 2 k16 steps ----
        #pragma unroll
        for (int ks = 0; ks < 2; ks++) {
            int kk = ks * 16;
            unsigned ah[2][4], al[2][4];
            #pragma unroll
            for (int mt = 0; mt < 2; mt++) {
                unsigned off = 2u * (unsigned)((wm*32 + mt*16 + a_r) * PAD + kk + a_c);
                LDM4(ah[mt], uAhi + off);
                LDM4(al[mt], uAlo + off);
            }
            #pragma unroll
            for (int bi = 0; bi < 4; bi++) {
                unsigned off = 2u * (unsigned)((wn*64 + bi*16 + b_r) * PAD + kk + b_c);
                unsigned bh[4], bl[4];
                LDM4(bh, uBhi + off);
                LDM4(bl, uBlo + off);
                #pragma unroll
                for (int mt = 0; mt < 2; mt++) {
                    #pragma unroll
                    for (int j = 0; j < 2; j++) {
                        float* cc = acc[mt][bi*2 + j];
                        MMA_BF16(cc, ah[mt], bh[j*2], bh[j*2+1]);
                        MMA_BF16(cc, ah[mt], bl[j*2], bl[j*2+1]);
                        MMA_BF16(cc, al[mt], bh[j*2], bh[j*2+1]);
                    }
                }
            }
        }
        __syncthreads();
    }

    // ---- epilogue ----
    int g = lane >> 2, tig = lane & 3;
    #pragma unroll
    for (int mt = 0; mt < 2; mt++) {
        #pragma unroll
        for (int nt = 0; nt < 8; nt++) {
            int col = n0 + wn*64 + nt*8 + tig*2;
            float b0 = bias[col], b1 = bias[col+1];
            #pragma unroll
            for (int half = 0; half < 2; half++) {
                int r = m0 + wm*32 + mt*16 + g + half*8;
                if (r >= M) continue;
                float scale = rs ? rs[r] : 1.0f;
                size_t idx = (size_t)r * N + col;
                float2 o;
                o.x = acc[mt][nt][half*2+0] * scale + b0;
                o.y = acc[mt][nt][half*2+1] * scale + b1;
                if (rd) {
                    const float2 rv = *(const float2*)&rd[idx];
                    o.x += rv.x; o.y += rv.y;
                }
                if (dogelu) {
                    o.x = 0.5f*o.x*(1.0f+erff(o.x*0.70710678118654752f));
                    o.y = 0.5f*o.y*(1.0f+erff(o.y*0.70710678118654752f));
                }
                *(float2*)&C[idx] = o;
            }
        }
    }
}

// ---------------- attention: scores + scatter-max (warp per edge) ----------------
__global__ void k_score(const float* __restrict__ q, const float* __restrict__ k,
                        const int* __restrict__ es, const int* __restrict__ ed) {
    int e2 = blockIdx.x * 8 + (threadIdx.x >> 5);
    if (e2 >= E2) return;
    int lane = threadIdx.x & 31;
    int et = e2 / EP;
    int sg = es[e2] + (et ? NP : 0);
    int dg = ed[e2] + (et ? 0 : NP);
    const float* qv = q + (size_t)dg * HID_;
    const float* kv = k + (size_t)sg * HID_;
    #pragma unroll
    for (int hh = 0; hh < 8; hh++) {
        float p = qv[hh*32 + lane] * kv[hh*32 + lane];
        #pragma unroll
        for (int o = 16; o; o >>= 1) p += __shfl_xor_sync(0xffffffffu, p, o);
        if (lane == 0) {
            float s = fminf(fmaxf(p * 0.17677669529663687f, -5.0f), 5.0f);
            g_sc[(size_t)e2*8 + hh] = s;
            atomicMax(&g_m[dg*8 + hh], __float_as_uint(s + 6.0f));
        }
    }
}

// ---------------- exp + denom accumulation ----------------
__global__ void k_expsum(const int* __restrict__ ed) {
    int gid = blockIdx.x * blockDim.x + threadIdx.x;
    if (gid >= E2 * 8) return;
    int e2 = gid >> 3, hh = gid & 7;
    int et = e2 / EP;
    int dg = ed[e2] + (et ? 0 : NP);
    float mm = __uint_as_float(g_m[dg*8 + hh]) - 6.0f;
    float ex = expf(g_sc[gid] - mm);
    g_sc[gid] = ex;
    atomicAdd(&g_den[dg*8 + hh], ex);
}

// ---------------- alpha * v scatter ----------------
__global__ void k_attn_scatter(const int* __restrict__ es, const int* __restrict__ ed) {
    long gid = (long)blockIdx.x * blockDim.x + threadIdx.x;
    if (gid >= (long)E2 * 64) return;
    int e2 = (int)(gid >> 6);
    int c  = (int)(gid & 63);
    int et = e2 / EP;
    int sg = es[e2] + (et ? NP : 0);
    int dg = ed[e2] + (et ? 0 : NP);
    int hh = c >> 3;
    float alpha = g_sc[(size_t)e2*8 + hh] / g_den[dg*8 + hh];
    const float4 vv = *(const float4*)&g_v[(size_t)sg*HID_ + c*4];
    float* o = &g_agg[(size_t)dg*HID_ + c*4];
    atomicAdd(o+0, vv.x*alpha); atomicAdd(o+1, vv.y*alpha);
    atomicAdd(o+2, vv.z*alpha); atomicAdd(o+3, vv.w*alpha);
}

// ---------------- host orchestration ----------------
extern "C" void kernel_launch(void* const* d_in, const int* in_sizes, int n_in,
                              void* d_out, int out_size) {
    const float* h      = (const float*)d_in[0];
    const int*   es     = (const int*)  d_in[1];
    const int*   ed     = (const int*)  d_in[2];
    const float* preW   = (const float*)d_in[3];
    const float* preB   = (const float*)d_in[4];
    const float* postW  = (const float*)d_in[5];
    const float* postB  = (const float*)d_in[6];
    const float* qW     = (const float*)d_in[7];
    const float* qB     = (const float*)d_in[8];
    const float* kW     = (const float*)d_in[9];
    const float* kB     = (const float*)d_in[10];
    const float* vW     = (const float*)d_in[11];
    const float* vB     = (const float*)d_in[12];
    const float* oW     = (const float*)d_in[13];
    const float* oB     = (const float*)d_in[14];
    const float* fW1    = (const float*)d_in[15];
    const float* fB1    = (const float*)d_in[16];
    const float* fW2    = (const float*)d_in[17];
    const float* fB2    = (const float*)d_in[18];
    const float* lnPreG = (const float*)d_in[19];
    const float* lnPreB = (const float*)d_in[20];
    const float* lnAtG  = (const float*)d_in[21];
    const float* lnAtB  = (const float*)d_in[22];
    const float* lnPoG  = (const float*)d_in[23];
    const float* lnPoB  = (const float*)d_in[24];
    const float* lnFfG  = (const float*)d_in[25];
    const float* lnFfB  = (const float*)d_in[26];
    float* out = (float*)d_out;

    float *hn, *q, *k, *v, *agg, *ffn, *cd;
    __nv_bfloat16 *wbhi, *wblo;
    unsigned int *m; float *den; int *degs, *degd;
    cudaGetSymbolAddress((void**)&hn,   g_hn);
    cudaGetSymbolAddress((void**)&q,    g_q);
    cudaGetSymbolAddress((void**)&k,    g_k);
    cudaGetSymbolAddress((void**)&v,    g_v);
    cudaGetSymbolAddress((void**)&agg,  g_agg);
    cudaGetSymbolAddress((void**)&ffn,  g_ffn);
    cudaGetSymbolAddress((void**)&cd,   g_cd);
    cudaGetSymbolAddress((void**)&m,    g_m);
    cudaGetSymbolAddress((void**)&den,  g_den);
    cudaGetSymbolAddress((void**)&degs, g_degs);
    cudaGetSymbolAddress((void**)&degd, g_degd);
    cudaGetSymbolAddress((void**)&wbhi, g_wbhi);
    cudaGetSymbolAddress((void**)&wblo, g_wblo);

    const dim3 lnGrid(NP, T_);
    const dim3 g256(2, 196, 2);   // N=256 GEMMs
    const dim3 g512(4, 196, 2);   // N=512 GEMM
    const int SC_BLOCKS = (long)E2 * 64 / 256;

    // weight split (deterministic per call)
    k_wconv<<<dim3(256,1,2), 256>>>(preW,  wbhi+WOFF_PRE,  wblo+WOFF_PRE,  256, 256);
    k_wconv<<<dim3(256,1,2), 256>>>(postW, wbhi+WOFF_POST, wblo+WOFF_POST, 256, 256);
    k_wconv<<<dim3(256,1,2), 256>>>(qW,    wbhi+WOFF_Q,    wblo+WOFF_Q,    256, 256);
    k_wconv<<<dim3(256,1,2), 256>>>(kW,    wbhi+WOFF_K,    wblo+WOFF_K,    256, 256);
    k_wconv<<<dim3(256,1,2), 256>>>(vW,    wbhi+WOFF_V,    wblo+WOFF_V,    256, 256);
    k_wconv<<<dim3(256,1,2), 256>>>(oW,    wbhi+WOFF_O,    wblo+WOFF_O,    256, 256);
    k_wconv<<<dim3(512,1,2), 256>>>(fW1,   wbhi+WOFF_F1,   wblo+WOFF_F1,   256, 512);
    k_wconv<<<dim3(512,1,2), 256>>>(fW2,   wbhi+WOFF_F2,   wblo+WOFF_F2,   512, 256);

    // degrees
    cudaMemsetAsync(degs, 0, sizeof(int) * T_ * NP);
    cudaMemsetAsync(degd, 0, sizeof(int) * T_ * NP);
    k_deg<<<(E2 + 255)/256, 256>>>(es, ed);
    k_degnorm<<<(NP + 255)/256, 256>>>();

    // ---- conv1 ----
    k_ln<<<lnGrid, 256>>>(h, lnPreG, lnPreB, hn);
    cudaMemsetAsync(agg, 0, sizeof(float) * (size_t)NTOT * HID_);
    k_conv_scatter<<<SC_BLOCKS, 256>>>(hn, es, ed);
    gemm_mma<<<g256, 256>>>(agg, wbhi+WOFF_PRE, wblo+WOFF_PRE, preB, cd, h, out, NP, HID_, HID_, 1, 0);

    // ---- attention ----
    k_ln<<<lnGrid, 256>>>(out, lnAtG, lnAtB, hn);
    gemm_mma<<<g256, 256>>>(hn, wbhi+WOFF_Q, wblo+WOFF_Q, qB, nullptr, nullptr, q, NP, HID_, HID_, 0, 0);
    gemm_mma<<<g256, 256>>>(hn, wbhi+WOFF_K, wblo+WOFF_K, kB, nullptr, nullptr, k, NP, HID_, HID_, 0, 0);
    gemm_mma<<<g256, 256>>>(hn, wbhi+WOFF_V, wblo+WOFF_V, vB, nullptr, nullptr, v, NP, HID_, HID_, 0, 0);
    cudaMemsetAsync(m,   0, sizeof(unsigned int) * NTOT * 8);
    cudaMemsetAsync(den, 0, sizeof(float) * NTOT * 8);
    k_score<<<(E2 + 7)/8, 256>>>(q, k, es, ed);
    k_expsum<<<(E2*8 + 255)/256, 256>>>(ed);
    cudaMemsetAsync(agg, 0, sizeof(float) * (size_t)NTOT * HID_);
    k_attn_scatter<<<SC_BLOCKS, 256>>>(es, ed);
    gemm_mma<<<g256, 256>>>(agg, wbhi+WOFF_O, wblo+WOFF_O, oB, nullptr, out, out, NP, HID_, HID_, 0, 0);

    // ---- conv2 ----
    k_ln<<<lnGrid, 256>>>(out, lnPoG, lnPoB, hn);
    cudaMemsetAsync(agg, 0, sizeof(float) * (size_t)NTOT * HID_);
    k_conv_scatter<<<SC_BLOCKS, 256>>>(hn, es, ed);
    gemm_mma<<<g256, 256>>>(agg, wbhi+WOFF_POST, wblo+WOFF_POST, postB, cd, out, out, NP, HID_, HID_, 1, 0);

    // ---- FFN ----
    k_ln<<<lnGrid, 256>>>(out, lnFfG, lnFfB, hn);
    gemm_mma<<<g512, 256>>>(hn,  wbhi+WOFF_F1, wblo+WOFF_F1, fB1, nullptr, nullptr, ffn, NP, HID_, 512, 0, 1);
    gemm_mma<<<g256, 256>>>(ffn, wbhi+WOFF_F2, wblo+WOFF_F2, fB2, nullptr, out,     out, NP, 512, HID_, 0, 0);
}

// round 4
// speedup vs baseline: 2.0022x; 1.2539x over previous
#include <cuda_runtime.h>
#include <cuda_bf16.h>
#include <math.h>

#define T_   2
#define NP   25000
#define EP   200000
#define HID_ 256
#define NTOT (T_*NP)
#define E2   (2*EP)

// ---------------- scratch (static __device__ — no allocations) ----------------
__device__ float g_hn [(size_t)T_*NP*HID_];
__device__ float g_q  [(size_t)NTOT*HID_];
__device__ float g_k  [(size_t)NTOT*HID_];
__device__ float g_v  [(size_t)NTOT*HID_];
__device__ float g_agg[(size_t)NTOT*HID_];   // conv agg / attn out (time-shared)
__device__ float g_ffn[(size_t)T_*NP*512];
__device__ float g_sc [(size_t)E2*8];        // scores, then ex
__device__ unsigned int g_m[NTOT*8];
__device__ float g_den[NTOT*8];
__device__ float g_cs [T_*NP];
__device__ float g_cd [T_*NP];
__device__ int   g_degs[T_*NP];
__device__ int   g_degd[T_*NP];
// split weights, bf16, layout [matrix][t][N][K] (n-major)
#define WCVT_TOTAL 1310720
__device__ __nv_bfloat16 g_wbhi[WCVT_TOTAL];
__device__ __nv_bfloat16 g_wblo[WCVT_TOTAL];
#define WOFF_PRE  0
#define WOFF_POST 131072
#define WOFF_Q    262144
#define WOFF_K    393216
#define WOFF_V    524288
#define WOFF_O    655360
#define WOFF_F1   786432
#define WOFF_F2   1048576

// ---------------- mma / atomic helpers ----------------
__device__ __forceinline__ unsigned smem_u32(const void* p) {
    unsigned a;
    asm("{ .reg .u64 t; cvta.to.shared.u64 t, %1; cvt.u32.u64 %0, t; }" : "=r"(a) : "l"(p));
    return a;
}
#define LDM4(r, a) \
    asm volatile("ldmatrix.sync.aligned.m8n8.x4.shared.b16 {%0,%1,%2,%3}, [%4];" \
        : "=r"((r)[0]),"=r"((r)[1]),"=r"((r)[2]),"=r"((r)[3]) : "r"(a))
#define MMA_BF16(c, a, b0, b1) \
    asm volatile("mma.sync.aligned.m16n8k16.row.col.f32.bf16.bf16.f32 " \
        "{%0,%1,%2,%3}, {%4,%5,%6,%7}, {%8,%9}, {%0,%1,%2,%3};" \
        : "+f"((c)[0]),"+f"((c)[1]),"+f"((c)[2]),"+f"((c)[3]) \
        : "r"((a)[0]),"r"((a)[1]),"r"((a)[2]),"r"((a)[3]), "r"(b0),"r"(b1))

__device__ __forceinline__ void red_v4(float* p, float x, float y, float z, float w) {
    asm volatile("red.global.add.v4.f32 [%0], {%1,%2,%3,%4};"
        :: "l"(p), "f"(x), "f"(y), "f"(z), "f"(w) : "memory");
}

__device__ __forceinline__ unsigned pack_bf2(__nv_bfloat16 a, __nv_bfloat16 b) {
    __nv_bfloat162 t = __halves2bfloat162(a, b);
    return *(unsigned*)&t;
}

// ---------------- helpers ----------------
__device__ __forceinline__ float block_sum(float v, float* sh) {
    #pragma unroll
    for (int o = 16; o; o >>= 1) v += __shfl_xor_sync(0xffffffffu, v, o);
    if ((threadIdx.x & 31) == 0) sh[threadIdx.x >> 5] = v;
    __syncthreads();
    float s = 0.f;
    #pragma unroll
    for (int i = 0; i < 8; i++) s += sh[i];
    __syncthreads();
    return s;
}

// ---------------- degree kernels ----------------
__global__ void k_deg(const int* __restrict__ es, const int* __restrict__ ed) {
    int gid = blockIdx.x * blockDim.x + threadIdx.x;
    if (gid >= E2) return;
    int et = gid / EP;
    atomicAdd(&g_degs[et*NP + es[gid]], 1);
    atomicAdd(&g_degd[et*NP + ed[gid]], 1);
}

__global__ void k_degnorm() {
    int n = blockIdx.x * blockDim.x + threadIdx.x;
    if (n >= NP) return;
    #pragma unroll
    for (int et = 0; et < 2; et++) {
        g_cs[et*NP + n]       = rsqrtf((float)max(g_degs[et*NP + n], 1));
        g_cd[(1-et)*NP + n]   = rsqrtf((float)max(g_degd[et*NP + n], 1)); // dt = 1-et
    }
}

// ---------------- layernorm ----------------
__global__ void k_ln(const float* __restrict__ x, const float* __restrict__ g,
                     const float* __restrict__ b, float* __restrict__ y) {
    __shared__ float sh[8];
    int n = blockIdx.x, t = blockIdx.y, c = threadIdx.x;
    size_t base = ((size_t)t*NP + n) * HID_;
    float v = x[base + c];
    float mu = block_sum(v, sh) * (1.0f / HID_);
    float d = v - mu;
    float var = block_sum(d * d, sh) * (1.0f / HID_);
    y[base + c] = d * rsqrtf(var + 1e-5f) * g[t*HID_ + c] + b[t*HID_ + c];
}

// ---------------- conv aggregation scatter (vectorized red) ----------------
__global__ void k_conv_scatter(const float* __restrict__ hn, const int* __restrict__ es,
                               const int* __restrict__ ed) {
    long gid = (long)blockIdx.x * blockDim.x + threadIdx.x;
    if (gid >= (long)E2 * 64) return;
    int e2 = (int)(gid >> 6);
    int c  = (int)(gid & 63) * 4;
    int et = e2 / EP;
    int src = es[e2], dst = ed[e2];
    float w = g_cs[et*NP + src];
    const float4 hv = *(const float4*)&hn[((size_t)et*NP + src)*HID_ + c];
    float* o = &g_agg[((size_t)(1-et)*NP + dst)*HID_ + c];
    red_v4(o, hv.x*w, hv.y*w, hv.z*w, hv.w*w);
}

// ---------------- weight split: W[t][K][N] fp32 -> hi/lo bf16 [t][N][K] ----------------
__global__ void k_wconv(const float* __restrict__ W, __nv_bfloat16* __restrict__ hi,
                        __nv_bfloat16* __restrict__ lo, int K, int N) {
    int t = blockIdx.z;
    size_t sz = (size_t)K * N;
    W += t * sz; hi += t * sz; lo += t * sz;
    int o = blockIdx.x * 256 + threadIdx.x;
    if (o >= K * N) return;
    int n = o / K, k = o % K;
    float x = W[(size_t)k * N + n];
    __nv_bfloat16 h = __float2bfloat16_rn(x);
    hi[o] = h;
    lo[o] = __float2bfloat16_rn(x - __bfloat162float(h));
}

// ---------------- bf16-split tensor GEMM: C = epi(A @ W) ----------------
// CTA 128x128, 8 warps (4m x 2n), warp tile 32x64, K-chunk 32.
// D = Ahi*Bhi + Ahi*Blo + Alo*Bhi  (fp32 reg accumulate)
#define PAD 40
__global__ void __launch_bounds__(256, 2) gemm_mma(
    const float* __restrict__ A, const __nv_bfloat16* __restrict__ Bhi_g,
    const __nv_bfloat16* __restrict__ Blo_g, const float* __restrict__ bias,
    const float* __restrict__ rowscale, const float* __restrict__ resid,
    float* __restrict__ C, int M, int K, int N, int wswap, int dogelu)
{
    __shared__ __nv_bfloat16 sAhi[128*PAD], sAlo[128*PAD];
    __shared__ __nv_bfloat16 sBhi[128*PAD], sBlo[128*PAD];

    int tid = threadIdx.x;
    int warp = tid >> 5, lane = tid & 31;
    int wm = warp & 3, wn = warp >> 2;
    int t = blockIdx.z;
    int wi = wswap ? (1 - t) : t;

    A     += (size_t)t  * M * K;
    Bhi_g += (size_t)wi * K * N;
    Blo_g += (size_t)wi * K * N;
    bias  += (size_t)wi * N;
    const float* rs = rowscale ? rowscale + (size_t)t * M : nullptr;
    const float* rd = resid ? resid + (size_t)t * M * N : nullptr;
    C += (size_t)t * M * N;

    int m0 = blockIdx.y * 128, n0 = blockIdx.x * 128;

    float acc[2][8][4];
    #pragma unroll
    for (int i = 0; i < 2; i++)
        #pragma unroll
        for (int j = 0; j < 8; j++)
            #pragma unroll
            for (int l = 0; l < 4; l++) acc[i][j][l] = 0.f;

    int lrow = lane & 7, lsel = lane >> 3;
    int a_r = (lsel & 1) * 8 + lrow;
    int a_c = (lsel >> 1) * 8;
    int b_r = (lsel >> 1) * 8 + lrow;
    int b_c = (lsel & 1) * 8;

    unsigned uAhi = smem_u32(sAhi), uAlo = smem_u32(sAlo);
    unsigned uBhi = smem_u32(sBhi), uBlo = smem_u32(sBlo);

    int nchunks = K >> 5;
    for (int c = 0; c < nchunks; c++) {
        // ---- A chunk: 128 rows x 32 fp32 -> split bf16 hi/lo ----
        #pragma unroll
        for (int i = 0; i < 4; i++) {
            int f = i * 256 + tid;
            int row = f >> 3, c4 = f & 7;
            float4 v = make_float4(0.f, 0.f, 0.f, 0.f);
            int gm = m0 + row;
            if (gm < M) v = *(const float4*)&A[(size_t)gm * K + (c << 5) + (c4 << 2)];
            __nv_bfloat16 h0 = __float2bfloat16_rn(v.x), h1 = __float2bfloat16_rn(v.y);
            __nv_bfloat16 h2 = __float2bfloat16_rn(v.z), h3 = __float2bfloat16_rn(v.w);
            uint2 hh, ll;
            hh.x = pack_bf2(h0, h1); hh.y = pack_bf2(h2, h3);
            ll.x = pack_bf2(__float2bfloat16_rn(v.x - __bfloat162float(h0)),
                            __float2bfloat16_rn(v.y - __bfloat162float(h1)));
            ll.y = pack_bf2(__float2bfloat16_rn(v.z - __bfloat162float(h2)),
                            __float2bfloat16_rn(v.w - __bfloat162float(h3)));
            *(uint2*)&sAhi[row * PAD + c4 * 4] = hh;
            *(uint2*)&sAlo[row * PAD + c4 * 4] = ll;
        }
        // ---- B chunk: 128 n-rows x 32 bf16 (hi and lo) ----
        #pragma unroll
        for (int i = 0; i < 2; i++) {
            int f = i * 256 + tid;
            int row = f >> 2, c4 = f & 3;
            size_t go = (size_t)(n0 + row) * K + (c << 5) + (c4 << 3);
            *(float4*)&sBhi[row * PAD + c4 * 8] = *(const float4*)&Bhi_g[go];
            *(float4*)&sBlo[row * PAD + c4 * 8] = *(const float4*)&Blo_g[go];
        }
        __syncthreads();

        #pragma unroll
        for (int ks = 0; ks < 2; ks++) {
            int kk = ks * 16;
            unsigned ah[2][4], al[2][4];
            #pragma unroll
            for (int mt = 0; mt < 2; mt++) {
                unsigned off = 2u * (unsigned)((wm*32 + mt*16 + a_r) * PAD + kk + a_c);
                LDM4(ah[mt], uAhi + off);
                LDM4(al[mt], uAlo + off);
            }
            #pragma unroll
            for (int bi = 0; bi < 4; bi++) {
                unsigned off = 2u * (unsigned)((wn*64 + bi*16 + b_r) * PAD + kk + b_c);
                unsigned bh[4], bl[4];
                LDM4(bh, uBhi + off);
                LDM4(bl, uBlo + off);
                #pragma unroll
                for (int mt = 0; mt < 2; mt++) {
                    #pragma unroll
                    for (int j = 0; j < 2; j++) {
                        float* cc = acc[mt][bi*2 + j];
                        MMA_BF16(cc, ah[mt], bh[j*2], bh[j*2+1]);
                        MMA_BF16(cc, ah[mt], bl[j*2], bl[j*2+1]);
                        MMA_BF16(cc, al[mt], bh[j*2], bh[j*2+1]);
                    }
                }
            }
        }
        __syncthreads();
    }

    // ---- epilogue ----
    int g = lane >> 2, tig = lane & 3;
    #pragma unroll
    for (int mt = 0; mt < 2; mt++) {
        #pragma unroll
        for (int nt = 0; nt < 8; nt++) {
            int col = n0 + wn*64 + nt*8 + tig*2;
            float b0 = bias[col], b1 = bias[col+1];
            #pragma unroll
            for (int half = 0; half < 2; half++) {
                int r = m0 + wm*32 + mt*16 + g + half*8;
                if (r >= M) continue;
                float scale = rs ? rs[r] : 1.0f;
                size_t idx = (size_t)r * N + col;
                float2 o;
                o.x = acc[mt][nt][half*2+0] * scale + b0;
                o.y = acc[mt][nt][half*2+1] * scale + b1;
                if (rd) {
                    const float2 rv = *(const float2*)&rd[idx];
                    o.x += rv.x; o.y += rv.y;
                }
                if (dogelu) {
                    o.x = 0.5f*o.x*(1.0f+erff(o.x*0.70710678118654752f));
                    o.y = 0.5f*o.y*(1.0f+erff(o.y*0.70710678118654752f));
                }
                *(float2*)&C[idx] = o;
            }
        }
    }
}

// ---------------- attention: scores + scatter-max (warp per edge) ----------------
__global__ void k_score(const float* __restrict__ q, const float* __restrict__ k,
                        const int* __restrict__ es, const int* __restrict__ ed) {
    int e2 = blockIdx.x * 8 + (threadIdx.x >> 5);
    if (e2 >= E2) return;
    int lane = threadIdx.x & 31;
    int et = e2 / EP;
    int sg = es[e2] + (et ? NP : 0);
    int dg = ed[e2] + (et ? 0 : NP);
    const float* qv = q + (size_t)dg * HID_;
    const float* kv = k + (size_t)sg * HID_;
    #pragma unroll
    for (int hh = 0; hh < 8; hh++) {
        float p = qv[hh*32 + lane] * kv[hh*32 + lane];
        #pragma unroll
        for (int o = 16; o; o >>= 1) p += __shfl_xor_sync(0xffffffffu, p, o);
        if (lane == 0) {
            float s = fminf(fmaxf(p * 0.17677669529663687f, -5.0f), 5.0f);
            g_sc[(size_t)e2*8 + hh] = s;
            atomicMax(&g_m[dg*8 + hh], __float_as_uint(s + 6.0f));
        }
    }
}

// ---------------- exp + denom accumulation (4 heads/thread, red.v4) ----------------
__global__ void k_expsum(const int* __restrict__ ed) {
    int gid = blockIdx.x * blockDim.x + threadIdx.x;
    if (gid >= E2 * 2) return;
    int e2 = gid >> 1, hq = (gid & 1) * 4;
    int et = e2 / EP;
    int dg = ed[e2] + (et ? 0 : NP);
    float4 sc = *(float4*)&g_sc[(size_t)e2*8 + hq];
    const uint4 mu = *(const uint4*)&g_m[dg*8 + hq];
    sc.x = expf(sc.x - (__uint_as_float(mu.x) - 6.0f));
    sc.y = expf(sc.y - (__uint_as_float(mu.y) - 6.0f));
    sc.z = expf(sc.z - (__uint_as_float(mu.z) - 6.0f));
    sc.w = expf(sc.w - (__uint_as_float(mu.w) - 6.0f));
    *(float4*)&g_sc[(size_t)e2*8 + hq] = sc;
    red_v4(&g_den[dg*8 + hq], sc.x, sc.y, sc.z, sc.w);
}

// ---------------- alpha * v scatter (vectorized red) ----------------
__global__ void k_attn_scatter(const int* __restrict__ es, const int* __restrict__ ed) {
    long gid = (long)blockIdx.x * blockDim.x + threadIdx.x;
    if (gid >= (long)E2 * 64) return;
    int e2 = (int)(gid >> 6);
    int c  = (int)(gid & 63);
    int et = e2 / EP;
    int sg = es[e2] + (et ? NP : 0);
    int dg = ed[e2] + (et ? 0 : NP);
    int hh = c >> 3;
    float alpha = g_sc[(size_t)e2*8 + hh] / g_den[dg*8 + hh];
    const float4 vv = *(const float4*)&g_v[(size_t)sg*HID_ + c*4];
    red_v4(&g_agg[(size_t)dg*HID_ + c*4], vv.x*alpha, vv.y*alpha, vv.z*alpha, vv.w*alpha);
}

// ---------------- host orchestration ----------------
extern "C" void kernel_launch(void* const* d_in, const int* in_sizes, int n_in,
                              void* d_out, int out_size) {
    const float* h      = (const float*)d_in[0];
    const int*   es     = (const int*)  d_in[1];
    const int*   ed     = (const int*)  d_in[2];
    const float* preW   = (const float*)d_in[3];
    const float* preB   = (const float*)d_in[4];
    const float* postW  = (const float*)d_in[5];
    const float* postB  = (const float*)d_in[6];
    const float* qW     = (const float*)d_in[7];
    const float* qB     = (const float*)d_in[8];
    const float* kW     = (const float*)d_in[9];
    const float* kB     = (const float*)d_in[10];
    const float* vW     = (const float*)d_in[11];
    const float* vB     = (const float*)d_in[12];
    const float* oW     = (const float*)d_in[13];
    const float* oB     = (const float*)d_in[14];
    const float* fW1    = (const float*)d_in[15];
    const float* fB1    = (const float*)d_in[16];
    const float* fW2    = (const float*)d_in[17];
    const float* fB2    = (const float*)d_in[18];
    const float* lnPreG = (const float*)d_in[19];
    const float* lnPreB = (const float*)d_in[20];
    const float* lnAtG  = (const float*)d_in[21];
    const float* lnAtB  = (const float*)d_in[22];
    const float* lnPoG  = (const float*)d_in[23];
    const float* lnPoB  = (const float*)d_in[24];
    const float* lnFfG  = (const float*)d_in[25];
    const float* lnFfB  = (const float*)d_in[26];
    float* out = (float*)d_out;

    float *hn, *q, *k, *v, *agg, *ffn, *cd;
    __nv_bfloat16 *wbhi, *wblo;
    unsigned int *m; float *den; int *degs, *degd;
    cudaGetSymbolAddress((void**)&hn,   g_hn);
    cudaGetSymbolAddress((void**)&q,    g_q);
    cudaGetSymbolAddress((void**)&k,    g_k);
    cudaGetSymbolAddress((void**)&v,    g_v);
    cudaGetSymbolAddress((void**)&agg,  g_agg);
    cudaGetSymbolAddress((void**)&ffn,  g_ffn);
    cudaGetSymbolAddress((void**)&cd,   g_cd);
    cudaGetSymbolAddress((void**)&m,    g_m);
    cudaGetSymbolAddress((void**)&den,  g_den);
    cudaGetSymbolAddress((void**)&degs, g_degs);
    cudaGetSymbolAddress((void**)&degd, g_degd);
    cudaGetSymbolAddress((void**)&wbhi, g_wbhi);
    cudaGetSymbolAddress((void**)&wblo, g_wblo);

    const dim3 lnGrid(NP, T_);
    const dim3 g256(2, 196, 2);
    const dim3 g512(4, 196, 2);
    const int SC_BLOCKS = (long)E2 * 64 / 256;

    // weight split (deterministic per call)
    k_wconv<<<dim3(256,1,2), 256>>>(preW,  wbhi+WOFF_PRE,  wblo+WOFF_PRE,  256, 256);
    k_wconv<<<dim3(256,1,2), 256>>>(postW, wbhi+WOFF_POST, wblo+WOFF_POST, 256, 256);
    k_wconv<<<dim3(256,1,2), 256>>>(qW,    wbhi+WOFF_Q,    wblo+WOFF_Q,    256, 256);
    k_wconv<<<dim3(256,1,2), 256>>>(kW,    wbhi+WOFF_K,    wblo+WOFF_K,    256, 256);
    k_wconv<<<dim3(256,1,2), 256>>>(vW,    wbhi+WOFF_V,    wblo+WOFF_V,    256, 256);
    k_wconv<<<dim3(256,1,2), 256>>>(oW,    wbhi+WOFF_O,    wblo+WOFF_O,    256, 256);
    k_wconv<<<dim3(512,1,2), 256>>>(fW1,   wbhi+WOFF_F1,   wblo+WOFF_F1,   256, 512);
    k_wconv<<<dim3(512,1,2), 256>>>(fW2,   wbhi+WOFF_F2,   wblo+WOFF_F2,   512, 256);

    // degrees
    cudaMemsetAsync(degs, 0, sizeof(int) * T_ * NP);
    cudaMemsetAsync(degd, 0, sizeof(int) * T_ * NP);
    k_deg<<<(E2 + 255)/256, 256>>>(es, ed);
    k_degnorm<<<(NP + 255)/256, 256>>>();

    // ---- conv1 ----
    k_ln<<<lnGrid, 256>>>(h, lnPreG, lnPreB, hn);
    cudaMemsetAsync(agg, 0, sizeof(float) * (size_t)NTOT * HID_);
    k_conv_scatter<<<SC_BLOCKS, 256>>>(hn, es, ed);
    gemm_mma<<<g256, 256>>>(agg, wbhi+WOFF_PRE, wblo+WOFF_PRE, preB, cd, h, out, NP, HID_, HID_, 1, 0);

    // ---- attention ----
    k_ln<<<lnGrid, 256>>>(out, lnAtG, lnAtB, hn);
    gemm_mma<<<g256, 256>>>(hn, wbhi+WOFF_Q, wblo+WOFF_Q, qB, nullptr, nullptr, q, NP, HID_, HID_, 0, 0);
    gemm_mma<<<g256, 256>>>(hn, wbhi+WOFF_K, wblo+WOFF_K, kB, nullptr, nullptr, k, NP, HID_, HID_, 0, 0);
    gemm_mma<<<g256, 256>>>(hn, wbhi+WOFF_V, wblo+WOFF_V, vB, nullptr, nullptr, v, NP, HID_, HID_, 0, 0);
    cudaMemsetAsync(m,   0, sizeof(unsigned int) * NTOT * 8);
    cudaMemsetAsync(den, 0, sizeof(float) * NTOT * 8);
    k_score<<<(E2 + 7)/8, 256>>>(q, k, es, ed);
    k_expsum<<<(E2*2 + 255)/256, 256>>>(ed);
    cudaMemsetAsync(agg, 0, sizeof(float) * (size_t)NTOT * HID_);
    k_attn_scatter<<<SC_BLOCKS, 256>>>(es, ed);
    gemm_mma<<<g256, 256>>>(agg, wbhi+WOFF_O, wblo+WOFF_O, oB, nullptr, out, out, NP, HID_, HID_, 0, 0);

    // ---- conv2 ----
    k_ln<<<lnGrid, 256>>>(out, lnPoG, lnPoB, hn);
    cudaMemsetAsync(agg, 0, sizeof(float) * (size_t)NTOT * HID_);
    k_conv_scatter<<<SC_BLOCKS, 256>>>(hn, es, ed);
    gemm_mma<<<g256, 256>>>(agg, wbhi+WOFF_POST, wblo+WOFF_POST, postB, cd, out, out, NP, HID_, HID_, 1, 0);

    // ---- FFN ----
    k_ln<<<lnGrid, 256>>>(out, lnFfG, lnFfB, hn);
    gemm_mma<<<g512, 256>>>(hn,  wbhi+WOFF_F1, wblo+WOFF_F1, fB1, nullptr, nullptr, ffn, NP, HID_, 512, 0, 1);
    gemm_mma<<<g256, 256>>>(ffn, wbhi+WOFF_F2, wblo+WOFF_F2, fB2, nullptr, out,     out, NP, 512, HID_, 0, 0);
}

// round 5
// speedup vs baseline: 2.1182x; 1.0580x over previous
#include <cuda_runtime.h>
#include <cuda_bf16.h>
#include <math.h>

#define T_   2
#define NP   25000
#define EP   200000
#define HID_ 256
#define NTOT (T_*NP)
#define E2   (2*EP)

// ---------------- scratch (static __device__ — no allocations) ----------------
__device__ float g_hn [(size_t)T_*NP*HID_];
__device__ float g_q  [(size_t)NTOT*HID_];
__device__ float g_k  [(size_t)NTOT*HID_];
__device__ float g_v  [(size_t)NTOT*HID_];
__device__ float g_agg[(size_t)NTOT*HID_];
__device__ float g_ffn[(size_t)T_*NP*512];
__device__ float g_sc [(size_t)E2*8];
__device__ unsigned int g_m[NTOT*8];
__device__ float g_den[NTOT*8];
__device__ float g_cs [T_*NP];
__device__ float g_cd [T_*NP];
__device__ int   g_degs[T_*NP];
__device__ int   g_degd[T_*NP];
#define WCVT_TOTAL 1310720
__device__ __nv_bfloat16 g_wbhi[WCVT_TOTAL];
__device__ __nv_bfloat16 g_wblo[WCVT_TOTAL];
#define WOFF_PRE  0
#define WOFF_POST 131072
#define WOFF_Q    262144
#define WOFF_K    393216
#define WOFF_V    524288
#define WOFF_O    655360
#define WOFF_F1   786432
#define WOFF_F2   1048576

// ---------------- mma / async helpers ----------------
__device__ __forceinline__ unsigned smem_u32(const void* p) {
    unsigned a;
    asm("{ .reg .u64 t; cvta.to.shared.u64 t, %1; cvt.u32.u64 %0, t; }" : "=r"(a) : "l"(p));
    return a;
}
#define LDM4(r, a) \
    asm volatile("ldmatrix.sync.aligned.m8n8.x4.shared.b16 {%0,%1,%2,%3}, [%4];" \
        : "=r"((r)[0]),"=r"((r)[1]),"=r"((r)[2]),"=r"((r)[3]) : "r"(a))
#define MMA_BF16(c, a, b0, b1) \
    asm volatile("mma.sync.aligned.m16n8k16.row.col.f32.bf16.bf16.f32 " \
        "{%0,%1,%2,%3}, {%4,%5,%6,%7}, {%8,%9}, {%0,%1,%2,%3};" \
        : "+f"((c)[0]),"+f"((c)[1]),"+f"((c)[2]),"+f"((c)[3]) \
        : "r"((a)[0]),"r"((a)[1]),"r"((a)[2]),"r"((a)[3]), "r"(b0),"r"(b1))
#define CP16(dst, src) \
    asm volatile("cp.async.cg.shared.global [%0], [%1], 16;" :: "r"(dst), "l"(src) : "memory")
#define CP_COMMIT() asm volatile("cp.async.commit_group;" ::: "memory")
#define CP_WAIT0()  asm volatile("cp.async.wait_group 0;" ::: "memory")

__device__ __forceinline__ void red_v4(float* p, float x, float y, float z, float w) {
    asm volatile("red.global.add.v4.f32 [%0], {%1,%2,%3,%4};"
        :: "l"(p), "f"(x), "f"(y), "f"(z), "f"(w) : "memory");
}
__device__ __forceinline__ unsigned pack_bf2(__nv_bfloat16 a, __nv_bfloat16 b) {
    __nv_bfloat162 t = __halves2bfloat162(a, b);
    return *(unsigned*)&t;
}

// ---------------- helpers ----------------
__device__ __forceinline__ float block_sum(float v, float* sh) {
    #pragma unroll
    for (int o = 16; o; o >>= 1) v += __shfl_xor_sync(0xffffffffu, v, o);
    if ((threadIdx.x & 31) == 0) sh[threadIdx.x >> 5] = v;
    __syncthreads();
    float s = 0.f;
    #pragma unroll
    for (int i = 0; i < 8; i++) s += sh[i];
    __syncthreads();
    return s;
}

// ---------------- degree kernels ----------------
__global__ void k_deg(const int* __restrict__ es, const int* __restrict__ ed) {
    int gid = blockIdx.x * blockDim.x + threadIdx.x;
    if (gid >= E2) return;
    int et = gid / EP;
    atomicAdd(&g_degs[et*NP + es[gid]], 1);
    atomicAdd(&g_degd[et*NP + ed[gid]], 1);
}

__global__ void k_degnorm() {
    int n = blockIdx.x * blockDim.x + threadIdx.x;
    if (n >= NP) return;
    #pragma unroll
    for (int et = 0; et < 2; et++) {
        g_cs[et*NP + n]       = rsqrtf((float)max(g_degs[et*NP + n], 1));
        g_cd[(1-et)*NP + n]   = rsqrtf((float)max(g_degd[et*NP + n], 1));
    }
}

// ---------------- layernorm ----------------
__global__ void k_ln(const float* __restrict__ x, const float* __restrict__ g,
                     const float* __restrict__ b, float* __restrict__ y) {
    __shared__ float sh[8];
    int n = blockIdx.x, t = blockIdx.y, c = threadIdx.x;
    size_t base = ((size_t)t*NP + n) * HID_;
    float v = x[base + c];
    float mu = block_sum(v, sh) * (1.0f / HID_);
    float d = v - mu;
    float var = block_sum(d * d, sh) * (1.0f / HID_);
    y[base + c] = d * rsqrtf(var + 1e-5f) * g[t*HID_ + c] + b[t*HID_ + c];
}

// ---------------- conv aggregation scatter ----------------
__global__ void k_conv_scatter(const float* __restrict__ hn, const int* __restrict__ es,
                               const int* __restrict__ ed) {
    long gid = (long)blockIdx.x * blockDim.x + threadIdx.x;
    if (gid >= (long)E2 * 64) return;
    int e2 = (int)(gid >> 6);
    int c  = (int)(gid & 63) * 4;
    int et = e2 / EP;
    int src = es[e2], dst = ed[e2];
    float w = g_cs[et*NP + src];
    const float4 hv = *(const float4*)&hn[((size_t)et*NP + src)*HID_ + c];
    float* o = &g_agg[((size_t)(1-et)*NP + dst)*HID_ + c];
    red_v4(o, hv.x*w, hv.y*w, hv.z*w, hv.w*w);
}

// ---------------- weight split ----------------
__global__ void k_wconv(const float* __restrict__ W, __nv_bfloat16* __restrict__ hi,
                        __nv_bfloat16* __restrict__ lo, int K, int N) {
    int t = blockIdx.z;
    size_t sz = (size_t)K * N;
    W += t * sz; hi += t * sz; lo += t * sz;
    int o = blockIdx.x * 256 + threadIdx.x;
    if (o >= K * N) return;
    int n = o / K, k = o % K;
    float x = W[(size_t)k * N + n];
    __nv_bfloat16 h = __float2bfloat16_rn(x);
    hi[o] = h;
    lo[o] = __float2bfloat16_rn(x - __bfloat162float(h));
}

// ---------------- bf16-split tensor GEMM, cp.async double-buffered ----------------
// CTA 128x128, 8 warps (4m x 2n), K-chunk 32, 2-stage pipeline.
#define PAD 40
#define ST_A   (128*PAD)          // elements per A buffer (hi or lo)
#define ST_ALL (4*128*PAD)        // elements per stage (Ahi,Alo,Bhi,Blo)
#define GSMEM  (2*ST_ALL*2)       // bytes: 2 stages * 4 bufs * 5120 elts * 2B = 81920

__global__ void __launch_bounds__(256, 2) gemm_mma(
    const float* __restrict__ A, const __nv_bfloat16* __restrict__ Bhi_g,
    const __nv_bfloat16* __restrict__ Blo_g, const float* __restrict__ bias,
    const float* __restrict__ rowscale, const float* __restrict__ resid,
    float* __restrict__ C, int M, int K, int N, int wswap, int dogelu)
{
    extern __shared__ __nv_bfloat16 smem[];

    int tid = threadIdx.x;
    int warp = tid >> 5, lane = tid & 31;
    int wm = warp & 3, wn = warp >> 2;
    int t = blockIdx.z;
    int wi = wswap ? (1 - t) : t;

    A     += (size_t)t  * M * K;
    Bhi_g += (size_t)wi * K * N;
    Blo_g += (size_t)wi * K * N;
    bias  += (size_t)wi * N;
    const float* rs = rowscale ? rowscale + (size_t)t * M : nullptr;
    const float* rd = resid ? resid + (size_t)t * M * N : nullptr;
    C += (size_t)t * M * N;

    int m0 = blockIdx.y * 128, n0 = blockIdx.x * 128;

    float acc[2][8][4];
    #pragma unroll
    for (int i = 0; i < 2; i++)
        #pragma unroll
        for (int j = 0; j < 8; j++)
            #pragma unroll
            for (int l = 0; l < 4; l++) acc[i][j][l] = 0.f;

    int lrow = lane & 7, lsel = lane >> 3;
    int a_r = (lsel & 1) * 8 + lrow;
    int a_c = (lsel >> 1) * 8;
    int b_r = (lsel >> 1) * 8 + lrow;
    int b_c = (lsel & 1) * 8;

    unsigned usm = smem_u32(smem);

    // per-thread A-load geometry: 4 float4s, rows tid>>3 + 32*i? Keep prior mapping:
    // f = i*256+tid; row=f>>3 (0..127), c4=f&7
    int arow0 = tid >> 3, ac4 = tid & 7;
    bool avalid = true; // rows handled per-i below

    // B cp.async geometry: f = i*256+tid; row=f>>2, c4=f&3
    int brow0 = tid >> 2, bc4 = tid & 3;

    int nchunks = K >> 5;

    float4 va[4];
    // ---- prologue: A chunk0 -> regs, B chunk0 -> stage 0 via cp.async ----
    #pragma unroll
    for (int i = 0; i < 4; i++) {
        int row = arow0 + i * 32;
        int gm = m0 + row;
        va[i] = (gm < M) ? *(const float4*)&A[(size_t)gm * K + (ac4 << 2)]
                         : make_float4(0.f, 0.f, 0.f, 0.f);
    }
    {
        unsigned ubh = usm + 2u * (2 * ST_A);   // stage0 Bhi
        unsigned ubl = usm + 2u * (3 * ST_A);   // stage0 Blo
        #pragma unroll
        for (int i = 0; i < 2; i++) {
            int row = brow0 + i * 64, c4 = bc4;
            size_t go = (size_t)(n0 + row) * K + (c4 << 3);
            unsigned loc = 2u * (unsigned)(row * PAD + c4 * 8);
            CP16(ubh + loc, &Bhi_g[go]);
            CP16(ubl + loc, &Blo_g[go]);
        }
        CP_COMMIT();
    }

    for (int c = 0; c < nchunks; c++) {
        int s = c & 1;
        unsigned base = usm + 2u * (unsigned)(s * ST_ALL);
        unsigned uah = base, ual = base + 2u*ST_A, ubh = base + 2u*2*ST_A, ubl = base + 2u*3*ST_A;

        CP_WAIT0();                      // B stage s landed
        // split A regs -> smem stage s
        #pragma unroll
        for (int i = 0; i < 4; i++) {
            int row = arow0 + i * 32;
            float4 v = va[i];
            __nv_bfloat16 h0 = __float2bfloat16_rn(v.x), h1 = __float2bfloat16_rn(v.y);
            __nv_bfloat16 h2 = __float2bfloat16_rn(v.z), h3 = __float2bfloat16_rn(v.w);
            uint2 hh, ll;
            hh.x = pack_bf2(h0, h1); hh.y = pack_bf2(h2, h3);
            ll.x = pack_bf2(__float2bfloat16_rn(v.x - __bfloat162float(h0)),
                            __float2bfloat16_rn(v.y - __bfloat162float(h1)));
            ll.y = pack_bf2(__float2bfloat16_rn(v.z - __bfloat162float(h2)),
                            __float2bfloat16_rn(v.w - __bfloat162float(h3)));
            unsigned loc = 2u * (unsigned)(row * PAD + ac4 * 4);
            *(uint2*)(smem + ((uah - usm) >> 1) + (loc >> 1)) = hh;
            *(uint2*)(smem + ((ual - usm) >> 1) + (loc >> 1)) = ll;
        }
        __syncthreads();

        // prefetch next chunk
        if (c + 1 < nchunks) {
            int koff = (c + 1) << 5;
            #pragma unroll
            for (int i = 0; i < 4; i++) {
                int row = arow0 + i * 32;
                int gm = m0 + row;
                va[i] = (gm < M) ? *(const float4*)&A[(size_t)gm * K + koff + (ac4 << 2)]
                                 : make_float4(0.f, 0.f, 0.f, 0.f);
            }
            unsigned nb = usm + 2u * (unsigned)((1 - s) * ST_ALL);
            unsigned nbh = nb + 2u*2*ST_A, nbl = nb + 2u*3*ST_A;
            #pragma unroll
            for (int i = 0; i < 2; i++) {
                int row = brow0 + i * 64, c4 = bc4;
                size_t go = (size_t)(n0 + row) * K + koff + (c4 << 3);
                unsigned loc = 2u * (unsigned)(row * PAD + c4 * 8);
                CP16(nbh + loc, &Bhi_g[go]);
                CP16(nbl + loc, &Blo_g[go]);
            }
            CP_COMMIT();
        }

        // compute on stage s
        #pragma unroll
        for (int ks = 0; ks < 2; ks++) {
            int kk = ks * 16;
            unsigned ah[2][4], al[2][4];
            #pragma unroll
            for (int mt = 0; mt < 2; mt++) {
                unsigned off = 2u * (unsigned)((wm*32 + mt*16 + a_r) * PAD + kk + a_c);
                LDM4(ah[mt], uah + off);
                LDM4(al[mt], ual + off);
            }
            #pragma unroll
            for (int bi = 0; bi < 4; bi++) {
                unsigned off = 2u * (unsigned)((wn*64 + bi*16 + b_r) * PAD + kk + b_c);
                unsigned bh[4], bl[4];
                LDM4(bh, ubh + off);
                LDM4(bl, ubl + off);
                #pragma unroll
                for (int mt = 0; mt < 2; mt++) {
                    #pragma unroll
                    for (int j = 0; j < 2; j++) {
                        float* cc = acc[mt][bi*2 + j];
                        MMA_BF16(cc, ah[mt], bh[j*2], bh[j*2+1]);
                        MMA_BF16(cc, ah[mt], bl[j*2], bl[j*2+1]);
                        MMA_BF16(cc, al[mt], bh[j*2], bh[j*2+1]);
                    }
                }
            }
        }
        __syncthreads();
    }

    // ---- epilogue ----
    int g = lane >> 2, tig = lane & 3;
    #pragma unroll
    for (int mt = 0; mt < 2; mt++) {
        #pragma unroll
        for (int nt = 0; nt < 8; nt++) {
            int col = n0 + wn*64 + nt*8 + tig*2;
            float b0 = bias[col], b1 = bias[col+1];
            #pragma unroll
            for (int half = 0; half < 2; half++) {
                int r = m0 + wm*32 + mt*16 + g + half*8;
                if (r >= M) continue;
                float scale = rs ? rs[r] : 1.0f;
                size_t idx = (size_t)r * N + col;
                float2 o;
                o.x = acc[mt][nt][half*2+0] * scale + b0;
                o.y = acc[mt][nt][half*2+1] * scale + b1;
                if (rd) {
                    const float2 rv = *(const float2*)&rd[idx];
                    o.x += rv.x; o.y += rv.y;
                }
                if (dogelu) {
                    o.x = 0.5f*o.x*(1.0f+erff(o.x*0.70710678118654752f));
                    o.y = 0.5f*o.y*(1.0f+erff(o.y*0.70710678118654752f));
                }
                *(float2*)&C[idx] = o;
            }
        }
    }
}

// ---------------- attention scores + scatter-max ----------------
__global__ void k_score(const float* __restrict__ q, const float* __restrict__ k,
                        const int* __restrict__ es, const int* __restrict__ ed) {
    int e2 = blockIdx.x * 8 + (threadIdx.x >> 5);
    if (e2 >= E2) return;
    int lane = threadIdx.x & 31;
    int et = e2 / EP;
    int sg = es[e2] + (et ? NP : 0);
    int dg = ed[e2] + (et ? 0 : NP);
    const float* qv = q + (size_t)dg * HID_;
    const float* kv = k + (size_t)sg * HID_;
    #pragma unroll
    for (int hh = 0; hh < 8; hh++) {
        float p = qv[hh*32 + lane] * kv[hh*32 + lane];
        #pragma unroll
        for (int o = 16; o; o >>= 1) p += __shfl_xor_sync(0xffffffffu, p, o);
        if (lane == 0) {
            float s = fminf(fmaxf(p * 0.17677669529663687f, -5.0f), 5.0f);
            g_sc[(size_t)e2*8 + hh] = s;
            atomicMax(&g_m[dg*8 + hh], __float_as_uint(s + 6.0f));
        }
    }
}

// ---------------- exp + denom ----------------
__global__ void k_expsum(const int* __restrict__ ed) {
    int gid = blockIdx.x * blockDim.x + threadIdx.x;
    if (gid >= E2 * 2) return;
    int e2 = gid >> 1, hq = (gid & 1) * 4;
    int et = e2 / EP;
    int dg = ed[e2] + (et ? 0 : NP);
    float4 sc = *(float4*)&g_sc[(size_t)e2*8 + hq];
    const uint4 mu = *(const uint4*)&g_m[dg*8 + hq];
    sc.x = expf(sc.x - (__uint_as_float(mu.x) - 6.0f));
    sc.y = expf(sc.y - (__uint_as_float(mu.y) - 6.0f));
    sc.z = expf(sc.z - (__uint_as_float(mu.z) - 6.0f));
    sc.w = expf(sc.w - (__uint_as_float(mu.w) - 6.0f));
    *(float4*)&g_sc[(size_t)e2*8 + hq] = sc;
    red_v4(&g_den[dg*8 + hq], sc.x, sc.y, sc.z, sc.w);
}

// ---------------- alpha * v scatter ----------------
__global__ void k_attn_scatter(const int* __restrict__ es, const int* __restrict__ ed) {
    long gid = (long)blockIdx.x * blockDim.x + threadIdx.x;
    if (gid >= (long)E2 * 64) return;
    int e2 = (int)(gid >> 6);
    int c  = (int)(gid & 63);
    int et = e2 / EP;
    int sg = es[e2] + (et ? NP : 0);
    int dg = ed[e2] + (et ? 0 : NP);
    int hh = c >> 3;
    float alpha = g_sc[(size_t)e2*8 + hh] / g_den[dg*8 + hh];
    const float4 vv = *(const float4*)&g_v[(size_t)sg*HID_ + c*4];
    red_v4(&g_agg[(size_t)dg*HID_ + c*4], vv.x*alpha, vv.y*alpha, vv.z*alpha, vv.w*alpha);
}

// ---------------- host orchestration ----------------
extern "C" void kernel_launch(void* const* d_in, const int* in_sizes, int n_in,
                              void* d_out, int out_size) {
    const float* h      = (const float*)d_in[0];
    const int*   es     = (const int*)  d_in[1];
    const int*   ed     = (const int*)  d_in[2];
    const float* preW   = (const float*)d_in[3];
    const float* preB   = (const float*)d_in[4];
    const float* postW  = (const float*)d_in[5];
    const float* postB  = (const float*)d_in[6];
    const float* qW     = (const float*)d_in[7];
    const float* qB     = (const float*)d_in[8];
    const float* kW     = (const float*)d_in[9];
    const float* kB     = (const float*)d_in[10];
    const float* vW     = (const float*)d_in[11];
    const float* vB     = (const float*)d_in[12];
    const float* oW     = (const float*)d_in[13];
    const float* oB     = (const float*)d_in[14];
    const float* fW1    = (const float*)d_in[15];
    const float* fB1    = (const float*)d_in[16];
    const float* fW2    = (const float*)d_in[17];
    const float* fB2    = (const float*)d_in[18];
    const float* lnPreG = (const float*)d_in[19];
    const float* lnPreB = (const float*)d_in[20];
    const float* lnAtG  = (const float*)d_in[21];
    const float* lnAtB  = (const float*)d_in[22];
    const float* lnPoG  = (const float*)d_in[23];
    const float* lnPoB  = (const float*)d_in[24];
    const float* lnFfG  = (const float*)d_in[25];
    const float* lnFfB  = (const float*)d_in[26];
    float* out = (float*)d_out;

    float *hn, *q, *k, *v, *agg, *ffn, *cd;
    __nv_bfloat16 *wbhi, *wblo;
    unsigned int *m; float *den; int *degs, *degd;
    cudaGetSymbolAddress((void**)&hn,   g_hn);
    cudaGetSymbolAddress((void**)&q,    g_q);
    cudaGetSymbolAddress((void**)&k,    g_k);
    cudaGetSymbolAddress((void**)&v,    g_v);
    cudaGetSymbolAddress((void**)&agg,  g_agg);
    cudaGetSymbolAddress((void**)&ffn,  g_ffn);
    cudaGetSymbolAddress((void**)&cd,   g_cd);
    cudaGetSymbolAddress((void**)&m,    g_m);
    cudaGetSymbolAddress((void**)&den,  g_den);
    cudaGetSymbolAddress((void**)&degs, g_degs);
    cudaGetSymbolAddress((void**)&degd, g_degd);
    cudaGetSymbolAddress((void**)&wbhi, g_wbhi);
    cudaGetSymbolAddress((void**)&wblo, g_wblo);

    cudaFuncSetAttribute(gemm_mma, cudaFuncAttributeMaxDynamicSharedMemorySize, GSMEM);

    const dim3 lnGrid(NP, T_);
    const dim3 g256(2, 196, 2);
    const dim3 g512(4, 196, 2);
    const int SC_BLOCKS = (long)E2 * 64 / 256;

    // weight split
    k_wconv<<<dim3(256,1,2), 256>>>(preW,  wbhi+WOFF_PRE,  wblo+WOFF_PRE,  256, 256);
    k_wconv<<<dim3(256,1,2), 256>>>(postW, wbhi+WOFF_POST, wblo+WOFF_POST, 256, 256);
    k_wconv<<<dim3(256,1,2), 256>>>(qW,    wbhi+WOFF_Q,    wblo+WOFF_Q,    256, 256);
    k_wconv<<<dim3(256,1,2), 256>>>(kW,    wbhi+WOFF_K,    wblo+WOFF_K,    256, 256);
    k_wconv<<<dim3(256,1,2), 256>>>(vW,    wbhi+WOFF_V,    wblo+WOFF_V,    256, 256);
    k_wconv<<<dim3(256,1,2), 256>>>(oW,    wbhi+WOFF_O,    wblo+WOFF_O,    256, 256);
    k_wconv<<<dim3(512,1,2), 256>>>(fW1,   wbhi+WOFF_F1,   wblo+WOFF_F1,   256, 512);
    k_wconv<<<dim3(512,1,2), 256>>>(fW2,   wbhi+WOFF_F2,   wblo+WOFF_F2,   512, 256);

    // degrees
    cudaMemsetAsync(degs, 0, sizeof(int) * T_ * NP);
    cudaMemsetAsync(degd, 0, sizeof(int) * T_ * NP);
    k_deg<<<(E2 + 255)/256, 256>>>(es, ed);
    k_degnorm<<<(NP + 255)/256, 256>>>();

    // ---- conv1 ----
    k_ln<<<lnGrid, 256>>>(h, lnPreG, lnPreB, hn);
    cudaMemsetAsync(agg, 0, sizeof(float) * (size_t)NTOT * HID_);
    k_conv_scatter<<<SC_BLOCKS, 256>>>(hn, es, ed);
    gemm_mma<<<g256, 256, GSMEM>>>(agg, wbhi+WOFF_PRE, wblo+WOFF_PRE, preB, cd, h, out, NP, HID_, HID_, 1, 0);

    // ---- attention ----
    k_ln<<<lnGrid, 256>>>(out, lnAtG, lnAtB, hn);
    gemm_mma<<<g256, 256, GSMEM>>>(hn, wbhi+WOFF_Q, wblo+WOFF_Q, qB, nullptr, nullptr, q, NP, HID_, HID_, 0, 0);
    gemm_mma<<<g256, 256, GSMEM>>>(hn, wbhi+WOFF_K, wblo+WOFF_K, kB, nullptr, nullptr, k, NP, HID_, HID_, 0, 0);
    gemm_mma<<<g256, 256, GSMEM>>>(hn, wbhi+WOFF_V, wblo+WOFF_V, vB, nullptr, nullptr, v, NP, HID_, HID_, 0, 0);
    cudaMemsetAsync(m,   0, sizeof(unsigned int) * NTOT * 8);
    cudaMemsetAsync(den, 0, sizeof(float) * NTOT * 8);
    k_score<<<(E2 + 7)/8, 256>>>(q, k, es, ed);
    k_expsum<<<(E2*2 + 255)/256, 256>>>(ed);
    cudaMemsetAsync(agg, 0, sizeof(float) * (size_t)NTOT * HID_);
    k_attn_scatter<<<SC_BLOCKS, 256>>>(es, ed);
    gemm_mma<<<g256, 256, GSMEM>>>(agg, wbhi+WOFF_O, wblo+WOFF_O, oB, nullptr, out, out, NP, HID_, HID_, 0, 0);

    // ---- conv2 ----
    k_ln<<<lnGrid, 256>>>(out, lnPoG, lnPoB, hn);
    cudaMemsetAsync(agg, 0, sizeof(float) * (size_t)NTOT * HID_);
    k_conv_scatter<<<SC_BLOCKS, 256>>>(hn, es, ed);
    gemm_mma<<<g256, 256, GSMEM>>>(agg, wbhi+WOFF_POST, wblo+WOFF_POST, postB, cd, out, out, NP, HID_, HID_, 1, 0);

    // ---- FFN ----
    k_ln<<<lnGrid, 256>>>(out, lnFfG, lnFfB, hn);
    gemm_mma<<<g512, 256, GSMEM>>>(hn,  wbhi+WOFF_F1, wblo+WOFF_F1, fB1, nullptr, nullptr, ffn, NP, HID_, 512, 0, 1);
    gemm_mma<<<g256, 256, GSMEM>>>(ffn, wbhi+WOFF_F2, wblo+WOFF_F2, fB2, nullptr, out,     out, NP, 512, HID_, 0, 0);
}

// round 6
// speedup vs baseline: 2.1370x; 1.0089x over previous
#include <cuda_runtime.h>
#include <cuda_bf16.h>
#include <math.h>

#define T_   2
#define NP   25000
#define EP   200000
#define HID_ 256
#define NTOT (T_*NP)
#define E2   (2*EP)

// ---------------- scratch (static __device__ — no allocations) ----------------
__device__ float g_hn [(size_t)T_*NP*HID_];       // fp32 LN out (conv paths)
__device__ float g_q  [(size_t)NTOT*HID_];
__device__ float g_k  [(size_t)NTOT*HID_];
__device__ float g_v  [(size_t)NTOT*HID_];
__device__ float g_agg[(size_t)NTOT*HID_];
__device__ float g_sc [(size_t)E2*8];             // ex values
__device__ float g_den[NTOT*8];
__device__ float g_cs [T_*NP];
__device__ float g_cd [T_*NP];
__device__ int   g_degs[T_*NP];
__device__ int   g_degd[T_*NP];
// split A operands (bf16 hi/lo)
__device__ __nv_bfloat16 g_ahi[(size_t)NTOT*HID_];
__device__ __nv_bfloat16 g_alo[(size_t)NTOT*HID_];
__device__ __nv_bfloat16 g_fhi[(size_t)NTOT*512];
__device__ __nv_bfloat16 g_flo[(size_t)NTOT*512];
// split weights, bf16, layout [matrix][t][N][K]
#define WCVT_TOTAL 1310720
__device__ __nv_bfloat16 g_wbhi[WCVT_TOTAL];
__device__ __nv_bfloat16 g_wblo[WCVT_TOTAL];
#define WOFF_PRE  0
#define WOFF_POST 131072
#define WOFF_Q    262144
#define WOFF_K    393216
#define WOFF_V    524288
#define WOFF_O    655360
#define WOFF_F1   786432
#define WOFF_F2   1048576

// ---------------- mma / async helpers ----------------
__device__ __forceinline__ unsigned smem_u32(const void* p) {
    unsigned a;
    asm("{ .reg .u64 t; cvta.to.shared.u64 t, %1; cvt.u32.u64 %0, t; }" : "=r"(a) : "l"(p));
    return a;
}
#define LDM4(r, a) \
    asm volatile("ldmatrix.sync.aligned.m8n8.x4.shared.b16 {%0,%1,%2,%3}, [%4];" \
        : "=r"((r)[0]),"=r"((r)[1]),"=r"((r)[2]),"=r"((r)[3]) : "r"(a))
#define MMA_BF16(c, a, b0, b1) \
    asm volatile("mma.sync.aligned.m16n8k16.row.col.f32.bf16.bf16.f32 " \
        "{%0,%1,%2,%3}, {%4,%5,%6,%7}, {%8,%9}, {%0,%1,%2,%3};" \
        : "+f"((c)[0]),"+f"((c)[1]),"+f"((c)[2]),"+f"((c)[3]) \
        : "r"((a)[0]),"r"((a)[1]),"r"((a)[2]),"r"((a)[3]), "r"(b0),"r"(b1))
#define CP16(dst, src) \
    asm volatile("cp.async.cg.shared.global [%0], [%1], 16;" :: "r"(dst), "l"(src) : "memory")
#define CP_COMMIT() asm volatile("cp.async.commit_group;" ::: "memory")
#define CP_WAIT0()  asm volatile("cp.async.wait_group 0;" ::: "memory")

__device__ __forceinline__ void red_v4(float* p, float x, float y, float z, float w) {
    asm volatile("red.global.add.v4.f32 [%0], {%1,%2,%3,%4};"
        :: "l"(p), "f"(x), "f"(y), "f"(z), "f"(w) : "memory");
}
__device__ __forceinline__ unsigned pack_bf2(__nv_bfloat16 a, __nv_bfloat16 b) {
    __nv_bfloat162 t = __halves2bfloat162(a, b);
    return *(unsigned*)&t;
}

// ---------------- helpers ----------------
__device__ __forceinline__ float block_sum(float v, float* sh) {
    #pragma unroll
    for (int o = 16; o; o >>= 1) v += __shfl_xor_sync(0xffffffffu, v, o);
    if ((threadIdx.x & 31) == 0) sh[threadIdx.x >> 5] = v;
    __syncthreads();
    float s = 0.f;
    #pragma unroll
    for (int i = 0; i < 8; i++) s += sh[i];
    __syncthreads();
    return s;
}

// ---------------- degree kernels ----------------
__global__ void k_deg(const int* __restrict__ es, const int* __restrict__ ed) {
    int gid = blockIdx.x * blockDim.x + threadIdx.x;
    if (gid >= E2) return;
    int et = gid / EP;
    atomicAdd(&g_degs[et*NP + es[gid]], 1);
    atomicAdd(&g_degd[et*NP + ed[gid]], 1);
}

__global__ void k_degnorm() {
    int n = blockIdx.x * blockDim.x + threadIdx.x;
    if (n >= NP) return;
    #pragma unroll
    for (int et = 0; et < 2; et++) {
        g_cs[et*NP + n]       = rsqrtf((float)max(g_degs[et*NP + n], 1));
        g_cd[(1-et)*NP + n]   = rsqrtf((float)max(g_degd[et*NP + n], 1));
    }
}

// ---------------- layernorm (fp32 out, conv paths) ----------------
__global__ void k_ln(const float* __restrict__ x, const float* __restrict__ g,
                     const float* __restrict__ b, float* __restrict__ y) {
    __shared__ float sh[8];
    int n = blockIdx.x, t = blockIdx.y, c = threadIdx.x;
    size_t base = ((size_t)t*NP + n) * HID_;
    float v = x[base + c];
    float mu = block_sum(v, sh) * (1.0f / HID_);
    float d = v - mu;
    float var = block_sum(d * d, sh) * (1.0f / HID_);
    y[base + c] = d * rsqrtf(var + 1e-5f) * g[t*HID_ + c] + b[t*HID_ + c];
}

// ---------------- layernorm with split bf16 output (GEMM-A paths) ----------------
__global__ void k_ln_split(const float* __restrict__ x, const float* __restrict__ g,
                           const float* __restrict__ b) {
    __shared__ float sh[8];
    int n = blockIdx.x, t = blockIdx.y, c = threadIdx.x;
    size_t base = ((size_t)t*NP + n) * HID_;
    float v = x[base + c];
    float mu = block_sum(v, sh) * (1.0f / HID_);
    float d = v - mu;
    float var = block_sum(d * d, sh) * (1.0f / HID_);
    float y = d * rsqrtf(var + 1e-5f) * g[t*HID_ + c] + b[t*HID_ + c];
    __nv_bfloat16 hi = __float2bfloat16_rn(y);
    g_ahi[base + c] = hi;
    g_alo[base + c] = __float2bfloat16_rn(y - __bfloat162float(hi));
}

// ---------------- fp32 buffer -> bf16 hi/lo split ----------------
__global__ void k_split(const float* __restrict__ x) {
    size_t gid = ((size_t)blockIdx.x * blockDim.x + threadIdx.x) * 4;
    if (gid >= (size_t)NTOT * HID_) return;
    float4 v = *(const float4*)&x[gid];
    __nv_bfloat16 h0 = __float2bfloat16_rn(v.x), h1 = __float2bfloat16_rn(v.y);
    __nv_bfloat16 h2 = __float2bfloat16_rn(v.z), h3 = __float2bfloat16_rn(v.w);
    uint2 hh, ll;
    hh.x = pack_bf2(h0, h1); hh.y = pack_bf2(h2, h3);
    ll.x = pack_bf2(__float2bfloat16_rn(v.x - __bfloat162float(h0)),
                    __float2bfloat16_rn(v.y - __bfloat162float(h1)));
    ll.y = pack_bf2(__float2bfloat16_rn(v.z - __bfloat162float(h2)),
                    __float2bfloat16_rn(v.w - __bfloat162float(h3)));
    *(uint2*)&g_ahi[gid] = hh;
    *(uint2*)&g_alo[gid] = ll;
}

// ---------------- conv aggregation scatter ----------------
__global__ void k_conv_scatter(const float* __restrict__ hn, const int* __restrict__ es,
                               const int* __restrict__ ed) {
    long gid = (long)blockIdx.x * blockDim.x + threadIdx.x;
    if (gid >= (long)E2 * 64) return;
    int e2 = (int)(gid >> 6);
    int c  = (int)(gid & 63) * 4;
    int et = e2 / EP;
    int src = es[e2], dst = ed[e2];
    float w = g_cs[et*NP + src];
    const float4 hv = *(const float4*)&hn[((size_t)et*NP + src)*HID_ + c];
    float* o = &g_agg[((size_t)(1-et)*NP + dst)*HID_ + c];
    red_v4(o, hv.x*w, hv.y*w, hv.z*w, hv.w*w);
}

// ---------------- weight split ----------------
__global__ void k_wconv(const float* __restrict__ W, __nv_bfloat16* __restrict__ hi,
                        __nv_bfloat16* __restrict__ lo, int K, int N) {
    int t = blockIdx.z;
    size_t sz = (size_t)K * N;
    W += t * sz; hi += t * sz; lo += t * sz;
    int o = blockIdx.x * 256 + threadIdx.x;
    if (o >= K * N) return;
    int n = o / K, k = o % K;
    float x = W[(size_t)k * N + n];
    __nv_bfloat16 h = __float2bfloat16_rn(x);
    hi[o] = h;
    lo[o] = __float2bfloat16_rn(x - __bfloat162float(h));
}

// ---------------- bf16-split tensor GEMM, all-cp.async double-buffered ----------------
// A pre-split bf16 hi/lo [t][M][K]; B pre-split [t][N][K].
// CTA 128x128, 8 warps (4m x 2n), K-chunk 32, 2-stage pipeline.
#define PAD 40
#define ST_A   (128*PAD)
#define ST_ALL (4*128*PAD)
#define GSMEM  (2*ST_ALL*2)

__global__ void __launch_bounds__(256, 2) gemm_mma(
    const __nv_bfloat16* __restrict__ Ahi_g, const __nv_bfloat16* __restrict__ Alo_g,
    const __nv_bfloat16* __restrict__ Bhi_g, const __nv_bfloat16* __restrict__ Blo_g,
    const float* __restrict__ bias, const float* __restrict__ rowscale,
    const float* __restrict__ resid, float* __restrict__ C,
    __nv_bfloat16* __restrict__ Chi, __nv_bfloat16* __restrict__ Clo,
    int M, int K, int N, int wswap, int dogelu)
{
    extern __shared__ __nv_bfloat16 smem[];

    int tid = threadIdx.x;
    int warp = tid >> 5, lane = tid & 31;
    int wm = warp & 3, wn = warp >> 2;
    int t = blockIdx.z;
    int wi = wswap ? (1 - t) : t;

    Ahi_g += (size_t)t  * M * K;
    Alo_g += (size_t)t  * M * K;
    Bhi_g += (size_t)wi * K * N;
    Blo_g += (size_t)wi * K * N;
    bias  += (size_t)wi * N;
    const float* rs = rowscale ? rowscale + (size_t)t * M : nullptr;
    const float* rd = resid ? resid + (size_t)t * M * N : nullptr;
    C   += (size_t)t * M * N;
    if (Chi) { Chi += (size_t)t * M * N; Clo += (size_t)t * M * N; }

    int m0 = blockIdx.y * 128, n0 = blockIdx.x * 128;

    float acc[2][8][4];
    #pragma unroll
    for (int i = 0; i < 2; i++)
        #pragma unroll
        for (int j = 0; j < 8; j++)
            #pragma unroll
            for (int l = 0; l < 4; l++) acc[i][j][l] = 0.f;

    int lrow = lane & 7, lsel = lane >> 3;
    int a_r = (lsel & 1) * 8 + lrow;
    int a_c = (lsel >> 1) * 8;
    int b_r = (lsel >> 1) * 8 + lrow;
    int b_c = (lsel & 1) * 8;

    unsigned usm = smem_u32(smem);

    // cp.async geometry: f = i*256+tid (i<2); row=f>>2 (0..127), seg=f&3 (16B units)
    int grow = tid >> 2, gseg = tid & 3;

    int nchunks = K >> 5;

    // ---- prologue: chunk 0 -> stage 0 ----
    {
        unsigned base = usm;
        #pragma unroll
        for (int i = 0; i < 2; i++) {
            int row = grow + i * 64;
            unsigned loc = 2u * (unsigned)(row * PAD + gseg * 8);
            size_t goa = (size_t)(m0 + row) * K + (gseg << 3);
            size_t gob = (size_t)(n0 + row) * K + (gseg << 3);
            CP16(base + loc,               &Ahi_g[goa]);
            CP16(base + 2u*ST_A + loc,     &Alo_g[goa]);
            CP16(base + 2u*2*ST_A + loc,   &Bhi_g[gob]);
            CP16(base + 2u*3*ST_A + loc,   &Blo_g[gob]);
        }
        CP_COMMIT();
    }

    for (int c = 0; c < nchunks; c++) {
        int s = c & 1;
        unsigned base = usm + 2u * (unsigned)(s * ST_ALL);
        unsigned uah = base, ual = base + 2u*ST_A, ubh = base + 2u*2*ST_A, ubl = base + 2u*3*ST_A;

        CP_WAIT0();
        __syncthreads();

        // prefetch next chunk into other stage
        if (c + 1 < nchunks) {
            int koff = (c + 1) << 5;
            unsigned nb = usm + 2u * (unsigned)((1 - s) * ST_ALL);
            #pragma unroll
            for (int i = 0; i < 2; i++) {
                int row = grow + i * 64;
                unsigned loc = 2u * (unsigned)(row * PAD + gseg * 8);
                size_t goa = (size_t)(m0 + row) * K + koff + (gseg << 3);
                size_t gob = (size_t)(n0 + row) * K + koff + (gseg << 3);
                CP16(nb + loc,             &Ahi_g[goa]);
                CP16(nb + 2u*ST_A + loc,   &Alo_g[goa]);
                CP16(nb + 2u*2*ST_A + loc, &Bhi_g[gob]);
                CP16(nb + 2u*3*ST_A + loc, &Blo_g[gob]);
            }
            CP_COMMIT();
        }

        // compute on stage s
        #pragma unroll
        for (int ks = 0; ks < 2; ks++) {
            int kk = ks * 16;
            unsigned ah[2][4], al[2][4];
            #pragma unroll
            for (int mt = 0; mt < 2; mt++) {
                unsigned off = 2u * (unsigned)((wm*32 + mt*16 + a_r) * PAD + kk + a_c);
                LDM4(ah[mt], uah + off);
                LDM4(al[mt], ual + off);
            }
            #pragma unroll
            for (int bi = 0; bi < 4; bi++) {
                unsigned off = 2u * (unsigned)((wn*64 + bi*16 + b_r) * PAD + kk + b_c);
                unsigned bh[4], bl[4];
                LDM4(bh, ubh + off);
                LDM4(bl, ubl + off);
                #pragma unroll
                for (int mt = 0; mt < 2; mt++) {
                    #pragma unroll
                    for (int j = 0; j < 2; j++) {
                        float* cc = acc[mt][bi*2 + j];
                        MMA_BF16(cc, ah[mt], bh[j*2], bh[j*2+1]);
                        MMA_BF16(cc, ah[mt], bl[j*2], bl[j*2+1]);
                        MMA_BF16(cc, al[mt], bh[j*2], bh[j*2+1]);
                    }
                }
            }
        }
        __syncthreads();
    }

    // ---- epilogue ----
    int g = lane >> 2, tig = lane & 3;
    #pragma unroll
    for (int mt = 0; mt < 2; mt++) {
        #pragma unroll
        for (int nt = 0; nt < 8; nt++) {
            int col = n0 + wn*64 + nt*8 + tig*2;
            float b0 = bias[col], b1 = bias[col+1];
            #pragma unroll
            for (int half = 0; half < 2; half++) {
                int r = m0 + wm*32 + mt*16 + g + half*8;
                if (r >= M) continue;
                float scale = rs ? rs[r] : 1.0f;
                size_t idx = (size_t)r * N + col;
                float2 o;
                o.x = acc[mt][nt][half*2+0] * scale + b0;
                o.y = acc[mt][nt][half*2+1] * scale + b1;
                if (rd) {
                    const float2 rv = *(const float2*)&rd[idx];
                    o.x += rv.x; o.y += rv.y;
                }
                if (dogelu) {
                    o.x = 0.5f*o.x*(1.0f+erff(o.x*0.70710678118654752f));
                    o.y = 0.5f*o.y*(1.0f+erff(o.y*0.70710678118654752f));
                }
                if (Chi) {
                    __nv_bfloat16 h0 = __float2bfloat16_rn(o.x);
                    __nv_bfloat16 h1 = __float2bfloat16_rn(o.y);
                    *(unsigned*)&Chi[idx] = pack_bf2(h0, h1);
                    *(unsigned*)&Clo[idx] = pack_bf2(
                        __float2bfloat16_rn(o.x - __bfloat162float(h0)),
                        __float2bfloat16_rn(o.y - __bfloat162float(h1)));
                } else {
                    *(float2*)&C[idx] = o;
                }
            }
        }
    }
}

// ---------------- attention: fused score + exp + denom ----------------
// scores clipped to [-5,5] so exp() cannot overflow; max-subtraction cancels
// exactly in alpha = ex/denom, so it is omitted.
__global__ void k_score(const float* __restrict__ q, const float* __restrict__ k,
                        const int* __restrict__ es, const int* __restrict__ ed) {
    int e2 = blockIdx.x * 8 + (threadIdx.x >> 5);
    if (e2 >= E2) return;
    int lane = threadIdx.x & 31;
    int et = e2 / EP;
    int sg = es[e2] + (et ? NP : 0);
    int dg = ed[e2] + (et ? 0 : NP);
    const float* qv = q + (size_t)dg * HID_;
    const float* kv = k + (size_t)sg * HID_;
    float ex[8];
    #pragma unroll
    for (int hh = 0; hh < 8; hh++) {
        float p = qv[hh*32 + lane] * kv[hh*32 + lane];
        #pragma unroll
        for (int o = 16; o; o >>= 1) p += __shfl_xor_sync(0xffffffffu, p, o);
        float s = fminf(fmaxf(p * 0.17677669529663687f, -5.0f), 5.0f);
        ex[hh] = expf(s);
    }
    if (lane == 0) {
        *(float4*)&g_sc[(size_t)e2*8 + 0] = make_float4(ex[0], ex[1], ex[2], ex[3]);
        *(float4*)&g_sc[(size_t)e2*8 + 4] = make_float4(ex[4], ex[5], ex[6], ex[7]);
        red_v4(&g_den[dg*8 + 0], ex[0], ex[1], ex[2], ex[3]);
        red_v4(&g_den[dg*8 + 4], ex[4], ex[5], ex[6], ex[7]);
    }
}

// ---------------- alpha * v scatter ----------------
__global__ void k_attn_scatter(const int* __restrict__ es, const int* __restrict__ ed) {
    long gid = (long)blockIdx.x * blockDim.x + threadIdx.x;
    if (gid >= (long)E2 * 64) return;
    int e2 = (int)(gid >> 6);
    int c  = (int)(gid & 63);
    int et = e2 / EP;
    int sg = es[e2] + (et ? NP : 0);
    int dg = ed[e2] + (et ? 0 : NP);
    int hh = c >> 3;
    float alpha = g_sc[(size_t)e2*8 + hh] / g_den[dg*8 + hh];
    const float4 vv = *(const float4*)&g_v[(size_t)sg*HID_ + c*4];
    red_v4(&g_agg[(size_t)dg*HID_ + c*4], vv.x*alpha, vv.y*alpha, vv.z*alpha, vv.w*alpha);
}

// ---------------- host orchestration ----------------
extern "C" void kernel_launch(void* const* d_in, const int* in_sizes, int n_in,
                              void* d_out, int out_size) {
    const float* h      = (const float*)d_in[0];
    const int*   es     = (const int*)  d_in[1];
    const int*   ed     = (const int*)  d_in[2];
    const float* preW   = (const float*)d_in[3];
    const float* preB   = (const float*)d_in[4];
    const float* postW  = (const float*)d_in[5];
    const float* postB  = (const float*)d_in[6];
    const float* qW     = (const float*)d_in[7];
    const float* qB     = (const float*)d_in[8];
    const float* kW     = (const float*)d_in[9];
    const float* kB     = (const float*)d_in[10];
    const float* vW     = (const float*)d_in[11];
    const float* vB     = (const float*)d_in[12];
    const float* oW     = (const float*)d_in[13];
    const float* oB     = (const float*)d_in[14];
    const float* fW1    = (const float*)d_in[15];
    const float* fB1    = (const float*)d_in[16];
    const float* fW2    = (const float*)d_in[17];
    const float* fB2    = (const float*)d_in[18];
    const float* lnPreG = (const float*)d_in[19];
    const float* lnPreB = (const float*)d_in[20];
    const float* lnAtG  = (const float*)d_in[21];
    const float* lnAtB  = (const float*)d_in[22];
    const float* lnPoG  = (const float*)d_in[23];
    const float* lnPoB  = (const float*)d_in[24];
    const float* lnFfG  = (const float*)d_in[25];
    const float* lnFfB  = (const float*)d_in[26];
    float* out = (float*)d_out;

    float *hn, *q, *k, *v, *agg, *cd, *den;
    __nv_bfloat16 *wbhi, *wblo, *ahi, *alo, *fhi, *flo;
    int *degs, *degd;
    cudaGetSymbolAddress((void**)&hn,   g_hn);
    cudaGetSymbolAddress((void**)&q,    g_q);
    cudaGetSymbolAddress((void**)&k,    g_k);
    cudaGetSymbolAddress((void**)&v,    g_v);
    cudaGetSymbolAddress((void**)&agg,  g_agg);
    cudaGetSymbolAddress((void**)&cd,   g_cd);
    cudaGetSymbolAddress((void**)&den,  g_den);
    cudaGetSymbolAddress((void**)&degs, g_degs);
    cudaGetSymbolAddress((void**)&degd, g_degd);
    cudaGetSymbolAddress((void**)&wbhi, g_wbhi);
    cudaGetSymbolAddress((void**)&wblo, g_wblo);
    cudaGetSymbolAddress((void**)&ahi,  g_ahi);
    cudaGetSymbolAddress((void**)&alo,  g_alo);
    cudaGetSymbolAddress((void**)&fhi,  g_fhi);
    cudaGetSymbolAddress((void**)&flo,  g_flo);

    cudaFuncSetAttribute(gemm_mma, cudaFuncAttributeMaxDynamicSharedMemorySize, GSMEM);

    const dim3 lnGrid(NP, T_);
    const dim3 g256(2, 196, 2);
    const dim3 g512(4, 196, 2);
    const int SC_BLOCKS = (long)E2 * 64 / 256;
    const int SPLIT_BLOCKS = (NTOT * HID_ / 4 + 255) / 256;

    // weight split
    k_wconv<<<dim3(256,1,2), 256>>>(preW,  wbhi+WOFF_PRE,  wblo+WOFF_PRE,  256, 256);
    k_wconv<<<dim3(256,1,2), 256>>>(postW, wbhi+WOFF_POST, wblo+WOFF_POST, 256, 256);
    k_wconv<<<dim3(256,1,2), 256>>>(qW,    wbhi+WOFF_Q,    wblo+WOFF_Q,    256, 256);
    k_wconv<<<dim3(256,1,2), 256>>>(kW,    wbhi+WOFF_K,    wblo+WOFF_K,    256, 256);
    k_wconv<<<dim3(256,1,2), 256>>>(vW,    wbhi+WOFF_V,    wblo+WOFF_V,    256, 256);
    k_wconv<<<dim3(256,1,2), 256>>>(oW,    wbhi+WOFF_O,    wblo+WOFF_O,    256, 256);
    k_wconv<<<dim3(512,1,2), 256>>>(fW1,   wbhi+WOFF_F1,   wblo+WOFF_F1,   256, 512);
    k_wconv<<<dim3(512,1,2), 256>>>(fW2,   wbhi+WOFF_F2,   wblo+WOFF_F2,   512, 256);

    // degrees
    cudaMemsetAsync(degs, 0, sizeof(int) * T_ * NP);
    cudaMemsetAsync(degd, 0, sizeof(int) * T_ * NP);
    k_deg<<<(E2 + 255)/256, 256>>>(es, ed);
    k_degnorm<<<(NP + 255)/256, 256>>>();

    // ---- conv1 ----
    k_ln<<<lnGrid, 256>>>(h, lnPreG, lnPreB, hn);
    cudaMemsetAsync(agg, 0, sizeof(float) * (size_t)NTOT * HID_);
    k_conv_scatter<<<SC_BLOCKS, 256>>>(hn, es, ed);
    k_split<<<SPLIT_BLOCKS, 256>>>(agg);
    gemm_mma<<<g256, 256, GSMEM>>>(ahi, alo, wbhi+WOFF_PRE, wblo+WOFF_PRE, preB, cd, h, out,
                                   nullptr, nullptr, NP, HID_, HID_, 1, 0);

    // ---- attention ----
    k_ln_split<<<lnGrid, 256>>>(out, lnAtG, lnAtB);
    gemm_mma<<<g256, 256, GSMEM>>>(ahi, alo, wbhi+WOFF_Q, wblo+WOFF_Q, qB, nullptr, nullptr, q,
                                   nullptr, nullptr, NP, HID_, HID_, 0, 0);
    gemm_mma<<<g256, 256, GSMEM>>>(ahi, alo, wbhi+WOFF_K, wblo+WOFF_K, kB, nullptr, nullptr, k,
                                   nullptr, nullptr, NP, HID_, HID_, 0, 0);
    gemm_mma<<<g256, 256, GSMEM>>>(ahi, alo, wbhi+WOFF_V, wblo+WOFF_V, vB, nullptr, nullptr, v,
                                   nullptr, nullptr, NP, HID_, HID_, 0, 0);
    cudaMemsetAsync(den, 0, sizeof(float) * NTOT * 8);
    k_score<<<(E2 + 7)/8, 256>>>(q, k, es, ed);
    cudaMemsetAsync(agg, 0, sizeof(float) * (size_t)NTOT * HID_);
    k_attn_scatter<<<SC_BLOCKS, 256>>>(es, ed);
    k_split<<<SPLIT_BLOCKS, 256>>>(agg);
    gemm_mma<<<g256, 256, GSMEM>>>(ahi, alo, wbhi+WOFF_O, wblo+WOFF_O, oB, nullptr, out, out,
                                   nullptr, nullptr, NP, HID_, HID_, 0, 0);

    // ---- conv2 ----
    k_ln<<<lnGrid, 256>>>(out, lnPoG, lnPoB, hn);
    cudaMemsetAsync(agg, 0, sizeof(float) * (size_t)NTOT * HID_);
    k_conv_scatter<<<SC_BLOCKS, 256>>>(hn, es, ed);
    k_split<<<SPLIT_BLOCKS, 256>>>(agg);
    gemm_mma<<<g256, 256, GSMEM>>>(ahi, alo, wbhi+WOFF_POST, wblo+WOFF_POST, postB, cd, out, out,
                                   nullptr, nullptr, NP, HID_, HID_, 1, 0);

    // ---- FFN ----
    k_ln_split<<<lnGrid, 256>>>(out, lnFfG, lnFfB);
    gemm_mma<<<g512, 256, GSMEM>>>(ahi, alo, wbhi+WOFF_F1, wblo+WOFF_F1, fB1, nullptr, nullptr,
                                   nullptr, fhi, flo, NP, HID_, 512, 0, 1);
    gemm_mma<<<g256, 256, GSMEM>>>(fhi, flo, wbhi+WOFF_F2, wblo+WOFF_F2, fB2, nullptr, out, out,
                                   nullptr, nullptr, NP, 512, HID_, 0, 0);
}

// round 7
// speedup vs baseline: 2.5205x; 1.1794x over previous
#include <cuda_runtime.h>
#include <cuda_bf16.h>
#include <math.h>

#define T_   2
#define NP   25000
#define EP   200000
#define HID_ 256
#define NTOT (T_*NP)
#define E2   (2*EP)

// ---------------- scratch (static __device__ — no allocations) ----------------
__device__ float g_hn [(size_t)T_*NP*HID_];       // fp32 LN out (conv paths)
__device__ float g_q  [(size_t)NTOT*HID_];
__device__ float g_k  [(size_t)NTOT*HID_];
__device__ float g_v  [(size_t)NTOT*HID_];
__device__ float g_sc [(size_t)E2*8];             // ex values (CSR order)
__device__ float g_cs [T_*NP];
__device__ float g_cd [T_*NP];
__device__ int   g_degs[T_*NP];
__device__ int   g_degd[T_*NP];
// CSR by global dst node
__device__ int   g_off [NTOT + 1];
__device__ int   g_fill[NTOT];
__device__ int   g_csr [E2];
// split A operands (bf16 hi/lo)
__device__ __nv_bfloat16 g_ahi[(size_t)NTOT*HID_];
__device__ __nv_bfloat16 g_alo[(size_t)NTOT*HID_];
__device__ __nv_bfloat16 g_fhi[(size_t)NTOT*512];
__device__ __nv_bfloat16 g_flo[(size_t)NTOT*512];
// split weights, bf16, layout [matrix][t][N][K]
#define WCVT_TOTAL 1310720
__device__ __nv_bfloat16 g_wbhi[WCVT_TOTAL];
__device__ __nv_bfloat16 g_wblo[WCVT_TOTAL];
#define WOFF_PRE  0
#define WOFF_POST 131072
#define WOFF_Q    262144
#define WOFF_K    393216
#define WOFF_V    524288
#define WOFF_O    655360
#define WOFF_F1   786432
#define WOFF_F2   1048576

// ---------------- mma / async helpers ----------------
__device__ __forceinline__ unsigned smem_u32(const void* p) {
    unsigned a;
    asm("{ .reg .u64 t; cvta.to.shared.u64 t, %1; cvt.u32.u64 %0, t; }" : "=r"(a) : "l"(p));
    return a;
}
#define LDM4(r, a) \
    asm volatile("ldmatrix.sync.aligned.m8n8.x4.shared.b16 {%0,%1,%2,%3}, [%4];" \
        : "=r"((r)[0]),"=r"((r)[1]),"=r"((r)[2]),"=r"((r)[3]) : "r"(a))
#define MMA_BF16(c, a, b0, b1) \
    asm volatile("mma.sync.aligned.m16n8k16.row.col.f32.bf16.bf16.f32 " \
        "{%0,%1,%2,%3}, {%4,%5,%6,%7}, {%8,%9}, {%0,%1,%2,%3};" \
        : "+f"((c)[0]),"+f"((c)[1]),"+f"((c)[2]),"+f"((c)[3]) \
        : "r"((a)[0]),"r"((a)[1]),"r"((a)[2]),"r"((a)[3]), "r"(b0),"r"(b1))
#define CP16(dst, src) \
    asm volatile("cp.async.cg.shared.global [%0], [%1], 16;" :: "r"(dst), "l"(src) : "memory")
#define CP_COMMIT() asm volatile("cp.async.commit_group;" ::: "memory")
#define CP_WAIT0()  asm volatile("cp.async.wait_group 0;" ::: "memory")

__device__ __forceinline__ unsigned pack_bf2(__nv_bfloat16 a, __nv_bfloat16 b) {
    __nv_bfloat162 t = __halves2bfloat162(a, b);
    return *(unsigned*)&t;
}
// write a float4 as split bf16 hi/lo
__device__ __forceinline__ void store_split4(size_t idx, float4 v) {
    __nv_bfloat16 h0 = __float2bfloat16_rn(v.x), h1 = __float2bfloat16_rn(v.y);
    __nv_bfloat16 h2 = __float2bfloat16_rn(v.z), h3 = __float2bfloat16_rn(v.w);
    uint2 hh, ll;
    hh.x = pack_bf2(h0, h1); hh.y = pack_bf2(h2, h3);
    ll.x = pack_bf2(__float2bfloat16_rn(v.x - __bfloat162float(h0)),
                    __float2bfloat16_rn(v.y - __bfloat162float(h1)));
    ll.y = pack_bf2(__float2bfloat16_rn(v.z - __bfloat162float(h2)),
                    __float2bfloat16_rn(v.w - __bfloat162float(h3)));
    *(uint2*)&g_ahi[idx] = hh;
    *(uint2*)&g_alo[idx] = ll;
}

// ---------------- helpers ----------------
__device__ __forceinline__ float block_sum(float v, float* sh) {
    #pragma unroll
    for (int o = 16; o; o >>= 1) v += __shfl_xor_sync(0xffffffffu, v, o);
    if ((threadIdx.x & 31) == 0) sh[threadIdx.x >> 5] = v;
    __syncthreads();
    float s = 0.f;
    #pragma unroll
    for (int i = 0; i < 8; i++) s += sh[i];
    __syncthreads();
    return s;
}

// ---------------- degree + CSR build ----------------
__global__ void k_deg(const int* __restrict__ es, const int* __restrict__ ed) {
    int gid = blockIdx.x * blockDim.x + threadIdx.x;
    if (gid >= E2) return;
    int et = gid / EP;
    atomicAdd(&g_degs[et*NP + es[gid]], 1);
    atomicAdd(&g_degd[et*NP + ed[gid]], 1);
}

__global__ void k_degnorm() {
    int n = blockIdx.x * blockDim.x + threadIdx.x;
    if (n >= NP) return;
    #pragma unroll
    for (int et = 0; et < 2; et++) {
        g_cs[et*NP + n]       = rsqrtf((float)max(g_degs[et*NP + n], 1));
        g_cd[(1-et)*NP + n]   = rsqrtf((float)max(g_degd[et*NP + n], 1));
    }
}

// single-block exclusive scan of in-degrees -> g_off
__global__ void k_scan() {
    __shared__ int wsum[32];
    __shared__ int sbase;
    int tid = threadIdx.x, lane = tid & 31, wid = tid >> 5;
    if (tid == 0) sbase = 0;
    __syncthreads();
    for (int start = 0; start < NTOT; start += 1024) {
        int g = start + tid;
        int deg = 0;
        if (g < NTOT) {
            int dt = g / NP, n = g - dt * NP;
            deg = g_degd[(1 - dt) * NP + n];
        }
        int x = deg;
        #pragma unroll
        for (int o = 1; o < 32; o <<= 1) { int y = __shfl_up_sync(~0u, x, o); if (lane >= o) x += y; }
        if (lane == 31) wsum[wid] = x;
        __syncthreads();
        if (wid == 0) {
            int w = wsum[lane];
            #pragma unroll
            for (int o = 1; o < 32; o <<= 1) { int y = __shfl_up_sync(~0u, w, o); if (lane >= o) w += y; }
            wsum[lane] = w;
        }
        __syncthreads();
        int warpBase = (wid == 0) ? 0 : wsum[wid - 1];
        if (g < NTOT) g_off[g] = sbase + warpBase + (x - deg);
        int total = wsum[31];
        __syncthreads();
        if (tid == 0) sbase += total;
        __syncthreads();
    }
    if (tid == 0) g_off[NTOT] = sbase;
}

__global__ void k_fill(const int* __restrict__ ed) {
    int gid = blockIdx.x * blockDim.x + threadIdx.x;
    if (gid >= E2) return;
    int et = gid / EP;
    int gnode = (1 - et) * NP + ed[gid];
    int pos = g_off[gnode] + atomicAdd(&g_fill[gnode], 1);
    g_csr[pos] = gid;
}

// ---------------- layernorm (fp32 out, conv paths) ----------------
__global__ void k_ln(const float* __restrict__ x, const float* __restrict__ g,
                     const float* __restrict__ b, float* __restrict__ y) {
    __shared__ float sh[8];
    int n = blockIdx.x, t = blockIdx.y, c = threadIdx.x;
    size_t base = ((size_t)t*NP + n) * HID_;
    float v = x[base + c];
    float mu = block_sum(v, sh) * (1.0f / HID_);
    float d = v - mu;
    float var = block_sum(d * d, sh) * (1.0f / HID_);
    y[base + c] = d * rsqrtf(var + 1e-5f) * g[t*HID_ + c] + b[t*HID_ + c];
}

// ---------------- layernorm with split bf16 output (GEMM-A paths) ----------------
__global__ void k_ln_split(const float* __restrict__ x, const float* __restrict__ g,
                           const float* __restrict__ b) {
    __shared__ float sh[8];
    int n = blockIdx.x, t = blockIdx.y, c = threadIdx.x;
    size_t base = ((size_t)t*NP + n) * HID_;
    float v = x[base + c];
    float mu = block_sum(v, sh) * (1.0f / HID_);
    float d = v - mu;
    float var = block_sum(d * d, sh) * (1.0f / HID_);
    float y = d * rsqrtf(var + 1e-5f) * g[t*HID_ + c] + b[t*HID_ + c];
    __nv_bfloat16 hi = __float2bfloat16_rn(y);
    g_ahi[base + c] = hi;
    g_alo[base + c] = __float2bfloat16_rn(y - __bfloat162float(hi));
}

// ---------------- conv aggregation: CSR gather, split bf16 out ----------------
__global__ void __launch_bounds__(64) k_conv_gather(const float* __restrict__ hn,
                                                    const int* __restrict__ es) {
    int gnode = blockIdx.x;
    int tid = threadIdx.x;
    int off = g_off[gnode], end = g_off[gnode + 1];
    int dt = gnode / NP;
    int et = 1 - dt;
    float4 acc = make_float4(0.f, 0.f, 0.f, 0.f);
    for (int i = off; i < end; i++) {
        int eid = g_csr[i];
        int src = es[eid];
        float w = g_cs[et*NP + src];
        const float4 hv = *(const float4*)&hn[((size_t)et*NP + src)*HID_ + tid*4];
        acc.x += hv.x*w; acc.y += hv.y*w; acc.z += hv.z*w; acc.w += hv.w*w;
    }
    store_split4((size_t)gnode*HID_ + tid*4, acc);
}

// ---------------- fused attention: score+exp+den+gather, split bf16 out ----------------
__global__ void __launch_bounds__(64) k_attn(const float* __restrict__ q,
                                             const float* __restrict__ k,
                                             const float* __restrict__ v,
                                             const int* __restrict__ es) {
    __shared__ float sq[HID_];
    __shared__ float sden[2][8];
    int gnode = blockIdx.x, tid = threadIdx.x, lane = tid & 31, wid = tid >> 5;
    int off = g_off[gnode], deg = g_off[gnode + 1] - off;

    *(float4*)&sq[tid*4] = *(const float4*)&q[(size_t)gnode*HID_ + tid*4];
    __syncthreads();

    // pass 1: warp per edge — scores, exp, local denominator
    float denAcc = 0.f;
    for (int i = wid; i < deg; i += 2) {
        int eid = g_csr[off + i];
        int et = eid / EP;
        int sg = es[eid] + (et ? NP : 0);
        const float* kv = &k[(size_t)sg * HID_];
        float myex = 0.f;
        #pragma unroll
        for (int hh = 0; hh < 8; hh++) {
            float p = sq[hh*32 + lane] * kv[hh*32 + lane];
            #pragma unroll
            for (int o = 16; o; o >>= 1) p += __shfl_xor_sync(~0u, p, o);
            float s = fminf(fmaxf(p * 0.17677669529663687f, -5.0f), 5.0f);
            float ex = expf(s);   // s in [-5,5]: no overflow; max-shift cancels exactly
            if (lane == hh) myex = ex;
        }
        if (lane < 8) {
            g_sc[(size_t)(off + i)*8 + lane] = myex;
            denAcc += myex;
        }
    }
    if (lane < 8) sden[wid][lane] = denAcc;
    __syncthreads();

    // pass 2: gather alpha * v
    int hh = tid >> 3;
    float den = sden[0][hh] + sden[1][hh];
    float rden = (den > 0.f) ? 1.0f / den : 0.f;
    float4 acc = make_float4(0.f, 0.f, 0.f, 0.f);
    for (int i = 0; i < deg; i++) {
        int eid = g_csr[off + i];
        int et = eid / EP;
        int sg = es[eid] + (et ? NP : 0);
        float alpha = g_sc[(size_t)(off + i)*8 + hh] * rden;
        const float4 vv = *(const float4*)&v[(size_t)sg*HID_ + tid*4];
        acc.x += vv.x*alpha; acc.y += vv.y*alpha; acc.z += vv.z*alpha; acc.w += vv.w*alpha;
    }
    store_split4((size_t)gnode*HID_ + tid*4, acc);
}

// ---------------- all-weights split (one launch) ----------------
__global__ void k_wconv_all(const float* __restrict__ preW, const float* __restrict__ postW,
                            const float* __restrict__ qW, const float* __restrict__ kW,
                            const float* __restrict__ vW, const float* __restrict__ oW,
                            const float* __restrict__ f1W, const float* __restrict__ f2W) {
    int gid = blockIdx.x * 256 + threadIdx.x;
    if (gid >= WCVT_TOTAL) return;
    const float* W; int K, N, loc;
    if (gid < 786432) {
        int seg = gid >> 17;
        loc = gid & 131071;
        const float* tbl[6] = {preW, postW, qW, kW, vW, oW};
        W = tbl[seg]; K = 256; N = 256;
    } else if (gid < 1048576) {
        loc = gid - 786432; W = f1W; K = 256; N = 512;
    } else {
        loc = gid - 1048576; W = f2W; K = 512; N = 256;
    }
    int sz = K * N;
    int t = loc / sz, o = loc - t * sz;
    int n = o / K, kk = o - n * K;
    float x = W[(size_t)t*sz + (size_t)kk*N + n];
    __nv_bfloat16 h = __float2bfloat16_rn(x);
    g_wbhi[gid] = h;
    g_wblo[gid] = __float2bfloat16_rn(x - __bfloat162float(h));
}

// ---------------- bf16-split tensor GEMM, all-cp.async double-buffered ----------------
#define PAD 40
#define ST_A   (128*PAD)
#define ST_ALL (4*128*PAD)
#define GSMEM  (2*ST_ALL*2)

__global__ void __launch_bounds__(256, 2) gemm_mma(
    const __nv_bfloat16* __restrict__ Ahi_g, const __nv_bfloat16* __restrict__ Alo_g,
    const __nv_bfloat16* __restrict__ Bhi_g, const __nv_bfloat16* __restrict__ Blo_g,
    const float* __restrict__ bias, const float* __restrict__ rowscale,
    const float* __restrict__ resid, float* __restrict__ C,
    __nv_bfloat16* __restrict__ Chi, __nv_bfloat16* __restrict__ Clo,
    int M, int K, int N, int wswap, int dogelu)
{
    extern __shared__ __nv_bfloat16 smem[];

    int tid = threadIdx.x;
    int warp = tid >> 5, lane = tid & 31;
    int wm = warp & 3, wn = warp >> 2;
    int t = blockIdx.z;
    int wi = wswap ? (1 - t) : t;

    Ahi_g += (size_t)t  * M * K;
    Alo_g += (size_t)t  * M * K;
    Bhi_g += (size_t)wi * K * N;
    Blo_g += (size_t)wi * K * N;
    bias  += (size_t)wi * N;
    const float* rs = rowscale ? rowscale + (size_t)t * M : nullptr;
    const float* rd = resid ? resid + (size_t)t * M * N : nullptr;
    C   += (size_t)t * M * N;
    if (Chi) { Chi += (size_t)t * M * N; Clo += (size_t)t * M * N; }

    int m0 = blockIdx.y * 128, n0 = blockIdx.x * 128;

    float acc[2][8][4];
    #pragma unroll
    for (int i = 0; i < 2; i++)
        #pragma unroll
        for (int j = 0; j < 8; j++)
            #pragma unroll
            for (int l = 0; l < 4; l++) acc[i][j][l] = 0.f;

    int lrow = lane & 7, lsel = lane >> 3;
    int a_r = (lsel & 1) * 8 + lrow;
    int a_c = (lsel >> 1) * 8;
    int b_r = (lsel >> 1) * 8 + lrow;
    int b_c = (lsel & 1) * 8;

    unsigned usm = smem_u32(smem);
    int grow = tid >> 2, gseg = tid & 3;
    int nchunks = K >> 5;

    {
        unsigned base = usm;
        #pragma unroll
        for (int i = 0; i < 2; i++) {
            int row = grow + i * 64;
            unsigned loc = 2u * (unsigned)(row * PAD + gseg * 8);
            size_t goa = (size_t)(m0 + row) * K + (gseg << 3);
            size_t gob = (size_t)(n0 + row) * K + (gseg << 3);
            CP16(base + loc,               &Ahi_g[goa]);
            CP16(base + 2u*ST_A + loc,     &Alo_g[goa]);
            CP16(base + 2u*2*ST_A + loc,   &Bhi_g[gob]);
            CP16(base + 2u*3*ST_A + loc,   &Blo_g[gob]);
        }
        CP_COMMIT();
    }

    for (int c = 0; c < nchunks; c++) {
        int s = c & 1;
        unsigned base = usm + 2u * (unsigned)(s * ST_ALL);
        unsigned uah = base, ual = base + 2u*ST_A, ubh = base + 2u*2*ST_A, ubl = base + 2u*3*ST_A;

        CP_WAIT0();
        __syncthreads();

        if (c + 1 < nchunks) {
            int koff = (c + 1) << 5;
            unsigned nb = usm + 2u * (unsigned)((1 - s) * ST_ALL);
            #pragma unroll
            for (int i = 0; i < 2; i++) {
                int row = grow + i * 64;
                unsigned loc = 2u * (unsigned)(row * PAD + gseg * 8);
                size_t goa = (size_t)(m0 + row) * K + koff + (gseg << 3);
                size_t gob = (size_t)(n0 + row) * K + koff + (gseg << 3);
                CP16(nb + loc,             &Ahi_g[goa]);
                CP16(nb + 2u*ST_A + loc,   &Alo_g[goa]);
                CP16(nb + 2u*2*ST_A + loc, &Bhi_g[gob]);
                CP16(nb + 2u*3*ST_A + loc, &Blo_g[gob]);
            }
            CP_COMMIT();
        }

        #pragma unroll
        for (int ks = 0; ks < 2; ks++) {
            int kk = ks * 16;
            unsigned ah[2][4], al[2][4];
            #pragma unroll
            for (int mt = 0; mt < 2; mt++) {
                unsigned off = 2u * (unsigned)((wm*32 + mt*16 + a_r) * PAD + kk + a_c);
                LDM4(ah[mt], uah + off);
                LDM4(al[mt], ual + off);
            }
            #pragma unroll
            for (int bi = 0; bi < 4; bi++) {
                unsigned off = 2u * (unsigned)((wn*64 + bi*16 + b_r) * PAD + kk + b_c);
                unsigned bh[4], bl[4];
                LDM4(bh, ubh + off);
                LDM4(bl, ubl + off);
                #pragma unroll
                for (int mt = 0; mt < 2; mt++) {
                    #pragma unroll
                    for (int j = 0; j < 2; j++) {
                        float* cc = acc[mt][bi*2 + j];
                        MMA_BF16(cc, ah[mt], bh[j*2], bh[j*2+1]);
                        MMA_BF16(cc, ah[mt], bl[j*2], bl[j*2+1]);
                        MMA_BF16(cc, al[mt], bh[j*2], bh[j*2+1]);
                    }
                }
            }
        }
        __syncthreads();
    }

    int g = lane >> 2, tig = lane & 3;
    #pragma unroll
    for (int mt = 0; mt < 2; mt++) {
        #pragma unroll
        for (int nt = 0; nt < 8; nt++) {
            int col = n0 + wn*64 + nt*8 + tig*2;
            float b0 = bias[col], b1 = bias[col+1];
            #pragma unroll
            for (int half = 0; half < 2; half++) {
                int r = m0 + wm*32 + mt*16 + g + half*8;
                if (r >= M) continue;
                float scale = rs ? rs[r] : 1.0f;
                size_t idx = (size_t)r * N + col;
                float2 o;
                o.x = acc[mt][nt][half*2+0] * scale + b0;
                o.y = acc[mt][nt][half*2+1] * scale + b1;
                if (rd) {
                    const float2 rv = *(const float2*)&rd[idx];
                    o.x += rv.x; o.y += rv.y;
                }
                if (dogelu) {
                    o.x = 0.5f*o.x*(1.0f+erff(o.x*0.70710678118654752f));
                    o.y = 0.5f*o.y*(1.0f+erff(o.y*0.70710678118654752f));
                }
                if (Chi) {
                    __nv_bfloat16 h0 = __float2bfloat16_rn(o.x);
                    __nv_bfloat16 h1 = __float2bfloat16_rn(o.y);
                    *(unsigned*)&Chi[idx] = pack_bf2(h0, h1);
                    *(unsigned*)&Clo[idx] = pack_bf2(
                        __float2bfloat16_rn(o.x - __bfloat162float(h0)),
                        __float2bfloat16_rn(o.y - __bfloat162float(h1)));
                } else {
                    *(float2*)&C[idx] = o;
                }
            }
        }
    }
}

// ---------------- host orchestration ----------------
extern "C" void kernel_launch(void* const* d_in, const int* in_sizes, int n_in,
                              void* d_out, int out_size) {
    const float* h      = (const float*)d_in[0];
    const int*   es     = (const int*)  d_in[1];
    const int*   ed     = (const int*)  d_in[2];
    const float* preW   = (const float*)d_in[3];
    const float* preB   = (const float*)d_in[4];
    const float* postW  = (const float*)d_in[5];
    const float* postB  = (const float*)d_in[6];
    const float* qW     = (const float*)d_in[7];
    const float* qB     = (const float*)d_in[8];
    const float* kW     = (const float*)d_in[9];
    const float* kB     = (const float*)d_in[10];
    const float* vW     = (const float*)d_in[11];
    const float* vB     = (const float*)d_in[12];
    const float* oW     = (const float*)d_in[13];
    const float* oB     = (const float*)d_in[14];
    const float* fW1    = (const float*)d_in[15];
    const float* fB1    = (const float*)d_in[16];
    const float* fW2    = (const float*)d_in[17];
    const float* fB2    = (const float*)d_in[18];
    const float* lnPreG = (const float*)d_in[19];
    const float* lnPreB = (const float*)d_in[20];
    const float* lnAtG  = (const float*)d_in[21];
    const float* lnAtB  = (const float*)d_in[22];
    const float* lnPoG  = (const float*)d_in[23];
    const float* lnPoB  = (const float*)d_in[24];
    const float* lnFfG  = (const float*)d_in[25];
    const float* lnFfB  = (const float*)d_in[26];
    float* out = (float*)d_out;

    float *hn, *q, *k, *v, *cd;
    __nv_bfloat16 *wbhi, *wblo, *ahi, *alo, *fhi, *flo;
    int *degs, *degd, *fill;
    cudaGetSymbolAddress((void**)&hn,   g_hn);
    cudaGetSymbolAddress((void**)&q,    g_q);
    cudaGetSymbolAddress((void**)&k,    g_k);
    cudaGetSymbolAddress((void**)&v,    g_v);
    cudaGetSymbolAddress((void**)&cd,   g_cd);
    cudaGetSymbolAddress((void**)&degs, g_degs);
    cudaGetSymbolAddress((void**)&degd, g_degd);
    cudaGetSymbolAddress((void**)&fill, g_fill);
    cudaGetSymbolAddress((void**)&wbhi, g_wbhi);
    cudaGetSymbolAddress((void**)&wblo, g_wblo);
    cudaGetSymbolAddress((void**)&ahi,  g_ahi);
    cudaGetSymbolAddress((void**)&alo,  g_alo);
    cudaGetSymbolAddress((void**)&fhi,  g_fhi);
    cudaGetSymbolAddress((void**)&flo,  g_flo);

    cudaFuncSetAttribute(gemm_mma, cudaFuncAttributeMaxDynamicSharedMemorySize, GSMEM);

    const dim3 lnGrid(NP, T_);
    const dim3 g256(2, 196, 2);
    const dim3 g512(4, 196, 2);

    // weights (one launch) + degrees + CSR
    k_wconv_all<<<WCVT_TOTAL/256, 256>>>(preW, postW, qW, kW, vW, oW, fW1, fW2);
    cudaMemsetAsync(degs, 0, sizeof(int) * T_ * NP);
    cudaMemsetAsync(degd, 0, sizeof(int) * T_ * NP);
    cudaMemsetAsync(fill, 0, sizeof(int) * NTOT);
    k_deg<<<(E2 + 255)/256, 256>>>(es, ed);
    k_degnorm<<<(NP + 255)/256, 256>>>();
    k_scan<<<1, 1024>>>();
    k_fill<<<(E2 + 255)/256, 256>>>(ed);

    // ---- conv1 ----
    k_ln<<<lnGrid, 256>>>(h, lnPreG, lnPreB, hn);
    k_conv_gather<<<NTOT, 64>>>(hn, es);
    gemm_mma<<<g256, 256, GSMEM>>>(ahi, alo, wbhi+WOFF_PRE, wblo+WOFF_PRE, preB, cd, h, out,
                                   nullptr, nullptr, NP, HID_, HID_, 1, 0);

    // ---- attention ----
    k_ln_split<<<lnGrid, 256>>>(out, lnAtG, lnAtB);
    gemm_mma<<<g256, 256, GSMEM>>>(ahi, alo, wbhi+WOFF_Q, wblo+WOFF_Q, qB, nullptr, nullptr, q,
                                   nullptr, nullptr, NP, HID_, HID_, 0, 0);
    gemm_mma<<<g256, 256, GSMEM>>>(ahi, alo, wbhi+WOFF_K, wblo+WOFF_K, kB, nullptr, nullptr, k,
                                   nullptr, nullptr, NP, HID_, HID_, 0, 0);
    gemm_mma<<<g256, 256, GSMEM>>>(ahi, alo, wbhi+WOFF_V, wblo+WOFF_V, vB, nullptr, nullptr, v,
                                   nullptr, nullptr, NP, HID_, HID_, 0, 0);
    k_attn<<<NTOT, 64>>>(q, k, v, es);
    gemm_mma<<<g256, 256, GSMEM>>>(ahi, alo, wbhi+WOFF_O, wblo+WOFF_O, oB, nullptr, out, out,
                                   nullptr, nullptr, NP, HID_, HID_, 0, 0);

    // ---- conv2 ----
    k_ln<<<lnGrid, 256>>>(out, lnPoG, lnPoB, hn);
    k_conv_gather<<<NTOT, 64>>>(hn, es);
    gemm_mma<<<g256, 256, GSMEM>>>(ahi, alo, wbhi+WOFF_POST, wblo+WOFF_POST, postB, cd, out, out,
                                   nullptr, nullptr, NP, HID_, HID_, 1, 0);

    // ---- FFN ----
    k_ln_split<<<lnGrid, 256>>>(out, lnFfG, lnFfB);
    gemm_mma<<<g512, 256, GSMEM>>>(ahi, alo, wbhi+WOFF_F1, wblo+WOFF_F1, fB1, nullptr, nullptr,
                                   nullptr, fhi, flo, NP, HID_, 512, 0, 1);
    gemm_mma<<<g256, 256, GSMEM>>>(fhi, flo, wbhi+WOFF_F2, wblo+WOFF_F2, fB2, nullptr, out, out,
                                   nullptr, nullptr, NP, 512, HID_, 0, 0);
}

// round 8
// speedup vs baseline: 2.6543x; 1.0531x over previous
#include <cuda_runtime.h>
#include <cuda_bf16.h>
#include <math.h>

#define T_   2
#define NP   25000
#define EP   200000
#define HID_ 256
#define NTOT (T_*NP)
#define E2   (2*EP)

// ---------------- scratch (static __device__ — no allocations) ----------------
__device__ float g_hn [(size_t)T_*NP*HID_];       // fp32 LN out (conv paths)
__device__ float g_qkv[(size_t)NTOT*768];         // interleaved q|k|v per node
__device__ float g_sc [(size_t)E2*8];             // ex values (CSR order)
__device__ float g_cs [T_*NP];
__device__ float g_cd [T_*NP];
__device__ float g_qkvb[T_*768];
__device__ int   g_degs[T_*NP];
__device__ int   g_degd[T_*NP];
__device__ int   g_bsum[256];
// CSR by global dst node
__device__ int   g_off [NTOT + 1];
__device__ int   g_fill[NTOT];
__device__ int   g_csr [E2];
// split A operands (bf16 hi/lo)
__device__ __nv_bfloat16 g_ahi[(size_t)NTOT*HID_];
__device__ __nv_bfloat16 g_alo[(size_t)NTOT*HID_];
__device__ __nv_bfloat16 g_fhi[(size_t)NTOT*512];
__device__ __nv_bfloat16 g_flo[(size_t)NTOT*512];
// split weights, bf16, layout [matrix][t][N][K]
#define WCVT_TOTAL 1310720
__device__ __nv_bfloat16 g_wbhi[WCVT_TOTAL];
__device__ __nv_bfloat16 g_wblo[WCVT_TOTAL];
#define WOFF_PRE  0
#define WOFF_POST 131072
#define WOFF_QKV  262144
#define WOFF_O    655360
#define WOFF_F1   786432
#define WOFF_F2   1048576

// ---------------- mma / async helpers ----------------
__device__ __forceinline__ unsigned smem_u32(const void* p) {
    unsigned a;
    asm("{ .reg .u64 t; cvta.to.shared.u64 t, %1; cvt.u32.u64 %0, t; }" : "=r"(a) : "l"(p));
    return a;
}
#define LDM4(r, a) \
    asm volatile("ldmatrix.sync.aligned.m8n8.x4.shared.b16 {%0,%1,%2,%3}, [%4];" \
        : "=r"((r)[0]),"=r"((r)[1]),"=r"((r)[2]),"=r"((r)[3]) : "r"(a))
#define MMA_BF16(c, a, b0, b1) \
    asm volatile("mma.sync.aligned.m16n8k16.row.col.f32.bf16.bf16.f32 " \
        "{%0,%1,%2,%3}, {%4,%5,%6,%7}, {%8,%9}, {%0,%1,%2,%3};" \
        : "+f"((c)[0]),"+f"((c)[1]),"+f"((c)[2]),"+f"((c)[3]) \
        : "r"((a)[0]),"r"((a)[1]),"r"((a)[2]),"r"((a)[3]), "r"(b0),"r"(b1))
#define CP16(dst, src) \
    asm volatile("cp.async.cg.shared.global [%0], [%1], 16;" :: "r"(dst), "l"(src) : "memory")
#define CP_COMMIT() asm volatile("cp.async.commit_group;" ::: "memory")
#define CP_WAIT0()  asm volatile("cp.async.wait_group 0;" ::: "memory")

__device__ __forceinline__ unsigned pack_bf2(__nv_bfloat16 a, __nv_bfloat16 b) {
    __nv_bfloat162 t = __halves2bfloat162(a, b);
    return *(unsigned*)&t;
}
__device__ __forceinline__ void store_split4(size_t idx, float4 v) {
    __nv_bfloat16 h0 = __float2bfloat16_rn(v.x), h1 = __float2bfloat16_rn(v.y);
    __nv_bfloat16 h2 = __float2bfloat16_rn(v.z), h3 = __float2bfloat16_rn(v.w);
    uint2 hh, ll;
    hh.x = pack_bf2(h0, h1); hh.y = pack_bf2(h2, h3);
    ll.x = pack_bf2(__float2bfloat16_rn(v.x - __bfloat162float(h0)),
                    __float2bfloat16_rn(v.y - __bfloat162float(h1)));
    ll.y = pack_bf2(__float2bfloat16_rn(v.z - __bfloat162float(h2)),
                    __float2bfloat16_rn(v.w - __bfloat162float(h3)));
    *(uint2*)&g_ahi[idx] = hh;
    *(uint2*)&g_alo[idx] = ll;
}

// ---------------- helpers ----------------
__device__ __forceinline__ float block_sum(float v, float* sh) {
    #pragma unroll
    for (int o = 16; o; o >>= 1) v += __shfl_xor_sync(0xffffffffu, v, o);
    if ((threadIdx.x & 31) == 0) sh[threadIdx.x >> 5] = v;
    __syncthreads();
    float s = 0.f;
    #pragma unroll
    for (int i = 0; i < 8; i++) s += sh[i];
    __syncthreads();
    return s;
}

// ---------------- degree + CSR build ----------------
__global__ void k_deg(const int* __restrict__ es, const int* __restrict__ ed) {
    int gid = blockIdx.x * blockDim.x + threadIdx.x;
    if (gid >= E2) return;
    int et = gid / EP;
    atomicAdd(&g_degs[et*NP + es[gid]], 1);
    atomicAdd(&g_degd[et*NP + ed[gid]], 1);
}

__global__ void k_degnorm() {
    int n = blockIdx.x * blockDim.x + threadIdx.x;
    if (n >= NP) return;
    #pragma unroll
    for (int et = 0; et < 2; et++) {
        g_cs[et*NP + n]       = rsqrtf((float)max(g_degs[et*NP + n], 1));
        g_cd[(1-et)*NP + n]   = rsqrtf((float)max(g_degd[et*NP + n], 1));
    }
}

// ---------------- parallel exclusive scan of in-degrees -> g_off ----------------
__global__ void k_scan1() {
    __shared__ int wsum[8];
    int tid = threadIdx.x, lane = tid & 31, wid = tid >> 5;
    int g = blockIdx.x * 256 + tid;
    int deg = 0;
    if (g < NTOT) {
        int dt = g / NP, n = g - dt * NP;
        deg = g_degd[(1 - dt) * NP + n];
    }
    int x = deg;
    #pragma unroll
    for (int o = 1; o < 32; o <<= 1) { int y = __shfl_up_sync(~0u, x, o); if (lane >= o) x += y; }
    if (lane == 31) wsum[wid] = x;
    __syncthreads();
    if (tid == 0) { int s = 0; for (int i = 0; i < 8; i++) { int t2 = wsum[i]; wsum[i] = s; s += t2; } }
    __syncthreads();
    if (g < NTOT) g_off[g] = wsum[wid] + x - deg;
    if (tid == 255) g_bsum[blockIdx.x] = wsum[7] + x;
}

__global__ void k_scan2() {    // 1 block, 256 threads, scans 196 block sums
    __shared__ int wsum[8];
    int tid = threadIdx.x, lane = tid & 31, wid = tid >> 5;
    int v = (tid < 196) ? g_bsum[tid] : 0;
    int x = v;
    #pragma unroll
    for (int o = 1; o < 32; o <<= 1) { int y = __shfl_up_sync(~0u, x, o); if (lane >= o) x += y; }
    if (lane == 31) wsum[wid] = x;
    __syncthreads();
    if (tid == 0) { int s = 0; for (int i = 0; i < 8; i++) { int t2 = wsum[i]; wsum[i] = s; s += t2; } }
    __syncthreads();
    int excl = wsum[wid] + x - v;
    if (tid < 196) g_bsum[tid] = excl;
    if (tid == 195) g_off[NTOT] = excl + v;
}

__global__ void k_scan3() {
    int g = blockIdx.x * 256 + threadIdx.x;
    if (g < NTOT) g_off[g] += g_bsum[blockIdx.x];
}

__global__ void k_fill(const int* __restrict__ ed) {
    int gid = blockIdx.x * blockDim.x + threadIdx.x;
    if (gid >= E2) return;
    int et = gid / EP;
    int gnode = (1 - et) * NP + ed[gid];
    int pos = g_off[gnode] + atomicAdd(&g_fill[gnode], 1);
    g_csr[pos] = gid;
}

// ---------------- layernorm (fp32 out, conv paths) ----------------
__global__ void k_ln(const float* __restrict__ x, const float* __restrict__ g,
                     const float* __restrict__ b, float* __restrict__ y) {
    __shared__ float sh[8];
    int n = blockIdx.x, t = blockIdx.y, c = threadIdx.x;
    size_t base = ((size_t)t*NP + n) * HID_;
    float v = x[base + c];
    float mu = block_sum(v, sh) * (1.0f / HID_);
    float d = v - mu;
    float var = block_sum(d * d, sh) * (1.0f / HID_);
    y[base + c] = d * rsqrtf(var + 1e-5f) * g[t*HID_ + c] + b[t*HID_ + c];
}

// ---------------- layernorm with split bf16 output (GEMM-A paths) ----------------
__global__ void k_ln_split(const float* __restrict__ x, const float* __restrict__ g,
                           const float* __restrict__ b) {
    __shared__ float sh[8];
    int n = blockIdx.x, t = blockIdx.y, c = threadIdx.x;
    size_t base = ((size_t)t*NP + n) * HID_;
    float v = x[base + c];
    float mu = block_sum(v, sh) * (1.0f / HID_);
    float d = v - mu;
    float var = block_sum(d * d, sh) * (1.0f / HID_);
    float y = d * rsqrtf(var + 1e-5f) * g[t*HID_ + c] + b[t*HID_ + c];
    __nv_bfloat16 hi = __float2bfloat16_rn(y);
    g_ahi[base + c] = hi;
    g_alo[base + c] = __float2bfloat16_rn(y - __bfloat162float(hi));
}

// ---------------- conv aggregation: CSR gather, split bf16 out ----------------
__global__ void __launch_bounds__(64) k_conv_gather(const float* __restrict__ hn,
                                                    const int* __restrict__ es) {
    int gnode = blockIdx.x;
    int tid = threadIdx.x;
    int off = g_off[gnode], end = g_off[gnode + 1];
    int dt = gnode / NP;
    int et = 1 - dt;
    float4 acc = make_float4(0.f, 0.f, 0.f, 0.f);
    for (int i = off; i < end; i++) {
        int eid = g_csr[i];
        int src = es[eid];
        float w = g_cs[et*NP + src];
        const float4 hv = *(const float4*)&hn[((size_t)et*NP + src)*HID_ + tid*4];
        acc.x += hv.x*w; acc.y += hv.y*w; acc.z += hv.z*w; acc.w += hv.w*w;
    }
    store_split4((size_t)gnode*HID_ + tid*4, acc);
}

// ---------------- fused attention: score+exp+den+gather, split bf16 out ----------------
// qkv layout: [node][ q(0:256) | k(256:512) | v(512:768) ]
__global__ void __launch_bounds__(64) k_attn(const float* __restrict__ qkv,
                                             const int* __restrict__ es) {
    __shared__ float sq[HID_];
    __shared__ float sden[2][8];
    int gnode = blockIdx.x, tid = threadIdx.x, lane = tid & 31, wid = tid >> 5;
    int off = g_off[gnode], deg = g_off[gnode + 1] - off;

    *(float4*)&sq[tid*4] = *(const float4*)&qkv[(size_t)gnode*768 + tid*4];
    __syncthreads();

    // pass 1: warp per edge — scores, exp, local denominator
    float denAcc = 0.f;
    for (int i = wid; i < deg; i += 2) {
        int eid = g_csr[off + i];
        int et = eid / EP;
        int sg = es[eid] + (et ? NP : 0);
        const float* kv = &qkv[(size_t)sg * 768 + 256];
        float myex = 0.f;
        #pragma unroll
        for (int hh = 0; hh < 8; hh++) {
            float p = sq[hh*32 + lane] * kv[hh*32 + lane];
            #pragma unroll
            for (int o = 16; o; o >>= 1) p += __shfl_xor_sync(~0u, p, o);
            float s = fminf(fmaxf(p * 0.17677669529663687f, -5.0f), 5.0f);
            float ex = expf(s);   // s in [-5,5]: no overflow; max-shift cancels exactly
            if (lane == hh) myex = ex;
        }
        if (lane < 8) {
            g_sc[(size_t)(off + i)*8 + lane] = myex;
            denAcc += myex;
        }
    }
    if (lane < 8) sden[wid][lane] = denAcc;
    __syncthreads();

    // pass 2: gather alpha * v
    int hh = tid >> 3;
    float den = sden[0][hh] + sden[1][hh];
    float rden = (den > 0.f) ? 1.0f / den : 0.f;
    float4 acc = make_float4(0.f, 0.f, 0.f, 0.f);
    for (int i = 0; i < deg; i++) {
        int eid = g_csr[off + i];
        int et = eid / EP;
        int sg = es[eid] + (et ? NP : 0);
        float alpha = g_sc[(size_t)(off + i)*8 + hh] * rden;
        const float4 vv = *(const float4*)&qkv[(size_t)sg*768 + 512 + tid*4];
        acc.x += vv.x*alpha; acc.y += vv.y*alpha; acc.z += vv.z*alpha; acc.w += vv.w*alpha;
    }
    store_split4((size_t)gnode*HID_ + tid*4, acc);
}

// ---------------- all-weights split (one launch) ----------------
// Input W layouts are [t][K][N]; output is [matrix][t][N][K] (QKV fused to N=768).
__global__ void k_wconv_all(const float* __restrict__ preW, const float* __restrict__ postW,
                            const float* __restrict__ qW, const float* __restrict__ kW,
                            const float* __restrict__ vW, const float* __restrict__ oW,
                            const float* __restrict__ f1W, const float* __restrict__ f2W) {
    int gid = blockIdx.x * 256 + threadIdx.x;
    if (gid >= WCVT_TOTAL) return;
    float x;
    if (gid < 262144) {                       // PRE, POST: [t][256][256]
        const float* W = (gid < 131072) ? preW : postW;
        int loc = gid & 131071;
        int t = loc >> 16, o = loc & 65535;
        int n = o >> 8, kk = o & 255;
        x = W[t*65536 + kk*256 + n];
    } else if (gid < 655360) {                // QKV: [t][768][256]
        int loc = gid - 262144;
        int t = loc / 196608, r = loc % 196608;
        int n7 = r >> 8, kk = r & 255;
        const float* W; int n;
        if (n7 < 256)      { W = qW; n = n7; }
        else if (n7 < 512) { W = kW; n = n7 - 256; }
        else               { W = vW; n = n7 - 512; }
        x = W[t*65536 + kk*256 + n];
    } else if (gid < 786432) {                // O: [t][256][256]
        int loc = gid - 655360;
        int t = loc >> 16, o = loc & 65535;
        int n = o >> 8, kk = o & 255;
        x = oW[t*65536 + kk*256 + n];
    } else if (gid < 1048576) {               // F1: [t][512][256]
        int loc = gid - 786432;
        int t = loc >> 17, o = loc & 131071;
        int n = o >> 8, kk = o & 255;
        x = f1W[t*131072 + kk*512 + n];
    } else {                                  // F2: [t][256][512]
        int loc = gid - 1048576;
        int t = loc >> 17, o = loc & 131071;
        int n = o >> 9, kk = o & 511;
        x = f2W[t*131072 + kk*256 + n];
    }
    __nv_bfloat16 h = __float2bfloat16_rn(x);
    g_wbhi[gid] = h;
    g_wblo[gid] = __float2bfloat16_rn(x - __bfloat162float(h));
}

__global__ void k_qkvb(const float* __restrict__ qB, const float* __restrict__ kB,
                       const float* __restrict__ vB) {
    int i = blockIdx.x * 256 + threadIdx.x;
    if (i >= T_ * 768) return;
    int t = i / 768, c = i % 768;
    g_qkvb[i] = (c < 256) ? qB[t*256 + c] : (c < 512) ? kB[t*256 + c - 256] : vB[t*256 + c - 512];
}

// ---------------- bf16-split tensor GEMM, all-cp.async double-buffered ----------------
#define PAD 40
#define ST_A   (128*PAD)
#define ST_ALL (4*128*PAD)
#define GSMEM  (2*ST_ALL*2)

__global__ void __launch_bounds__(256, 2) gemm_mma(
    const __nv_bfloat16* __restrict__ Ahi_g, const __nv_bfloat16* __restrict__ Alo_g,
    const __nv_bfloat16* __restrict__ Bhi_g, const __nv_bfloat16* __restrict__ Blo_g,
    const float* __restrict__ bias, const float* __restrict__ rowscale,
    const float* __restrict__ resid, float* __restrict__ C,
    __nv_bfloat16* __restrict__ Chi, __nv_bfloat16* __restrict__ Clo,
    int M, int K, int N, int wswap, int dogelu)
{
    extern __shared__ __nv_bfloat16 smem[];

    int tid = threadIdx.x;
    int warp = tid >> 5, lane = tid & 31;
    int wm = warp & 3, wn = warp >> 2;
    int t = blockIdx.z;
    int wi = wswap ? (1 - t) : t;

    Ahi_g += (size_t)t  * M * K;
    Alo_g += (size_t)t  * M * K;
    Bhi_g += (size_t)wi * K * N;
    Blo_g += (size_t)wi * K * N;
    bias  += (size_t)wi * N;
    const float* rs = rowscale ? rowscale + (size_t)t * M : nullptr;
    const float* rd = resid ? resid + (size_t)t * M * N : nullptr;
    C   += (size_t)t * M * N;
    if (Chi) { Chi += (size_t)t * M * N; Clo += (size_t)t * M * N; }

    int m0 = blockIdx.y * 128, n0 = blockIdx.x * 128;

    float acc[2][8][4];
    #pragma unroll
    for (int i = 0; i < 2; i++)
        #pragma unroll
        for (int j = 0; j < 8; j++)
            #pragma unroll
            for (int l = 0; l < 4; l++) acc[i][j][l] = 0.f;

    int lrow = lane & 7, lsel = lane >> 3;
    int a_r = (lsel & 1) * 8 + lrow;
    int a_c = (lsel >> 1) * 8;
    int b_r = (lsel >> 1) * 8 + lrow;
    int b_c = (lsel & 1) * 8;

    unsigned usm = smem_u32(smem);
    int grow = tid >> 2, gseg = tid & 3;
    int nchunks = K >> 5;

    {
        unsigned base = usm;
        #pragma unroll
        for (int i = 0; i < 2; i++) {
            int row = grow + i * 64;
            unsigned loc = 2u * (unsigned)(row * PAD + gseg * 8);
            size_t goa = (size_t)(m0 + row) * K + (gseg << 3);
            size_t gob = (size_t)(n0 + row) * K + (gseg << 3);
            CP16(base + loc,               &Ahi_g[goa]);
            CP16(base + 2u*ST_A + loc,     &Alo_g[goa]);
            CP16(base + 2u*2*ST_A + loc,   &Bhi_g[gob]);
            CP16(base + 2u*3*ST_A + loc,   &Blo_g[gob]);
        }
        CP_COMMIT();
    }

    for (int c = 0; c < nchunks; c++) {
        int s = c & 1;
        unsigned base = usm + 2u * (unsigned)(s * ST_ALL);
        unsigned uah = base, ual = base + 2u*ST_A, ubh = base + 2u*2*ST_A, ubl = base + 2u*3*ST_A;

        CP_WAIT0();
        __syncthreads();

        if (c + 1 < nchunks) {
            int koff = (c + 1) << 5;
            unsigned nb = usm + 2u * (unsigned)((1 - s) * ST_ALL);
            #pragma unroll
            for (int i = 0; i < 2; i++) {
                int row = grow + i * 64;
                unsigned loc = 2u * (unsigned)(row * PAD + gseg * 8);
                size_t goa = (size_t)(m0 + row) * K + koff + (gseg << 3);
                size_t gob = (size_t)(n0 + row) * K + koff + (gseg << 3);
                CP16(nb + loc,             &Ahi_g[goa]);
                CP16(nb + 2u*ST_A + loc,   &Alo_g[goa]);
                CP16(nb + 2u*2*ST_A + loc, &Bhi_g[gob]);
                CP16(nb + 2u*3*ST_A + loc, &Blo_g[gob]);
            }
            CP_COMMIT();
        }

        #pragma unroll
        for (int ks = 0; ks < 2; ks++) {
            int kk = ks * 16;
            unsigned ah[2][4], al[2][4];
            #pragma unroll
            for (int mt = 0; mt < 2; mt++) {
                unsigned off = 2u * (unsigned)((wm*32 + mt*16 + a_r) * PAD + kk + a_c);
                LDM4(ah[mt], uah + off);
                LDM4(al[mt], ual + off);
            }
            #pragma unroll
            for (int bi = 0; bi < 4; bi++) {
                unsigned off = 2u * (unsigned)((wn*64 + bi*16 + b_r) * PAD + kk + b_c);
                unsigned bh[4], bl[4];
                LDM4(bh, ubh + off);
                LDM4(bl, ubl + off);
                #pragma unroll
                for (int mt = 0; mt < 2; mt++) {
                    #pragma unroll
                    for (int j = 0; j < 2; j++) {
                        float* cc = acc[mt][bi*2 + j];
                        MMA_BF16(cc, ah[mt], bh[j*2], bh[j*2+1]);
                        MMA_BF16(cc, ah[mt], bl[j*2], bl[j*2+1]);
                        MMA_BF16(cc, al[mt], bh[j*2], bh[j*2+1]);
                    }
                }
            }
        }
        __syncthreads();
    }

    int g = lane >> 2, tig = lane & 3;
    #pragma unroll
    for (int mt = 0; mt < 2; mt++) {
        #pragma unroll
        for (int nt = 0; nt < 8; nt++) {
            int col = n0 + wn*64 + nt*8 + tig*2;
            float b0 = bias[col], b1 = bias[col+1];
            #pragma unroll
            for (int half = 0; half < 2; half++) {
                int r = m0 + wm*32 + mt*16 + g + half*8;
                if (r >= M) continue;
                float scale = rs ? rs[r] : 1.0f;
                size_t idx = (size_t)r * N + col;
                float2 o;
                o.x = acc[mt][nt][half*2+0] * scale + b0;
                o.y = acc[mt][nt][half*2+1] * scale + b1;
                if (rd) {
                    const float2 rv = *(const float2*)&rd[idx];
                    o.x += rv.x; o.y += rv.y;
                }
                if (dogelu) {
                    o.x = 0.5f*o.x*(1.0f+erff(o.x*0.70710678118654752f));
                    o.y = 0.5f*o.y*(1.0f+erff(o.y*0.70710678118654752f));
                }
                if (Chi) {
                    __nv_bfloat16 h0 = __float2bfloat16_rn(o.x);
                    __nv_bfloat16 h1 = __float2bfloat16_rn(o.y);
                    *(unsigned*)&Chi[idx] = pack_bf2(h0, h1);
                    *(unsigned*)&Clo[idx] = pack_bf2(
                        __float2bfloat16_rn(o.x - __bfloat162float(h0)),
                        __float2bfloat16_rn(o.y - __bfloat162float(h1)));
                } else {
                    *(float2*)&C[idx] = o;
                }
            }
        }
    }
}

// ---------------- host orchestration ----------------
extern "C" void kernel_launch(void* const* d_in, const int* in_sizes, int n_in,
                              void* d_out, int out_size) {
    const float* h      = (const float*)d_in[0];
    const int*   es     = (const int*)  d_in[1];
    const int*   ed     = (const int*)  d_in[2];
    const float* preW   = (const float*)d_in[3];
    const float* preB   = (const float*)d_in[4];
    const float* postW  = (const float*)d_in[5];
    const float* postB  = (const float*)d_in[6];
    const float* qW     = (const float*)d_in[7];
    const float* qB     = (const float*)d_in[8];
    const float* kW     = (const float*)d_in[9];
    const float* kB     = (const float*)d_in[10];
    const float* vW     = (const float*)d_in[11];
    const float* vB     = (const float*)d_in[12];
    const float* oW     = (const float*)d_in[13];
    const float* oB     = (const float*)d_in[14];
    const float* fW1    = (const float*)d_in[15];
    const float* fB1    = (const float*)d_in[16];
    const float* fW2    = (const float*)d_in[17];
    const float* fB2    = (const float*)d_in[18];
    const float* lnPreG = (const float*)d_in[19];
    const float* lnPreB = (const float*)d_in[20];
    const float* lnAtG  = (const float*)d_in[21];
    const float* lnAtB  = (const float*)d_in[22];
    const float* lnPoG  = (const float*)d_in[23];
    const float* lnPoB  = (const float*)d_in[24];
    const float* lnFfG  = (const float*)d_in[25];
    const float* lnFfB  = (const float*)d_in[26];
    float* out = (float*)d_out;

    float *hn, *qkv, *cd, *qkvb;
    __nv_bfloat16 *wbhi, *wblo, *ahi, *alo, *fhi, *flo;
    int *degs, *degd, *fill;
    cudaGetSymbolAddress((void**)&hn,   g_hn);
    cudaGetSymbolAddress((void**)&qkv,  g_qkv);
    cudaGetSymbolAddress((void**)&cd,   g_cd);
    cudaGetSymbolAddress((void**)&qkvb, g_qkvb);
    cudaGetSymbolAddress((void**)&degs, g_degs);
    cudaGetSymbolAddress((void**)&degd, g_degd);
    cudaGetSymbolAddress((void**)&fill, g_fill);
    cudaGetSymbolAddress((void**)&wbhi, g_wbhi);
    cudaGetSymbolAddress((void**)&wblo, g_wblo);
    cudaGetSymbolAddress((void**)&ahi,  g_ahi);
    cudaGetSymbolAddress((void**)&alo,  g_alo);
    cudaGetSymbolAddress((void**)&fhi,  g_fhi);
    cudaGetSymbolAddress((void**)&flo,  g_flo);

    cudaFuncSetAttribute(gemm_mma, cudaFuncAttributeMaxDynamicSharedMemorySize, GSMEM);

    const dim3 lnGrid(NP, T_);
    const dim3 g256(2, 196, 2);
    const dim3 g768(6, 196, 2);
    const dim3 g512(4, 196, 2);
    const int NB = (NTOT + 255) / 256;   // 196

    // weights + bias + degrees + CSR
    k_wconv_all<<<WCVT_TOTAL/256, 256>>>(preW, postW, qW, kW, vW, oW, fW1, fW2);
    k_qkvb<<<(T_*768 + 255)/256, 256>>>(qB, kB, vB);
    cudaMemsetAsync(degs, 0, sizeof(int) * T_ * NP);
    cudaMemsetAsync(degd, 0, sizeof(int) * T_ * NP);
    cudaMemsetAsync(fill, 0, sizeof(int) * NTOT);
    k_deg<<<(E2 + 255)/256, 256>>>(es, ed);
    k_degnorm<<<(NP + 255)/256, 256>>>();
    k_scan1<<<NB, 256>>>();
    k_scan2<<<1, 256>>>();
    k_scan3<<<NB, 256>>>();
    k_fill<<<(E2 + 255)/256, 256>>>(ed);

    // ---- conv1 ----
    k_ln<<<lnGrid, 256>>>(h, lnPreG, lnPreB, hn);
    k_conv_gather<<<NTOT, 64>>>(hn, es);
    gemm_mma<<<g256, 256, GSMEM>>>(ahi, alo, wbhi+WOFF_PRE, wblo+WOFF_PRE, preB, cd, h, out,
                                   nullptr, nullptr, NP, HID_, HID_, 1, 0);

    // ---- attention ----
    k_ln_split<<<lnGrid, 256>>>(out, lnAtG, lnAtB);
    gemm_mma<<<g768, 256, GSMEM>>>(ahi, alo, wbhi+WOFF_QKV, wblo+WOFF_QKV, qkvb, nullptr, nullptr,
                                   qkv, nullptr, nullptr, NP, HID_, 768, 0, 0);
    k_attn<<<NTOT, 64>>>(qkv, es);
    gemm_mma<<<g256, 256, GSMEM>>>(ahi, alo, wbhi+WOFF_O, wblo+WOFF_O, oB, nullptr, out, out,
                                   nullptr, nullptr, NP, HID_, HID_, 0, 0);

    // ---- conv2 ----
    k_ln<<<lnGrid, 256>>>(out, lnPoG, lnPoB, hn);
    k_conv_gather<<<NTOT, 64>>>(hn, es);
    gemm_mma<<<g256, 256, GSMEM>>>(ahi, alo, wbhi+WOFF_POST, wblo+WOFF_POST, postB, cd, out, out,
                                   nullptr, nullptr, NP, HID_, HID_, 1, 0);

    // ---- FFN ----
    k_ln_split<<<lnGrid, 256>>>(out, lnFfG, lnFfB);
    gemm_mma<<<g512, 256, GSMEM>>>(ahi, alo, wbhi+WOFF_F1, wblo+WOFF_F1, fB1, nullptr, nullptr,
                                   nullptr, fhi, flo, NP, HID_, 512, 0, 1);
    gemm_mma<<<g256, 256, GSMEM>>>(fhi, flo, wbhi+WOFF_F2, wblo+WOFF_F2, fB2, nullptr, out, out,
                                   nullptr, nullptr, NP, 512, HID_, 0, 0);
}

// round 9
// speedup vs baseline: 2.9735x; 1.1203x over previous
#include <cuda_runtime.h>
#include <cuda_bf16.h>
#include <math.h>

#define T_   2
#define NP   25000
#define EP   200000
#define HID_ 256
#define NTOT (T_*NP)
#define E2   (2*EP)

// ---------------- scratch (static __device__ — no allocations) ----------------
__device__ float g_hn [(size_t)T_*NP*HID_];       // fp32 LN out (conv paths)
__device__ float g_qkv[(size_t)NTOT*768];         // interleaved q|k|v per node
__device__ float g_sc [(size_t)E2*8];             // ex values (CSR order)
__device__ float g_cs [T_*NP];
__device__ float g_cd [T_*NP];
__device__ float g_qkvb[T_*768];
__device__ int   g_degs[T_*NP];
__device__ int   g_degd[T_*NP];
__device__ int   g_bsum[256];
// CSR by global dst node
__device__ int   g_off [NTOT + 1];
__device__ int   g_fill[NTOT];
__device__ int   g_csr [E2];
// split A operands (bf16 hi/lo)
__device__ __nv_bfloat16 g_ahi[(size_t)NTOT*HID_];
__device__ __nv_bfloat16 g_alo[(size_t)NTOT*HID_];
__device__ __nv_bfloat16 g_fhi[(size_t)NTOT*512];
__device__ __nv_bfloat16 g_flo[(size_t)NTOT*512];
// split weights, bf16, layout [matrix][t][N][K]
#define WCVT_TOTAL 1310720
__device__ __nv_bfloat16 g_wbhi[WCVT_TOTAL];
__device__ __nv_bfloat16 g_wblo[WCVT_TOTAL];
#define WOFF_PRE  0
#define WOFF_POST 131072
#define WOFF_QKV  262144
#define WOFF_O    655360
#define WOFF_F1   786432
#define WOFF_F2   1048576

// ---------------- mma / async helpers ----------------
__device__ __forceinline__ unsigned smem_u32(const void* p) {
    unsigned a;
    asm("{ .reg .u64 t; cvta.to.shared.u64 t, %1; cvt.u32.u64 %0, t; }" : "=r"(a) : "l"(p));
    return a;
}
#define LDM4(r, a) \
    asm volatile("ldmatrix.sync.aligned.m8n8.x4.shared.b16 {%0,%1,%2,%3}, [%4];" \
        : "=r"((r)[0]),"=r"((r)[1]),"=r"((r)[2]),"=r"((r)[3]) : "r"(a))
#define MMA_BF16(c, a, b0, b1) \
    asm volatile("mma.sync.aligned.m16n8k16.row.col.f32.bf16.bf16.f32 " \
        "{%0,%1,%2,%3}, {%4,%5,%6,%7}, {%8,%9}, {%0,%1,%2,%3};" \
        : "+f"((c)[0]),"+f"((c)[1]),"+f"((c)[2]),"+f"((c)[3]) \
        : "r"((a)[0]),"r"((a)[1]),"r"((a)[2]),"r"((a)[3]), "r"(b0),"r"(b1))
#define CP16(dst, src) \
    asm volatile("cp.async.cg.shared.global [%0], [%1], 16;" :: "r"(dst), "l"(src) : "memory")
#define CP_COMMIT() asm volatile("cp.async.commit_group;" ::: "memory")
#define CP_WAIT0()  asm volatile("cp.async.wait_group 0;" ::: "memory")

__device__ __forceinline__ unsigned pack_bf2(__nv_bfloat16 a, __nv_bfloat16 b) {
    __nv_bfloat162 t = __halves2bfloat162(a, b);
    return *(unsigned*)&t;
}
__device__ __forceinline__ void store_split4(size_t idx, float4 v) {
    __nv_bfloat16 h0 = __float2bfloat16_rn(v.x), h1 = __float2bfloat16_rn(v.y);
    __nv_bfloat16 h2 = __float2bfloat16_rn(v.z), h3 = __float2bfloat16_rn(v.w);
    uint2 hh, ll;
    hh.x = pack_bf2(h0, h1); hh.y = pack_bf2(h2, h3);
    ll.x = pack_bf2(__float2bfloat16_rn(v.x - __bfloat162float(h0)),
                    __float2bfloat16_rn(v.y - __bfloat162float(h1)));
    ll.y = pack_bf2(__float2bfloat16_rn(v.z - __bfloat162float(h2)),
                    __float2bfloat16_rn(v.w - __bfloat162float(h3)));
    *(uint2*)&g_ahi[idx] = hh;
    *(uint2*)&g_alo[idx] = ll;
}
__device__ __forceinline__ float warp_sum(float v) {
    #pragma unroll
    for (int o = 16; o; o >>= 1) v += __shfl_xor_sync(0xffffffffu, v, o);
    return v;
}

// ---------------- degree + CSR build ----------------
__global__ void k_deg(const int* __restrict__ es, const int* __restrict__ ed) {
    int gid = blockIdx.x * blockDim.x + threadIdx.x;
    if (gid >= E2) return;
    int et = gid / EP;
    atomicAdd(&g_degs[et*NP + es[gid]], 1);
    atomicAdd(&g_degd[et*NP + ed[gid]], 1);
}

__global__ void k_degnorm() {
    int n = blockIdx.x * blockDim.x + threadIdx.x;
    if (n >= NP) return;
    #pragma unroll
    for (int et = 0; et < 2; et++) {
        g_cs[et*NP + n]       = rsqrtf((float)max(g_degs[et*NP + n], 1));
        g_cd[(1-et)*NP + n]   = rsqrtf((float)max(g_degd[et*NP + n], 1));
    }
}

// ---------------- parallel exclusive scan of in-degrees -> g_off ----------------
__global__ void k_scan1() {
    __shared__ int wsum[8];
    int tid = threadIdx.x, lane = tid & 31, wid = tid >> 5;
    int g = blockIdx.x * 256 + tid;
    int deg = 0;
    if (g < NTOT) {
        int dt = g / NP, n = g - dt * NP;
        deg = g_degd[(1 - dt) * NP + n];
    }
    int x = deg;
    #pragma unroll
    for (int o = 1; o < 32; o <<= 1) { int y = __shfl_up_sync(~0u, x, o); if (lane >= o) x += y; }
    if (lane == 31) wsum[wid] = x;
    __syncthreads();
    if (tid == 0) { int s = 0; for (int i = 0; i < 8; i++) { int t2 = wsum[i]; wsum[i] = s; s += t2; } }
    __syncthreads();
    if (g < NTOT) g_off[g] = wsum[wid] + x - deg;
    if (tid == 255) g_bsum[blockIdx.x] = wsum[7] + x;
}

__global__ void k_scan2() {    // 1 block, 256 threads, scans 196 block sums
    __shared__ int wsum[8];
    int tid = threadIdx.x, lane = tid & 31, wid = tid >> 5;
    int v = (tid < 196) ? g_bsum[tid] : 0;
    int x = v;
    #pragma unroll
    for (int o = 1; o < 32; o <<= 1) { int y = __shfl_up_sync(~0u, x, o); if (lane >= o) x += y; }
    if (lane == 31) wsum[wid] = x;
    __syncthreads();
    if (tid == 0) { int s = 0; for (int i = 0; i < 8; i++) { int t2 = wsum[i]; wsum[i] = s; s += t2; } }
    __syncthreads();
    int excl = wsum[wid] + x - v;
    if (tid < 196) g_bsum[tid] = excl;
    if (tid == 195) g_off[NTOT] = excl + v;
}

__global__ void k_scan3() {
    int g = blockIdx.x * 256 + threadIdx.x;
    if (g < NTOT) g_off[g] += g_bsum[blockIdx.x];
}

__global__ void k_fill(const int* __restrict__ ed) {
    int gid = blockIdx.x * blockDim.x + threadIdx.x;
    if (gid >= E2) return;
    int et = gid / EP;
    int gnode = (1 - et) * NP + ed[gid];
    int pos = g_off[gnode] + atomicAdd(&g_fill[gnode], 1);
    g_csr[pos] = gid;
}

// ---------------- layernorm: warp per node, no barriers ----------------
// block = 256 thr = 8 warps = 8 nodes. Lane covers 8 contiguous floats.
__global__ void k_ln(const float* __restrict__ x, const float* __restrict__ g,
                     const float* __restrict__ b, float* __restrict__ y) {
    int gn = blockIdx.x * 8 + (threadIdx.x >> 5);
    int lane = threadIdx.x & 31;
    int t = gn / NP;
    size_t base = (size_t)gn * HID_ + lane * 8;
    float4 v0 = *(const float4*)&x[base];
    float4 v1 = *(const float4*)&x[base + 4];
    float s = v0.x+v0.y+v0.z+v0.w + v1.x+v1.y+v1.z+v1.w;
    float mu = warp_sum(s) * (1.0f / HID_);
    float d0x=v0.x-mu, d0y=v0.y-mu, d0z=v0.z-mu, d0w=v0.w-mu;
    float d1x=v1.x-mu, d1y=v1.y-mu, d1z=v1.z-mu, d1w=v1.w-mu;
    float ss = d0x*d0x+d0y*d0y+d0z*d0z+d0w*d0w + d1x*d1x+d1y*d1y+d1z*d1z+d1w*d1w;
    float rstd = rsqrtf(warp_sum(ss) * (1.0f / HID_) + 1e-5f);
    size_t pb = (size_t)t * HID_ + lane * 8;
    float4 g0 = *(const float4*)&g[pb],  g1 = *(const float4*)&g[pb + 4];
    float4 b0 = *(const float4*)&b[pb],  b1 = *(const float4*)&b[pb + 4];
    float4 o0, o1;
    o0.x = d0x*rstd*g0.x + b0.x; o0.y = d0y*rstd*g0.y + b0.y;
    o0.z = d0z*rstd*g0.z + b0.z; o0.w = d0w*rstd*g0.w + b0.w;
    o1.x = d1x*rstd*g1.x + b1.x; o1.y = d1y*rstd*g1.y + b1.y;
    o1.z = d1z*rstd*g1.z + b1.z; o1.w = d1w*rstd*g1.w + b1.w;
    *(float4*)&y[base]     = o0;
    *(float4*)&y[base + 4] = o1;
}

// warp-per-node LN with split bf16 output
__global__ void k_ln_split(const float* __restrict__ x, const float* __restrict__ g,
                           const float* __restrict__ b) {
    int gn = blockIdx.x * 8 + (threadIdx.x >> 5);
    int lane = threadIdx.x & 31;
    int t = gn / NP;
    size_t base = (size_t)gn * HID_ + lane * 8;
    float4 v0 = *(const float4*)&x[base];
    float4 v1 = *(const float4*)&x[base + 4];
    float s = v0.x+v0.y+v0.z+v0.w + v1.x+v1.y+v1.z+v1.w;
    float mu = warp_sum(s) * (1.0f / HID_);
    float d0x=v0.x-mu, d0y=v0.y-mu, d0z=v0.z-mu, d0w=v0.w-mu;
    float d1x=v1.x-mu, d1y=v1.y-mu, d1z=v1.z-mu, d1w=v1.w-mu;
    float ss = d0x*d0x+d0y*d0y+d0z*d0z+d0w*d0w + d1x*d1x+d1y*d1y+d1z*d1z+d1w*d1w;
    float rstd = rsqrtf(warp_sum(ss) * (1.0f / HID_) + 1e-5f);
    size_t pb = (size_t)t * HID_ + lane * 8;
    float4 g0 = *(const float4*)&g[pb],  g1 = *(const float4*)&g[pb + 4];
    float4 b0 = *(const float4*)&b[pb],  b1 = *(const float4*)&b[pb + 4];
    float4 o0, o1;
    o0.x = d0x*rstd*g0.x + b0.x; o0.y = d0y*rstd*g0.y + b0.y;
    o0.z = d0z*rstd*g0.z + b0.z; o0.w = d0w*rstd*g0.w + b0.w;
    o1.x = d1x*rstd*g1.x + b1.x; o1.y = d1y*rstd*g1.y + b1.y;
    o1.z = d1z*rstd*g1.z + b1.z; o1.w = d1w*rstd*g1.w + b1.w;
    store_split4(base,     o0);
    store_split4(base + 4, o1);
}

// ---------------- conv aggregation: CSR gather, split bf16 out ----------------
__global__ void __launch_bounds__(64) k_conv_gather(const float* __restrict__ hn,
                                                    const int* __restrict__ es) {
    int gnode = blockIdx.x;
    int tid = threadIdx.x;
    int off = g_off[gnode], end = g_off[gnode + 1];
    int dt = gnode / NP;
    int et = 1 - dt;
    float4 acc = make_float4(0.f, 0.f, 0.f, 0.f);
    for (int i = off; i < end; i++) {
        int eid = g_csr[i];
        int src = es[eid];
        float w = g_cs[et*NP + src];
        const float4 hv = *(const float4*)&hn[((size_t)et*NP + src)*HID_ + tid*4];
        acc.x += hv.x*w; acc.y += hv.y*w; acc.z += hv.z*w; acc.w += hv.w*w;
    }
    store_split4((size_t)gnode*HID_ + tid*4, acc);
}

// ---------------- fused attention: score+exp+den+gather, split bf16 out ----------------
// qkv layout: [node][ q(0:256) | k(256:512) | v(512:768) ]
#define ECACHE 160
__global__ void __launch_bounds__(64) k_attn(const float* __restrict__ qkv,
                                             const int* __restrict__ es) {
    __shared__ float sq[HID_];
    __shared__ float sden[2][8];
    __shared__ int ssrc[ECACHE];
    int gnode = blockIdx.x, tid = threadIdx.x, lane = tid & 31, wid = tid >> 5;
    int off = g_off[gnode], deg = g_off[gnode + 1] - off;

    *(float4*)&sq[tid*4] = *(const float4*)&qkv[(size_t)gnode*768 + tid*4];
    int ncache = (deg < ECACHE) ? deg : ECACHE;
    for (int i = tid; i < ncache; i += 64) {
        int eid = g_csr[off + i];
        int et = eid / EP;
        ssrc[i] = es[eid] + (et ? NP : 0);
    }
    __syncthreads();

    // pass 1: warp per edge — scores, exp, local denominator
    float denAcc = 0.f;
    for (int i = wid; i < deg; i += 2) {
        int sg;
        if (i < ECACHE) sg = ssrc[i];
        else { int eid = g_csr[off + i]; int et = eid / EP; sg = es[eid] + (et ? NP : 0); }
        const float* kv = &qkv[(size_t)sg * 768 + 256];
        float myex = 0.f;
        #pragma unroll
        for (int hh = 0; hh < 8; hh++) {
            float p = sq[hh*32 + lane] * kv[hh*32 + lane];
            p = warp_sum(p);
            float s = fminf(fmaxf(p * 0.17677669529663687f, -5.0f), 5.0f);
            float ex = expf(s);   // s in [-5,5]: no overflow; max-shift cancels exactly
            if (lane == hh) myex = ex;
        }
        if (lane < 8) {
            g_sc[(size_t)(off + i)*8 + lane] = myex;
            denAcc += myex;
        }
    }
    if (lane < 8) sden[wid][lane] = denAcc;
    __syncthreads();

    // pass 2: gather alpha * v
    int hh = tid >> 3;
    float den = sden[0][hh] + sden[1][hh];
    float rden = (den > 0.f) ? 1.0f / den : 0.f;
    float4 acc = make_float4(0.f, 0.f, 0.f, 0.f);
    for (int i = 0; i < deg; i++) {
        int sg;
        if (i < ECACHE) sg = ssrc[i];
        else { int eid = g_csr[off + i]; int et = eid / EP; sg = es[eid] + (et ? NP : 0); }
        float alpha = g_sc[(size_t)(off + i)*8 + hh] * rden;
        const float4 vv = *(const float4*)&qkv[(size_t)sg*768 + 512 + tid*4];
        acc.x += vv.x*alpha; acc.y += vv.y*alpha; acc.z += vv.z*alpha; acc.w += vv.w*alpha;
    }
    store_split4((size_t)gnode*HID_ + tid*4, acc);
}

// ---------------- all-weights split (one launch) ----------------
// Input W layouts are [t][K][N]; output is [matrix][t][N][K] (QKV fused to N=768).
__global__ void k_wconv_all(const float* __restrict__ preW, const float* __restrict__ postW,
                            const float* __restrict__ qW, const float* __restrict__ kW,
                            const float* __restrict__ vW, const float* __restrict__ oW,
                            const float* __restrict__ f1W, const float* __restrict__ f2W) {
    int gid = blockIdx.x * 256 + threadIdx.x;
    if (gid >= WCVT_TOTAL) return;
    float x;
    if (gid < 262144) {                       // PRE, POST: [t][256][256]
        const float* W = (gid < 131072) ? preW : postW;
        int loc = gid & 131071;
        int t = loc >> 16, o = loc & 65535;
        int n = o >> 8, kk = o & 255;
        x = W[t*65536 + kk*256 + n];
    } else if (gid < 655360) {                // QKV: [t][768][256]
        int loc = gid - 262144;
        int t = loc / 196608, r = loc % 196608;
        int n7 = r >> 8, kk = r & 255;
        const float* W; int n;
        if (n7 < 256)      { W = qW; n = n7; }
        else if (n7 < 512) { W = kW; n = n7 - 256; }
        else               { W = vW; n = n7 - 512; }
        x = W[t*65536 + kk*256 + n];
    } else if (gid < 786432) {                // O: [t][256][256]
        int loc = gid - 655360;
        int t = loc >> 16, o = loc & 65535;
        int n = o >> 8, kk = o & 255;
        x = oW[t*65536 + kk*256 + n];
    } else if (gid < 1048576) {               // F1: [t][512][256]
        int loc = gid - 786432;
        int t = loc >> 17, o = loc & 131071;
        int n = o >> 8, kk = o & 255;
        x = f1W[t*131072 + kk*512 + n];
    } else {                                  // F2: [t][256][512]
        int loc = gid - 1048576;
        int t = loc >> 17, o = loc & 131071;
        int n = o >> 9, kk = o & 511;
        x = f2W[t*131072 + kk*256 + n];
    }
    __nv_bfloat16 h = __float2bfloat16_rn(x);
    g_wbhi[gid] = h;
    g_wblo[gid] = __float2bfloat16_rn(x - __bfloat162float(h));
}

__global__ void k_qkvb(const float* __restrict__ qB, const float* __restrict__ kB,
                       const float* __restrict__ vB) {
    int i = blockIdx.x * 256 + threadIdx.x;
    if (i >= T_ * 768) return;
    int t = i / 768, c = i % 768;
    g_qkvb[i] = (c < 256) ? qB[t*256 + c] : (c < 512) ? kB[t*256 + c - 256] : vB[t*256 + c - 512];
}

// ---------------- bf16-split tensor GEMM, all-cp.async double-buffered ----------------
#define PAD 40
#define ST_A   (128*PAD)
#define ST_ALL (4*128*PAD)
#define GSMEM  (2*ST_ALL*2)

__global__ void __launch_bounds__(256, 2) gemm_mma(
    const __nv_bfloat16* __restrict__ Ahi_g, const __nv_bfloat16* __restrict__ Alo_g,
    const __nv_bfloat16* __restrict__ Bhi_g, const __nv_bfloat16* __restrict__ Blo_g,
    const float* __restrict__ bias, const float* __restrict__ rowscale,
    const float* __restrict__ resid, float* __restrict__ C,
    __nv_bfloat16* __restrict__ Chi, __nv_bfloat16* __restrict__ Clo,
    int M, int K, int N, int wswap, int dogelu)
{
    extern __shared__ __nv_bfloat16 smem[];

    int tid = threadIdx.x;
    int warp = tid >> 5, lane = tid & 31;
    int wm = warp & 3, wn = warp >> 2;
    int t = blockIdx.z;
    int wi = wswap ? (1 - t) : t;

    Ahi_g += (size_t)t  * M * K;
    Alo_g += (size_t)t  * M * K;
    Bhi_g += (size_t)wi * K * N;
    Blo_g += (size_t)wi * K * N;
    bias  += (size_t)wi * N;
    const float* rs = rowscale ? rowscale + (size_t)t * M : nullptr;
    const float* rd = resid ? resid + (size_t)t * M * N : nullptr;
    C   += (size_t)t * M * N;
    if (Chi) { Chi += (size_t)t * M * N; Clo += (size_t)t * M * N; }

    int m0 = blockIdx.y * 128, n0 = blockIdx.x * 128;

    float acc[2][8][4];
    #pragma unroll
    for (int i = 0; i < 2; i++)
        #pragma unroll
        for (int j = 0; j < 8; j++)
            #pragma unroll
            for (int l = 0; l < 4; l++) acc[i][j][l] = 0.f;

    int lrow = lane & 7, lsel = lane >> 3;
    int a_r = (lsel & 1) * 8 + lrow;
    int a_c = (lsel >> 1) * 8;
    int b_r = (lsel >> 1) * 8 + lrow;
    int b_c = (lsel & 1) * 8;

    unsigned usm = smem_u32(smem);
    int grow = tid >> 2, gseg = tid & 3;
    int nchunks = K >> 5;

    {
        unsigned base = usm;
        #pragma unroll
        for (int i = 0; i < 2; i++) {
            int row = grow + i * 64;
            unsigned loc = 2u * (unsigned)(row * PAD + gseg * 8);
            size_t goa = (size_t)(m0 + row) * K + (gseg << 3);
            size_t gob = (size_t)(n0 + row) * K + (gseg << 3);
            CP16(base + loc,               &Ahi_g[goa]);
            CP16(base + 2u*ST_A + loc,     &Alo_g[goa]);
            CP16(base + 2u*2*ST_A + loc,   &Bhi_g[gob]);
            CP16(base + 2u*3*ST_A + loc,   &Blo_g[gob]);
        }
        CP_COMMIT();
    }

    for (int c = 0; c < nchunks; c++) {
        int s = c & 1;
        unsigned base = usm + 2u * (unsigned)(s * ST_ALL);
        unsigned uah = base, ual = base + 2u*ST_A, ubh = base + 2u*2*ST_A, ubl = base + 2u*3*ST_A;

        CP_WAIT0();
        __syncthreads();

        if (c + 1 < nchunks) {
            int koff = (c + 1) << 5;
            unsigned nb = usm + 2u * (unsigned)((1 - s) * ST_ALL);
            #pragma unroll
            for (int i = 0; i < 2; i++) {
                int row = grow + i * 64;
                unsigned loc = 2u * (unsigned)(row * PAD + gseg * 8);
                size_t goa = (size_t)(m0 + row) * K + koff + (gseg << 3);
                size_t gob = (size_t)(n0 + row) * K + koff + (gseg << 3);
                CP16(nb + loc,             &Ahi_g[goa]);
                CP16(nb + 2u*ST_A + loc,   &Alo_g[goa]);
                CP16(nb + 2u*2*ST_A + loc, &Bhi_g[gob]);
                CP16(nb + 2u*3*ST_A + loc, &Blo_g[gob]);
            }
            CP_COMMIT();
        }

        #pragma unroll
        for (int ks = 0; ks < 2; ks++) {
            int kk = ks * 16;
            unsigned ah[2][4], al[2][4];
            #pragma unroll
            for (int mt = 0; mt < 2; mt++) {
                unsigned off = 2u * (unsigned)((wm*32 + mt*16 + a_r) * PAD + kk + a_c);
                LDM4(ah[mt], uah + off);
                LDM4(al[mt], ual + off);
            }
            #pragma unroll
            for (int bi = 0; bi < 4; bi++) {
                unsigned off = 2u * (unsigned)((wn*64 + bi*16 + b_r) * PAD + kk + b_c);
                unsigned bh[4], bl[4];
                LDM4(bh, ubh + off);
                LDM4(bl, ubl + off);
                #pragma unroll
                for (int mt = 0; mt < 2; mt++) {
                    #pragma unroll
                    for (int j = 0; j < 2; j++) {
                        float* cc = acc[mt][bi*2 + j];
                        MMA_BF16(cc, ah[mt], bh[j*2], bh[j*2+1]);
                        MMA_BF16(cc, ah[mt], bl[j*2], bl[j*2+1]);
                        MMA_BF16(cc, al[mt], bh[j*2], bh[j*2+1]);
                    }
                }
            }
        }
        __syncthreads();
    }

    int g = lane >> 2, tig = lane & 3;
    #pragma unroll
    for (int mt = 0; mt < 2; mt++) {
        #pragma unroll
        for (int nt = 0; nt < 8; nt++) {
            int col = n0 + wn*64 + nt*8 + tig*2;
            float b0 = bias[col], b1 = bias[col+1];
            #pragma unroll
            for (int half = 0; half < 2; half++) {
                int r = m0 + wm*32 + mt*16 + g + half*8;
                if (r >= M) continue;
                float scale = rs ? rs[r] : 1.0f;
                size_t idx = (size_t)r * N + col;
                float2 o;
                o.x = acc[mt][nt][half*2+0] * scale + b0;
                o.y = acc[mt][nt][half*2+1] * scale + b1;
                if (rd) {
                    const float2 rv = *(const float2*)&rd[idx];
                    o.x += rv.x; o.y += rv.y;
                }
                if (dogelu) {
                    o.x = 0.5f*o.x*(1.0f+erff(o.x*0.70710678118654752f));
                    o.y = 0.5f*o.y*(1.0f+erff(o.y*0.70710678118654752f));
                }
                if (Chi) {
                    __nv_bfloat16 h0 = __float2bfloat16_rn(o.x);
                    __nv_bfloat16 h1 = __float2bfloat16_rn(o.y);
                    *(unsigned*)&Chi[idx] = pack_bf2(h0, h1);
                    *(unsigned*)&Clo[idx] = pack_bf2(
                        __float2bfloat16_rn(o.x - __bfloat162float(h0)),
                        __float2bfloat16_rn(o.y - __bfloat162float(h1)));
                } else {
                    *(float2*)&C[idx] = o;
                }
            }
        }
    }
}

// ---------------- host orchestration ----------------
extern "C" void kernel_launch(void* const* d_in, const int* in_sizes, int n_in,
                              void* d_out, int out_size) {
    const float* h      = (const float*)d_in[0];
    const int*   es     = (const int*)  d_in[1];
    const int*   ed     = (const int*)  d_in[2];
    const float* preW   = (const float*)d_in[3];
    const float* preB   = (const float*)d_in[4];
    const float* postW  = (const float*)d_in[5];
    const float* postB  = (const float*)d_in[6];
    const float* qW     = (const float*)d_in[7];
    const float* qB     = (const float*)d_in[8];
    const float* kW     = (const float*)d_in[9];
    const float* kB     = (const float*)d_in[10];
    const float* vW     = (const float*)d_in[11];
    const float* vB     = (const float*)d_in[12];
    const float* oW     = (const float*)d_in[13];
    const float* oB     = (const float*)d_in[14];
    const float* fW1    = (const float*)d_in[15];
    const float* fB1    = (const float*)d_in[16];
    const float* fW2    = (const float*)d_in[17];
    const float* fB2    = (const float*)d_in[18];
    const float* lnPreG = (const float*)d_in[19];
    const float* lnPreB = (const float*)d_in[20];
    const float* lnAtG  = (const float*)d_in[21];
    const float* lnAtB  = (const float*)d_in[22];
    const float* lnPoG  = (const float*)d_in[23];
    const float* lnPoB  = (const float*)d_in[24];
    const float* lnFfG  = (const float*)d_in[25];
    const float* lnFfB  = (const float*)d_in[26];
    float* out = (float*)d_out;

    float *hn, *qkv, *cd, *qkvb;
    __nv_bfloat16 *wbhi, *wblo, *ahi, *alo, *fhi, *flo;
    int *degs, *degd, *fill;
    cudaGetSymbolAddress((void**)&hn,   g_hn);
    cudaGetSymbolAddress((void**)&qkv,  g_qkv);
    cudaGetSymbolAddress((void**)&cd,   g_cd);
    cudaGetSymbolAddress((void**)&qkvb, g_qkvb);
    cudaGetSymbolAddress((void**)&degs, g_degs);
    cudaGetSymbolAddress((void**)&degd, g_degd);
    cudaGetSymbolAddress((void**)&fill, g_fill);
    cudaGetSymbolAddress((void**)&wbhi, g_wbhi);
    cudaGetSymbolAddress((void**)&wblo, g_wblo);
    cudaGetSymbolAddress((void**)&ahi,  g_ahi);
    cudaGetSymbolAddress((void**)&alo,  g_alo);
    cudaGetSymbolAddress((void**)&fhi,  g_fhi);
    cudaGetSymbolAddress((void**)&flo,  g_flo);

    cudaFuncSetAttribute(gemm_mma, cudaFuncAttributeMaxDynamicSharedMemorySize, GSMEM);

    const dim3 g256(2, 196, 2);
    const dim3 g768(6, 196, 2);
    const dim3 g512(4, 196, 2);
    const int NB = (NTOT + 255) / 256;   // 196
    const int LNB = NTOT / 8;            // 6250, warp-per-node LN

    // weights + bias + degrees + CSR
    k_wconv_all<<<WCVT_TOTAL/256, 256>>>(preW, postW, qW, kW, vW, oW, fW1, fW2);
    k_qkvb<<<(T_*768 + 255)/256, 256>>>(qB, kB, vB);
    cudaMemsetAsync(degs, 0, sizeof(int) * T_ * NP);
    cudaMemsetAsync(degd, 0, sizeof(int) * T_ * NP);
    cudaMemsetAsync(fill, 0, sizeof(int) * NTOT);
    k_deg<<<(E2 + 255)/256, 256>>>(es, ed);
    k_degnorm<<<(NP + 255)/256, 256>>>();
    k_scan1<<<NB, 256>>>();
    k_scan2<<<1, 256>>>();
    k_scan3<<<NB, 256>>>();
    k_fill<<<(E2 + 255)/256, 256>>>(ed);

    // ---- conv1 ----
    k_ln<<<LNB, 256>>>(h, lnPreG, lnPreB, hn);
    k_conv_gather<<<NTOT, 64>>>(hn, es);
    gemm_mma<<<g256, 256, GSMEM>>>(ahi, alo, wbhi+WOFF_PRE, wblo+WOFF_PRE, preB, cd, h, out,
                                   nullptr, nullptr, NP, HID_, HID_, 1, 0);

    // ---- attention ----
    k_ln_split<<<LNB, 256>>>(out, lnAtG, lnAtB);
    gemm_mma<<<g768, 256, GSMEM>>>(ahi, alo, wbhi+WOFF_QKV, wblo+WOFF_QKV, qkvb, nullptr, nullptr,
                                   qkv, nullptr, nullptr, NP, HID_, 768, 0, 0);
    k_attn<<<NTOT, 64>>>(qkv, es);
    gemm_mma<<<g256, 256, GSMEM>>>(ahi, alo, wbhi+WOFF_O, wblo+WOFF_O, oB, nullptr, out, out,
                                   nullptr, nullptr, NP, HID_, HID_, 0, 0);

    // ---- conv2 ----
    k_ln<<<LNB, 256>>>(out, lnPoG, lnPoB, hn);
    k_conv_gather<<<NTOT, 64>>>(hn, es);
    gemm_mma<<<g256, 256, GSMEM>>>(ahi, alo, wbhi+WOFF_POST, wblo+WOFF_POST, postB, cd, out, out,
                                   nullptr, nullptr, NP, HID_, HID_, 1, 0);

    // ---- FFN ----
    k_ln_split<<<LNB, 256>>>(out, lnFfG, lnFfB);
    gemm_mma<<<g512, 256, GSMEM>>>(ahi, alo, wbhi+WOFF_F1, wblo+WOFF_F1, fB1, nullptr, nullptr,
                                   nullptr, fhi, flo, NP, HID_, 512, 0, 1);
    gemm_mma<<<g256, 256, GSMEM>>>(fhi, flo, wbhi+WOFF_F2, wblo+WOFF_F2, fB2, nullptr, out, out,
                                   nullptr, nullptr, NP, 512, HID_, 0, 0);
}

// round 10
// speedup vs baseline: 3.5950x; 1.2090x over previous
#include <cuda_runtime.h>
#include <cuda_fp16.h>
#include <math.h>

#define T_   2
#define NP   25000
#define EP   200000
#define HID_ 256
#define NTOT (T_*NP)
#define E2   (2*EP)

// ---------------- scratch (static __device__ — no allocations) ----------------
__device__ float g_hn [(size_t)T_*NP*HID_];       // fp32 LN out (conv paths)
__device__ float g_qkv[(size_t)NTOT*768];         // interleaved q|k|v per node
__device__ float g_sc [(size_t)E2*8];             // ex values (CSR order)
__device__ float g_cs [T_*NP];
__device__ float g_cd [T_*NP];
__device__ float g_qkvb[T_*768];
__device__ int   g_degs[T_*NP];
__device__ int   g_degd[T_*NP];
__device__ int   g_bsum[256];
// CSR by global dst node
__device__ int   g_off [NTOT + 1];
__device__ int   g_fill[NTOT];
__device__ int   g_csr [E2];
// fp16 A operands (single precision-split NOT needed on A side)
__device__ __half g_ah[(size_t)NTOT*HID_];
__device__ __half g_fh[(size_t)NTOT*512];
// split weights, fp16 hi/lo, layout [matrix][t][N][K]
#define WCVT_TOTAL 1310720
__device__ __half g_whi[WCVT_TOTAL];
__device__ __half g_wlo[WCVT_TOTAL];
#define WOFF_PRE  0
#define WOFF_POST 131072
#define WOFF_QKV  262144
#define WOFF_O    655360
#define WOFF_F1   786432
#define WOFF_F2   1048576

// ---------------- mma / async helpers ----------------
__device__ __forceinline__ unsigned smem_u32(const void* p) {
    unsigned a;
    asm("{ .reg .u64 t; cvta.to.shared.u64 t, %1; cvt.u32.u64 %0, t; }" : "=r"(a) : "l"(p));
    return a;
}
#define LDM4(r, a) \
    asm volatile("ldmatrix.sync.aligned.m8n8.x4.shared.b16 {%0,%1,%2,%3}, [%4];" \
        : "=r"((r)[0]),"=r"((r)[1]),"=r"((r)[2]),"=r"((r)[3]) : "r"(a))
#define MMA_F16(c, a, b0, b1) \
    asm volatile("mma.sync.aligned.m16n8k16.row.col.f32.f16.f16.f32 " \
        "{%0,%1,%2,%3}, {%4,%5,%6,%7}, {%8,%9}, {%0,%1,%2,%3};" \
        : "+f"((c)[0]),"+f"((c)[1]),"+f"((c)[2]),"+f"((c)[3]) \
        : "r"((a)[0]),"r"((a)[1]),"r"((a)[2]),"r"((a)[3]), "r"(b0),"r"(b1))
#define CP16(dst, src) \
    asm volatile("cp.async.cg.shared.global [%0], [%1], 16;" :: "r"(dst), "l"(src) : "memory")
#define CP_COMMIT() asm volatile("cp.async.commit_group;" ::: "memory")
#define CP_WAIT0()  asm volatile("cp.async.wait_group 0;" ::: "memory")

// write a float4 as fp16x4 into g_ah
__device__ __forceinline__ void store_h4(__half* dst, float4 v) {
    __half2 p0 = __floats2half2_rn(v.x, v.y);
    __half2 p1 = __floats2half2_rn(v.z, v.w);
    uint2 u;
    u.x = *(unsigned*)&p0; u.y = *(unsigned*)&p1;
    *(uint2*)dst = u;
}
__device__ __forceinline__ float warp_sum(float v) {
    #pragma unroll
    for (int o = 16; o; o >>= 1) v += __shfl_xor_sync(0xffffffffu, v, o);
    return v;
}

// ---------------- degree + CSR build ----------------
__global__ void k_deg(const int* __restrict__ es, const int* __restrict__ ed) {
    int gid = blockIdx.x * blockDim.x + threadIdx.x;
    if (gid >= E2) return;
    int et = gid / EP;
    atomicAdd(&g_degs[et*NP + es[gid]], 1);
    atomicAdd(&g_degd[et*NP + ed[gid]], 1);
}

__global__ void k_degnorm() {
    int n = blockIdx.x * blockDim.x + threadIdx.x;
    if (n >= NP) return;
    #pragma unroll
    for (int et = 0; et < 2; et++) {
        g_cs[et*NP + n]       = rsqrtf((float)max(g_degs[et*NP + n], 1));
        g_cd[(1-et)*NP + n]   = rsqrtf((float)max(g_degd[et*NP + n], 1));
    }
}

// ---------------- parallel exclusive scan of in-degrees -> g_off ----------------
__global__ void k_scan1() {
    __shared__ int wsum[8];
    int tid = threadIdx.x, lane = tid & 31, wid = tid >> 5;
    int g = blockIdx.x * 256 + tid;
    int deg = 0;
    if (g < NTOT) {
        int dt = g / NP, n = g - dt * NP;
        deg = g_degd[(1 - dt) * NP + n];
    }
    int x = deg;
    #pragma unroll
    for (int o = 1; o < 32; o <<= 1) { int y = __shfl_up_sync(~0u, x, o); if (lane >= o) x += y; }
    if (lane == 31) wsum[wid] = x;
    __syncthreads();
    if (tid == 0) { int s = 0; for (int i = 0; i < 8; i++) { int t2 = wsum[i]; wsum[i] = s; s += t2; } }
    __syncthreads();
    if (g < NTOT) g_off[g] = wsum[wid] + x - deg;
    if (tid == 255) g_bsum[blockIdx.x] = wsum[7] + x;
}

__global__ void k_scan2() {
    __shared__ int wsum[8];
    int tid = threadIdx.x, lane = tid & 31, wid = tid >> 5;
    int v = (tid < 196) ? g_bsum[tid] : 0;
    int x = v;
    #pragma unroll
    for (int o = 1; o < 32; o <<= 1) { int y = __shfl_up_sync(~0u, x, o); if (lane >= o) x += y; }
    if (lane == 31) wsum[wid] = x;
    __syncthreads();
    if (tid == 0) { int s = 0; for (int i = 0; i < 8; i++) { int t2 = wsum[i]; wsum[i] = s; s += t2; } }
    __syncthreads();
    int excl = wsum[wid] + x - v;
    if (tid < 196) g_bsum[tid] = excl;
    if (tid == 195) g_off[NTOT] = excl + v;
}

__global__ void k_scan3() {
    int g = blockIdx.x * 256 + threadIdx.x;
    if (g < NTOT) g_off[g] += g_bsum[blockIdx.x];
}

__global__ void k_fill(const int* __restrict__ ed) {
    int gid = blockIdx.x * blockDim.x + threadIdx.x;
    if (gid >= E2) return;
    int et = gid / EP;
    int gnode = (1 - et) * NP + ed[gid];
    int pos = g_off[gnode] + atomicAdd(&g_fill[gnode], 1);
    g_csr[pos] = gid;
}

// ---------------- layernorm: warp per node, fp32 out (conv paths) ----------------
__global__ void k_ln(const float* __restrict__ x, const float* __restrict__ g,
                     const float* __restrict__ b, float* __restrict__ y) {
    int gn = blockIdx.x * 8 + (threadIdx.x >> 5);
    int lane = threadIdx.x & 31;
    int t = gn / NP;
    size_t base = (size_t)gn * HID_ + lane * 8;
    float4 v0 = *(const float4*)&x[base];
    float4 v1 = *(const float4*)&x[base + 4];
    float s = v0.x+v0.y+v0.z+v0.w + v1.x+v1.y+v1.z+v1.w;
    float mu = warp_sum(s) * (1.0f / HID_);
    float d0x=v0.x-mu, d0y=v0.y-mu, d0z=v0.z-mu, d0w=v0.w-mu;
    float d1x=v1.x-mu, d1y=v1.y-mu, d1z=v1.z-mu, d1w=v1.w-mu;
    float ss = d0x*d0x+d0y*d0y+d0z*d0z+d0w*d0w + d1x*d1x+d1y*d1y+d1z*d1z+d1w*d1w;
    float rstd = rsqrtf(warp_sum(ss) * (1.0f / HID_) + 1e-5f);
    size_t pb = (size_t)t * HID_ + lane * 8;
    float4 g0 = *(const float4*)&g[pb],  g1 = *(const float4*)&g[pb + 4];
    float4 b0 = *(const float4*)&b[pb],  b1 = *(const float4*)&b[pb + 4];
    float4 o0, o1;
    o0.x = d0x*rstd*g0.x + b0.x; o0.y = d0y*rstd*g0.y + b0.y;
    o0.z = d0z*rstd*g0.z + b0.z; o0.w = d0w*rstd*g0.w + b0.w;
    o1.x = d1x*rstd*g1.x + b1.x; o1.y = d1y*rstd*g1.y + b1.y;
    o1.z = d1z*rstd*g1.z + b1.z; o1.w = d1w*rstd*g1.w + b1.w;
    *(float4*)&y[base]     = o0;
    *(float4*)&y[base + 4] = o1;
}

// warp-per-node LN with fp16 output (GEMM-A paths)
__global__ void k_ln_h(const float* __restrict__ x, const float* __restrict__ g,
                       const float* __restrict__ b) {
    int gn = blockIdx.x * 8 + (threadIdx.x >> 5);
    int lane = threadIdx.x & 31;
    int t = gn / NP;
    size_t base = (size_t)gn * HID_ + lane * 8;
    float4 v0 = *(const float4*)&x[base];
    float4 v1 = *(const float4*)&x[base + 4];
    float s = v0.x+v0.y+v0.z+v0.w + v1.x+v1.y+v1.z+v1.w;
    float mu = warp_sum(s) * (1.0f / HID_);
    float d0x=v0.x-mu, d0y=v0.y-mu, d0z=v0.z-mu, d0w=v0.w-mu;
    float d1x=v1.x-mu, d1y=v1.y-mu, d1z=v1.z-mu, d1w=v1.w-mu;
    float ss = d0x*d0x+d0y*d0y+d0z*d0z+d0w*d0w + d1x*d1x+d1y*d1y+d1z*d1z+d1w*d1w;
    float rstd = rsqrtf(warp_sum(ss) * (1.0f / HID_) + 1e-5f);
    size_t pb = (size_t)t * HID_ + lane * 8;
    float4 g0 = *(const float4*)&g[pb],  g1 = *(const float4*)&g[pb + 4];
    float4 b0 = *(const float4*)&b[pb],  b1 = *(const float4*)&b[pb + 4];
    float4 o0, o1;
    o0.x = d0x*rstd*g0.x + b0.x; o0.y = d0y*rstd*g0.y + b0.y;
    o0.z = d0z*rstd*g0.z + b0.z; o0.w = d0w*rstd*g0.w + b0.w;
    o1.x = d1x*rstd*g1.x + b1.x; o1.y = d1y*rstd*g1.y + b1.y;
    o1.z = d1z*rstd*g1.z + b1.z; o1.w = d1w*rstd*g1.w + b1.w;
    store_h4(&g_ah[base],     o0);
    store_h4(&g_ah[base + 4], o1);
}

// ---------------- conv aggregation: CSR gather, fp16 out ----------------
__global__ void __launch_bounds__(64) k_conv_gather(const float* __restrict__ hn,
                                                    const int* __restrict__ es) {
    int gnode = blockIdx.x;
    int tid = threadIdx.x;
    int off = g_off[gnode], end = g_off[gnode + 1];
    int dt = gnode / NP;
    int et = 1 - dt;
    float4 acc = make_float4(0.f, 0.f, 0.f, 0.f);
    for (int i = off; i < end; i++) {
        int eid = g_csr[i];
        int src = es[eid];
        float w = g_cs[et*NP + src];
        const float4 hv = *(const float4*)&hn[((size_t)et*NP + src)*HID_ + tid*4];
        acc.x += hv.x*w; acc.y += hv.y*w; acc.z += hv.z*w; acc.w += hv.w*w;
    }
    store_h4(&g_ah[(size_t)gnode*HID_ + tid*4], acc);
}

// ---------------- fused attention: score+exp+den+gather, fp16 out ----------------
#define ECACHE 160
__global__ void __launch_bounds__(64) k_attn(const float* __restrict__ qkv,
                                             const int* __restrict__ es) {
    __shared__ float sq[HID_];
    __shared__ float sden[2][8];
    __shared__ int ssrc[ECACHE];
    int gnode = blockIdx.x, tid = threadIdx.x, lane = tid & 31, wid = tid >> 5;
    int off = g_off[gnode], deg = g_off[gnode + 1] - off;

    *(float4*)&sq[tid*4] = *(const float4*)&qkv[(size_t)gnode*768 + tid*4];
    int ncache = (deg < ECACHE) ? deg : ECACHE;
    for (int i = tid; i < ncache; i += 64) {
        int eid = g_csr[off + i];
        int et = eid / EP;
        ssrc[i] = es[eid] + (et ? NP : 0);
    }
    __syncthreads();

    float denAcc = 0.f;
    for (int i = wid; i < deg; i += 2) {
        int sg;
        if (i < ECACHE) sg = ssrc[i];
        else { int eid = g_csr[off + i]; int et = eid / EP; sg = es[eid] + (et ? NP : 0); }
        const float* kv = &qkv[(size_t)sg * 768 + 256];
        float myex = 0.f;
        #pragma unroll
        for (int hh = 0; hh < 8; hh++) {
            float p = sq[hh*32 + lane] * kv[hh*32 + lane];
            p = warp_sum(p);
            float s = fminf(fmaxf(p * 0.17677669529663687f, -5.0f), 5.0f);
            float ex = expf(s);   // s in [-5,5]: no overflow; max-shift cancels exactly
            if (lane == hh) myex = ex;
        }
        if (lane < 8) {
            g_sc[(size_t)(off + i)*8 + lane] = myex;
            denAcc += myex;
        }
    }
    if (lane < 8) sden[wid][lane] = denAcc;
    __syncthreads();

    int hh = tid >> 3;
    float den = sden[0][hh] + sden[1][hh];
    float rden = (den > 0.f) ? 1.0f / den : 0.f;
    float4 acc = make_float4(0.f, 0.f, 0.f, 0.f);
    for (int i = 0; i < deg; i++) {
        int sg;
        if (i < ECACHE) sg = ssrc[i];
        else { int eid = g_csr[off + i]; int et = eid / EP; sg = es[eid] + (et ? NP : 0); }
        float alpha = g_sc[(size_t)(off + i)*8 + hh] * rden;
        const float4 vv = *(const float4*)&qkv[(size_t)sg*768 + 512 + tid*4];
        acc.x += vv.x*alpha; acc.y += vv.y*alpha; acc.z += vv.z*alpha; acc.w += vv.w*alpha;
    }
    store_h4(&g_ah[(size_t)gnode*HID_ + tid*4], acc);
}

// ---------------- all-weights split to fp16 hi/lo (one launch) ----------------
__global__ void k_wconv_all(const float* __restrict__ preW, const float* __restrict__ postW,
                            const float* __restrict__ qW, const float* __restrict__ kW,
                            const float* __restrict__ vW, const float* __restrict__ oW,
                            const float* __restrict__ f1W, const float* __restrict__ f2W) {
    int gid = blockIdx.x * 256 + threadIdx.x;
    if (gid >= WCVT_TOTAL) return;
    float x;
    if (gid < 262144) {                       // PRE, POST: [t][256][256]
        const float* W = (gid < 131072) ? preW : postW;
        int loc = gid & 131071;
        int t = loc >> 16, o = loc & 65535;
        int n = o >> 8, kk = o & 255;
        x = W[t*65536 + kk*256 + n];
    } else if (gid < 655360) {                // QKV: [t][768][256]
        int loc = gid - 262144;
        int t = loc / 196608, r = loc % 196608;
        int n7 = r >> 8, kk = r & 255;
        const float* W; int n;
        if (n7 < 256)      { W = qW; n = n7; }
        else if (n7 < 512) { W = kW; n = n7 - 256; }
        else               { W = vW; n = n7 - 512; }
        x = W[t*65536 + kk*256 + n];
    } else if (gid < 786432) {                // O: [t][256][256]
        int loc = gid - 655360;
        int t = loc >> 16, o = loc & 65535;
        int n = o >> 8, kk = o & 255;
        x = oW[t*65536 + kk*256 + n];
    } else if (gid < 1048576) {               // F1: [t][512][256]
        int loc = gid - 786432;
        int t = loc >> 17, o = loc & 131071;
        int n = o >> 8, kk = o & 255;
        x = f1W[t*131072 + kk*512 + n];
    } else {                                  // F2: [t][256][512]
        int loc = gid - 1048576;
        int t = loc >> 17, o = loc & 131071;
        int n = o >> 9, kk = o & 511;
        x = f2W[t*131072 + kk*256 + n];
    }
    __half h = __float2half_rn(x);
    g_whi[gid] = h;
    g_wlo[gid] = __float2half_rn(x - __half2float(h));
}

__global__ void k_qkvb(const float* __restrict__ qB, const float* __restrict__ kB,
                       const float* __restrict__ vB) {
    int i = blockIdx.x * 256 + threadIdx.x;
    if (i >= T_ * 768) return;
    int t = i / 768, c = i % 768;
    g_qkvb[i] = (c < 256) ? qB[t*256 + c] : (c < 512) ? kB[t*256 + c - 256] : vB[t*256 + c - 512];
}

// ---------------- fp16 tensor GEMM: D = A*(Bhi+Blo), cp.async double-buffered ----------------
// A fp16 [t][M][K]; B split fp16 hi/lo [t][N][K].
// CTA 128x128, 8 warps (4m x 2n), K-chunk 32, 2-stage pipeline, 3 smem bufs.
#define PAD 40
#define ST_A   (128*PAD)
#define ST_ALL (3*128*PAD)
#define GSMEM  (2*ST_ALL*2)

__global__ void __launch_bounds__(256, 2) gemm_mma(
    const __half* __restrict__ A_g,
    const __half* __restrict__ Bhi_g, const __half* __restrict__ Blo_g,
    const float* __restrict__ bias, const float* __restrict__ rowscale,
    const float* __restrict__ resid, float* __restrict__ C,
    __half* __restrict__ Ch,
    int M, int K, int N, int wswap, int dogelu)
{
    extern __shared__ __half smem[];

    int tid = threadIdx.x;
    int warp = tid >> 5, lane = tid & 31;
    int wm = warp & 3, wn = warp >> 2;
    int t = blockIdx.z;
    int wi = wswap ? (1 - t) : t;

    A_g   += (size_t)t  * M * K;
    Bhi_g += (size_t)wi * K * N;
    Blo_g += (size_t)wi * K * N;
    bias  += (size_t)wi * N;
    const float* rs = rowscale ? rowscale + (size_t)t * M : nullptr;
    const float* rd = resid ? resid + (size_t)t * M * N : nullptr;
    C  += (size_t)t * M * N;
    if (Ch) Ch += (size_t)t * M * N;

    int m0 = blockIdx.y * 128, n0 = blockIdx.x * 128;

    float acc[2][8][4];
    #pragma unroll
    for (int i = 0; i < 2; i++)
        #pragma unroll
        for (int j = 0; j < 8; j++)
            #pragma unroll
            for (int l = 0; l < 4; l++) acc[i][j][l] = 0.f;

    int lrow = lane & 7, lsel = lane >> 3;
    int a_r = (lsel & 1) * 8 + lrow;
    int a_c = (lsel >> 1) * 8;
    int b_r = (lsel >> 1) * 8 + lrow;
    int b_c = (lsel & 1) * 8;

    unsigned usm = smem_u32(smem);
    int grow = tid >> 2, gseg = tid & 3;
    int nchunks = K >> 5;

    {
        unsigned base = usm;
        #pragma unroll
        for (int i = 0; i < 2; i++) {
            int row = grow + i * 64;
            unsigned loc = 2u * (unsigned)(row * PAD + gseg * 8);
            size_t goa = (size_t)(m0 + row) * K + (gseg << 3);
            size_t gob = (size_t)(n0 + row) * K + (gseg << 3);
            CP16(base + loc,               &A_g[goa]);
            CP16(base + 2u*ST_A + loc,     &Bhi_g[gob]);
            CP16(base + 2u*2*ST_A + loc,   &Blo_g[gob]);
        }
        CP_COMMIT();
    }

    for (int c = 0; c < nchunks; c++) {
        int s = c & 1;
        unsigned base = usm + 2u * (unsigned)(s * ST_ALL);
        unsigned ua = base, ubh = base + 2u*ST_A, ubl = base + 2u*2*ST_A;

        CP_WAIT0();
        __syncthreads();

        if (c + 1 < nchunks) {
            int koff = (c + 1) << 5;
            unsigned nb = usm + 2u * (unsigned)((1 - s) * ST_ALL);
            #pragma unroll
            for (int i = 0; i < 2; i++) {
                int row = grow + i * 64;
                unsigned loc = 2u * (unsigned)(row * PAD + gseg * 8);
                size_t goa = (size_t)(m0 + row) * K + koff + (gseg << 3);
                size_t gob = (size_t)(n0 + row) * K + koff + (gseg << 3);
                CP16(nb + loc,             &A_g[goa]);
                CP16(nb + 2u*ST_A + loc,   &Bhi_g[gob]);
                CP16(nb + 2u*2*ST_A + loc, &Blo_g[gob]);
            }
            CP_COMMIT();
        }

        #pragma unroll
        for (int ks = 0; ks < 2; ks++) {
            int kk = ks * 16;
            unsigned ah[2][4];
            #pragma unroll
            for (int mt = 0; mt < 2; mt++) {
                unsigned off = 2u * (unsigned)((wm*32 + mt*16 + a_r) * PAD + kk + a_c);
                LDM4(ah[mt], ua + off);
            }
            #pragma unroll
            for (int bi = 0; bi < 4; bi++) {
                unsigned off = 2u * (unsigned)((wn*64 + bi*16 + b_r) * PAD + kk + b_c);
                unsigned bh[4], bl[4];
                LDM4(bh, ubh + off);
                LDM4(bl, ubl + off);
                #pragma unroll
                for (int mt = 0; mt < 2; mt++) {
                    #pragma unroll
                    for (int j = 0; j < 2; j++) {
                        float* cc = acc[mt][bi*2 + j];
                        MMA_F16(cc, ah[mt], bh[j*2], bh[j*2+1]);
                        MMA_F16(cc, ah[mt], bl[j*2], bl[j*2+1]);
                    }
                }
            }
        }
        __syncthreads();
    }

    int g = lane >> 2, tig = lane & 3;
    #pragma unroll
    for (int mt = 0; mt < 2; mt++) {
        #pragma unroll
        for (int nt = 0; nt < 8; nt++) {
            int col = n0 + wn*64 + nt*8 + tig*2;
            float b0 = bias[col], b1 = bias[col+1];
            #pragma unroll
            for (int half = 0; half < 2; half++) {
                int r = m0 + wm*32 + mt*16 + g + half*8;
                if (r >= M) continue;
                float scale = rs ? rs[r] : 1.0f;
                size_t idx = (size_t)r * N + col;
                float2 o;
                o.x = acc[mt][nt][half*2+0] * scale + b0;
                o.y = acc[mt][nt][half*2+1] * scale + b1;
                if (rd) {
                    const float2 rv = *(const float2*)&rd[idx];
                    o.x += rv.x; o.y += rv.y;
                }
                if (dogelu) {
                    o.x = 0.5f*o.x*(1.0f+erff(o.x*0.70710678118654752f));
                    o.y = 0.5f*o.y*(1.0f+erff(o.y*0.70710678118654752f));
                }
                if (Ch) {
                    __half2 p = __floats2half2_rn(o.x, o.y);
                    *(unsigned*)&Ch[idx] = *(unsigned*)&p;
                } else {
                    *(float2*)&C[idx] = o;
                }
            }
        }
    }
}

// ---------------- host orchestration ----------------
extern "C" void kernel_launch(void* const* d_in, const int* in_sizes, int n_in,
                              void* d_out, int out_size) {
    const float* h      = (const float*)d_in[0];
    const int*   es     = (const int*)  d_in[1];
    const int*   ed     = (const int*)  d_in[2];
    const float* preW   = (const float*)d_in[3];
    const float* preB   = (const float*)d_in[4];
    const float* postW  = (const float*)d_in[5];
    const float* postB  = (const float*)d_in[6];
    const float* qW     = (const float*)d_in[7];
    const float* qB     = (const float*)d_in[8];
    const float* kW     = (const float*)d_in[9];
    const float* kB     = (const float*)d_in[10];
    const float* vW     = (const float*)d_in[11];
    const float* vB     = (const float*)d_in[12];
    const float* oW     = (const float*)d_in[13];
    const float* oB     = (const float*)d_in[14];
    const float* fW1    = (const float*)d_in[15];
    const float* fB1    = (const float*)d_in[16];
    const float* fW2    = (const float*)d_in[17];
    const float* fB2    = (const float*)d_in[18];
    const float* lnPreG = (const float*)d_in[19];
    const float* lnPreB = (const float*)d_in[20];
    const float* lnAtG  = (const float*)d_in[21];
    const float* lnAtB  = (const float*)d_in[22];
    const float* lnPoG  = (const float*)d_in[23];
    const float* lnPoB  = (const float*)d_in[24];
    const float* lnFfG  = (const float*)d_in[25];
    const float* lnFfB  = (const float*)d_in[26];
    float* out = (float*)d_out;

    float *hn, *qkv, *cd, *qkvb;
    __half *whi, *wlo, *ah, *fh;
    int *degs, *degd, *fill;
    cudaGetSymbolAddress((void**)&hn,   g_hn);
    cudaGetSymbolAddress((void**)&qkv,  g_qkv);
    cudaGetSymbolAddress((void**)&cd,   g_cd);
    cudaGetSymbolAddress((void**)&qkvb, g_qkvb);
    cudaGetSymbolAddress((void**)&degs, g_degs);
    cudaGetSymbolAddress((void**)&degd, g_degd);
    cudaGetSymbolAddress((void**)&fill, g_fill);
    cudaGetSymbolAddress((void**)&whi,  g_whi);
    cudaGetSymbolAddress((void**)&wlo,  g_wlo);
    cudaGetSymbolAddress((void**)&ah,   g_ah);
    cudaGetSymbolAddress((void**)&fh,   g_fh);

    cudaFuncSetAttribute(gemm_mma, cudaFuncAttributeMaxDynamicSharedMemorySize, GSMEM);

    const dim3 g256(2, 196, 2);
    const dim3 g768(6, 196, 2);
    const dim3 g512(4, 196, 2);
    const int NB = (NTOT + 255) / 256;   // 196
    const int LNB = NTOT / 8;            // 6250, warp-per-node LN

    // weights + bias + degrees + CSR
    k_wconv_all<<<WCVT_TOTAL/256, 256>>>(preW, postW, qW, kW, vW, oW, fW1, fW2);
    k_qkvb<<<(T_*768 + 255)/256, 256>>>(qB, kB, vB);
    cudaMemsetAsync(degs, 0, sizeof(int) * T_ * NP);
    cudaMemsetAsync(degd, 0, sizeof(int) * T_ * NP);
    cudaMemsetAsync(fill, 0, sizeof(int) * NTOT);
    k_deg<<<(E2 + 255)/256, 256>>>(es, ed);
    k_degnorm<<<(NP + 255)/256, 256>>>();
    k_scan1<<<NB, 256>>>();
    k_scan2<<<1, 256>>>();
    k_scan3<<<NB, 256>>>();
    k_fill<<<(E2 + 255)/256, 256>>>(ed);

    // ---- conv1 ----
    k_ln<<<LNB, 256>>>(h, lnPreG, lnPreB, hn);
    k_conv_gather<<<NTOT, 64>>>(hn, es);
    gemm_mma<<<g256, 256, GSMEM>>>(ah, whi+WOFF_PRE, wlo+WOFF_PRE, preB, cd, h, out,
                                   nullptr, NP, HID_, HID_, 1, 0);

    // ---- attention ----
    k_ln_h<<<LNB, 256>>>(out, lnAtG, lnAtB);
    gemm_mma<<<g768, 256, GSMEM>>>(ah, whi+WOFF_QKV, wlo+WOFF_QKV, qkvb, nullptr, nullptr,
                                   qkv, nullptr, NP, HID_, 768, 0, 0);
    k_attn<<<NTOT, 64>>>(qkv, es);
    gemm_mma<<<g256, 256, GSMEM>>>(ah, whi+WOFF_O, wlo+WOFF_O, oB, nullptr, out, out,
                                   nullptr, NP, HID_, HID_, 0, 0);

    // ---- conv2 ----
    k_ln<<<LNB, 256>>>(out, lnPoG, lnPoB, hn);
    k_conv_gather<<<NTOT, 64>>>(hn, es);
    gemm_mma<<<g256, 256, GSMEM>>>(ah, whi+WOFF_POST, wlo+WOFF_POST, postB, cd, out, out,
                                   nullptr, NP, HID_, HID_, 1, 0);

    // ---- FFN ----
    k_ln_h<<<LNB, 256>>>(out, lnFfG, lnFfB);
    gemm_mma<<<g512, 256, GSMEM>>>(ah, whi+WOFF_F1, wlo+WOFF_F1, fB1, nullptr, nullptr,
                                   nullptr, fh, NP, HID_, 512, 0, 1);
    gemm_mma<<<g256, 256, GSMEM>>>(fh, whi+WOFF_F2, wlo+WOFF_F2, fB2, nullptr, out, out,
                                   nullptr, NP, 512, HID_, 0, 0);
}